// round 8
// baseline (speedup 1.0000x reference)
#include <cuda_runtime.h>
#include <cuda_fp16.h>
#include <math.h>
#include <stdint.h>

// ---------------- problem constants ----------------
#define Dm   768
#define Hh   12
#define DHd  64
#define BLKS 64
#define NB   64
#define SEQ  4096
#define BB   2
#define NTOK (BB*SEQ)
#define RR   3
#define FF   3072
#define QKVD 2304

#define WSZ   589824
#define W1SZ  2359296
#define OFFL  (4*WSZ + 2*W1SZ)

// ---------------- scratch (device globals) ----------------
__device__ float g_x  [NTOK*Dm];
__device__ float g_tmp[NTOK*Dm];
__device__ __half g_xh [NTOK*Dm];
__device__ __half g_xl [NTOK*Dm];
__device__ __half g_qkvh[NTOK*QKVD];
__device__ __half g_qkvl[NTOK*QKVD];
__device__ __half g_ch [NTOK*Dm];
__device__ __half g_cl [NTOK*Dm];
__device__ __half g_fh [NTOK*FF];
__device__ __half g_fl [NTOK*FF];
__device__ __half g_wh [2*OFFL];        // weights: single fp16 (rn)
__device__ float g_bqkv[2*QKVD];
__device__ float g_part[64];

// ---------------- helpers ----------------
__device__ __forceinline__ float gelu_tanh(float x) {
    float x3 = x * x * x;
    return 0.5f * x * (1.f + tanhf(0.7978845608028654f * (x + 0.044715f * x3)));
}

__device__ __forceinline__ float blk_sum256(float v) {
    __shared__ float red[32];
    int lane = threadIdx.x & 31, wid = threadIdx.x >> 5;
    #pragma unroll
    for (int o = 16; o > 0; o >>= 1) v += __shfl_xor_sync(0xffffffffu, v, o);
    if (lane == 0) red[wid] = v;
    __syncthreads();
    if (wid == 0) {
        v = (lane < 8) ? red[lane] : 0.f;
        #pragma unroll
        for (int o = 4; o > 0; o >>= 1) v += __shfl_xor_sync(0xffffffffu, v, o);
        if (lane == 0) red[0] = v;
    }
    __syncthreads();
    float r = red[0];
    __syncthreads();
    return r;
}

__device__ __forceinline__ uint32_t s2u(const void* p) {
    uint32_t a;
    asm("{ .reg .u64 t; cvta.to.shared.u64 t, %1; cvt.u32.u64 %0, t; }" : "=r"(a) : "l"(p));
    return a;
}

#define LDSM4(r, a) \
    asm volatile("ldmatrix.sync.aligned.m8n8.x4.shared.b16 {%0,%1,%2,%3}, [%4];" \
        : "=r"((r)[0]), "=r"((r)[1]), "=r"((r)[2]), "=r"((r)[3]) : "r"(a))
#define LDSM2(r0, r1, a) \
    asm volatile("ldmatrix.sync.aligned.m8n8.x2.shared.b16 {%0,%1}, [%2];" \
        : "=r"(r0), "=r"(r1) : "r"(a))
#define LDSM2T(r0, r1, a) \
    asm volatile("ldmatrix.sync.aligned.m8n8.x2.trans.shared.b16 {%0,%1}, [%2];" \
        : "=r"(r0), "=r"(r1) : "r"(a))

#define CPA16(dst, src) \
    asm volatile("cp.async.cg.shared.global [%0], [%1], 16;" :: "r"(dst), "l"(src))
#define CP_COMMIT() asm volatile("cp.async.commit_group;" ::: "memory")
#define CP_WAIT(n)  asm volatile("cp.async.wait_group %0;" :: "n"(n) : "memory")

__device__ __forceinline__ void mma16816(float* c, const uint32_t* a,
                                         uint32_t b0, uint32_t b1) {
    asm volatile(
        "mma.sync.aligned.m16n8k16.row.col.f32.f16.f16.f32 "
        "{%0,%1,%2,%3}, {%4,%5,%6,%7}, {%8,%9}, {%0,%1,%2,%3};"
        : "+f"(c[0]), "+f"(c[1]), "+f"(c[2]), "+f"(c[3])
        : "r"(a[0]), "r"(a[1]), "r"(a[2]), "r"(a[3]), "r"(b0), "r"(b1));
}

__device__ __forceinline__ void split2h(float a, float b, uint32_t& hi, uint32_t& lo) {
    __half ha = __float2half_rn(a);
    __half hb = __float2half_rn(b);
    __half la = __float2half_rn(a - __half2float(ha));
    __half lb = __float2half_rn(b - __half2float(hb));
    hi = (uint32_t)__half_as_ushort(ha) | ((uint32_t)__half_as_ushort(hb) << 16);
    lo = (uint32_t)__half_as_ushort(la) | ((uint32_t)__half_as_ushort(lb) << 16);
}

// ---------------- weight transpose + fp16 convert ----------------
__global__ void __launch_bounds__(256) wsplit_kernel(
    const float* __restrict__ W, __half* __restrict__ hi, int K, int N)
{
    __shared__ float t[32][33];
    int n0 = blockIdx.x * 32, k0 = blockIdx.y * 32;
    int tx = threadIdx.x & 31, ty = threadIdx.x >> 5;
    #pragma unroll
    for (int j = 0; j < 4; j++)
        t[ty + j * 8][tx] = W[(size_t)(k0 + ty + j * 8) * N + n0 + tx];
    __syncthreads();
    #pragma unroll
    for (int j = 0; j < 4; j++) {
        int n = n0 + ty + j * 8, k = k0 + tx;
        hi[(size_t)n * K + k] = __float2half_rn(t[tx][ty + j * 8]);
    }
}

// qkv weight convert (one launch) + bias concat
__global__ void __launch_bounds__(256) wsplit3_kernel(
    const float* __restrict__ Wa, const float* __restrict__ Wb,
    const float* __restrict__ Wc, __half* __restrict__ hi,
    const float* __restrict__ ba, const float* __restrict__ bb,
    const float* __restrict__ bc, float* __restrict__ bqkv)
{
    __shared__ float t[32][33];
    int z = blockIdx.z;
    const float* W = (z == 0) ? Wa : (z == 1) ? Wb : Wc;
    __half* hz = hi + (size_t)z * WSZ;
    int n0 = blockIdx.x * 32, k0 = blockIdx.y * 32;
    int tx = threadIdx.x & 31, ty = threadIdx.x >> 5;
    if (blockIdx.x == 0 && blockIdx.y == 0) {
        const float* bz = (z == 0) ? ba : (z == 1) ? bb : bc;
        for (int i = threadIdx.x; i < Dm; i += 256) bqkv[z * Dm + i] = bz[i];
    }
    #pragma unroll
    for (int j = 0; j < 4; j++)
        t[ty + j * 8][tx] = W[(size_t)(k0 + ty + j * 8) * Dm + n0 + tx];
    __syncthreads();
    #pragma unroll
    for (int j = 0; j < 4; j++) {
        int n = n0 + ty + j * 8, k = k0 + tx;
        hz[(size_t)n * Dm + k] = __float2half_rn(t[tx][ty + j * 8]);
    }
}

// ---------------- cp.async warp-MMA GEMM (2-term fp16) ----------------
// A = activations hi/lo fp16 [M,K] (exact); B = weights single fp16 [N,K].
// C = (Ahi + Alo) @ B : 2 MMAs per fragment pair.
#define RS_B   80
#define TILE_B (128*RS_B)
#define STG3   (3*TILE_B)

template<int GELU, int WF32, int WSPL, int KC>
__global__ void __launch_bounds__(256, 2) gemm_mma(
    const __half* __restrict__ Ahi, const __half* __restrict__ Alo,
    const __half* __restrict__ Bh,
    const float* __restrict__ bias, float* __restrict__ C,
    __half* __restrict__ Chi, __half* __restrict__ Clo,
    int M, int N)
{
    const int K = KC * 32;
    extern __shared__ char sm[];
    uint32_t sbase = s2u(sm);
    int tid = threadIdx.x, lane = tid & 31, wid = tid >> 5;
    int m0 = blockIdx.y * 128, n0 = blockIdx.x * 128;
    int wm = (wid & 3) * 32, wn = (wid >> 2) * 64;

    int lr = tid & 127, lh = tid >> 7;
    const __half* ah_p = Ahi + (size_t)(m0 + lr) * K + lh * 16;
    const __half* al_p = Alo + (size_t)(m0 + lr) * K + lh * 16;
    const __half* bh_p = Bh  + (size_t)(n0 + lr) * K + lh * 16;
    uint32_t woff = (uint32_t)lr * RS_B + (uint32_t)lh * 32;

    float acc[2][8][4];
    #pragma unroll
    for (int i = 0; i < 2; i++)
        #pragma unroll
        for (int j = 0; j < 8; j++)
            #pragma unroll
            for (int t = 0; t < 4; t++) acc[i][j][t] = 0.f;

    {
        uint32_t d = sbase + woff;
        CPA16(d,                  ah_p);  CPA16(d + 16,              ah_p + 8);
        CPA16(d + TILE_B,         al_p);  CPA16(d + TILE_B + 16,     al_p + 8);
        CPA16(d + 2 * TILE_B,     bh_p);  CPA16(d + 2 * TILE_B + 16, bh_p + 8);
        CP_COMMIT();
    }

    int r16 = lane & 15, c16 = lane >> 4;
    int r8  = lane & 7,  c8  = (lane >> 3) & 1;

    #pragma unroll 2
    for (int c = 0; c < KC; c++) {
        if (c + 1 < KC) {
            uint32_t d = sbase + ((c + 1) & 1) * STG3 + woff;
            int off = (c + 1) * 32;
            CPA16(d,                  ah_p + off);  CPA16(d + 16,              ah_p + off + 8);
            CPA16(d + TILE_B,         al_p + off);  CPA16(d + TILE_B + 16,     al_p + off + 8);
            CPA16(d + 2 * TILE_B,     bh_p + off);  CPA16(d + 2 * TILE_B + 16, bh_p + off + 8);
            CP_COMMIT();
            CP_WAIT(1);
        } else {
            CP_WAIT(0);
        }
        __syncthreads();
        {
            uint32_t base = sbase + (c & 1) * STG3;
            #pragma unroll
            for (int ks = 0; ks < 2; ks++) {
                uint32_t ah[2][4], al[2][4];
                #pragma unroll
                for (int mi = 0; mi < 2; mi++) {
                    uint32_t rel = (uint32_t)(wm + mi * 16 + r16) * RS_B
                                 + ks * 32 + c16 * 16;
                    LDSM4(ah[mi], base + rel);
                    LDSM4(al[mi], base + TILE_B + rel);
                }
                #pragma unroll
                for (int ni = 0; ni < 8; ni++) {
                    uint32_t rel = (uint32_t)(wn + ni * 8 + r8) * RS_B
                                 + ks * 32 + c8 * 16;
                    uint32_t bh0, bh1;
                    LDSM2(bh0, bh1, base + 2 * TILE_B + rel);
                    #pragma unroll
                    for (int mi = 0; mi < 2; mi++) {
                        mma16816(acc[mi][ni], ah[mi], bh0, bh1);
                        mma16816(acc[mi][ni], al[mi], bh0, bh1);
                    }
                }
            }
        }
        __syncthreads();
    }

    int g = lane >> 2, t4 = lane & 3;
    #pragma unroll
    for (int mi = 0; mi < 2; mi++) {
        int row0 = m0 + wm + mi * 16 + g;
        #pragma unroll
        for (int ni = 0; ni < 8; ni++) {
            int col = n0 + wn + ni * 8 + 2 * t4;
            float2 bi = *(const float2*)(bias + col);
            float2 o0, o1;
            o0.x = acc[mi][ni][0] + bi.x;
            o0.y = acc[mi][ni][1] + bi.y;
            o1.x = acc[mi][ni][2] + bi.x;
            o1.y = acc[mi][ni][3] + bi.y;
            if (GELU) {
                o0.x = gelu_tanh(o0.x); o0.y = gelu_tanh(o0.y);
                o1.x = gelu_tanh(o1.x); o1.y = gelu_tanh(o1.y);
            }
            size_t i0 = (size_t)row0 * N + col;
            size_t i1 = (size_t)(row0 + 8) * N + col;
            if (WF32) {
                *(float2*)(C + i0) = o0;
                *(float2*)(C + i1) = o1;
            }
            if (WSPL) {
                uint32_t h0, l0, h1, l1;
                split2h(o0.x, o0.y, h0, l0);
                split2h(o1.x, o1.y, h1, l1);
                *(uint32_t*)(Chi + i0) = h0;
                *(uint32_t*)(Clo + i0) = l0;
                *(uint32_t*)(Chi + i1) = h1;
                *(uint32_t*)(Clo + i1) = l1;
            }
        }
    }
}

// ---------------- embedding + LN ----------------
__global__ void __launch_bounds__(256) embed_ln_kernel(
    const int* __restrict__ ids, const float* __restrict__ tok,
    const float* __restrict__ pos, const float* __restrict__ g,
    const float* __restrict__ b, float* __restrict__ x,
    __half* __restrict__ xh, __half* __restrict__ xl)
{
    int t = blockIdx.x, s = t & (SEQ - 1), id = ids[t];
    float val[3];
    #pragma unroll
    for (int j = 0; j < 3; j++) {
        int i = threadIdx.x + j * 256;
        val[j] = tok[(size_t)id * Dm + i] + pos[(size_t)s * Dm + i];
    }
    float mean = blk_sum256(val[0] + val[1] + val[2]) * (1.f / 768.f);
    float sq = 0.f;
    #pragma unroll
    for (int j = 0; j < 3; j++) { float d = val[j] - mean; sq += d * d; }
    float rstd = rsqrtf(blk_sum256(sq) * (1.f / 768.f) + 1e-12f);
    #pragma unroll
    for (int j = 0; j < 3; j++) {
        int i = threadIdx.x + j * 256;
        float o = (val[j] - mean) * rstd * g[i] + b[i];
        size_t idx = (size_t)t * Dm + i;
        x[idx] = o;
        __half h = __float2half_rn(o);
        xh[idx] = h;
        xl[idx] = __float2half_rn(o - __half2float(h));
    }
}

// ---------------- residual add + LN ----------------
__global__ void __launch_bounds__(256) add_ln_kernel(
    float* __restrict__ x, const float* __restrict__ y,
    const float* __restrict__ g, const float* __restrict__ b,
    __half* __restrict__ xh, __half* __restrict__ xl)
{
    size_t t = blockIdx.x;
    float* xp = x + t * Dm;
    const float* yp = y + t * Dm;
    float val[3];
    #pragma unroll
    for (int j = 0; j < 3; j++) {
        int i = threadIdx.x + j * 256;
        val[j] = xp[i] + yp[i];
    }
    float mean = blk_sum256(val[0] + val[1] + val[2]) * (1.f / 768.f);
    float sq = 0.f;
    #pragma unroll
    for (int j = 0; j < 3; j++) { float d = val[j] - mean; sq += d * d; }
    float rstd = rsqrtf(blk_sum256(sq) * (1.f / 768.f) + 1e-12f);
    #pragma unroll
    for (int j = 0; j < 3; j++) {
        int i = threadIdx.x + j * 256;
        float o = (val[j] - mean) * rstd * g[i] + b[i];
        xp[i] = o;
        __half h = __float2half_rn(o);
        xh[t * Dm + i] = h;
        xl[t * Dm + i] = __float2half_rn(o - __half2float(h));
    }
}

// ================= attention (fp16, 3-term compensated) =================
#define ARS 144
#define A_QH 0
#define A_QL 9216
#define A_KH 18432
#define A_SMEM 55296
#define D_GRP 36864
#define D_G0  18432
#define D_SMEM (18432 + 2*D_GRP)
#define D_MRG 18432

struct AttnState {
    float m0, m1, l0, l1;
    float co[8][4];
};

__device__ __forceinline__ void stage_kv(
    const __half* __restrict__ qkvh, const __half* __restrict__ qkvl,
    size_t kbase, uint32_t dk, uint32_t dkl, uint32_t dv, uint32_t dvl)
{
    size_t vbase = kbase + Dm;
    CPA16(dk,      qkvh + kbase);      CPA16(dk + 16, qkvh + kbase + 8);
    CPA16(dk + 32, qkvh + kbase + 16); CPA16(dk + 48, qkvh + kbase + 24);
    CPA16(dkl,      qkvl + kbase);      CPA16(dkl + 16, qkvl + kbase + 8);
    CPA16(dkl + 32, qkvl + kbase + 16); CPA16(dkl + 48, qkvl + kbase + 24);
    CPA16(dv,      qkvh + vbase);      CPA16(dv + 16, qkvh + vbase + 8);
    CPA16(dv + 32, qkvh + vbase + 16); CPA16(dv + 48, qkvh + vbase + 24);
    CPA16(dvl,      qkvl + vbase);      CPA16(dvl + 16, qkvl + vbase + 8);
    CPA16(dvl + 32, qkvl + vbase + 16); CPA16(dvl + 48, qkvl + vbase + 24);
    CP_COMMIT(); CP_WAIT(0);
}

__device__ __forceinline__ void attn_block(
    AttnState& st, const uint32_t qfh[4][4], const uint32_t qfl[4][4],
    uint32_t sbase, uint32_t offKH, int lane)
{
    const uint32_t dKL = 9216, dVH = 18432, dVL = 27648;
    uint32_t kb_h = sbase + offKH + (uint32_t)(lane & 7) * ARS + ((lane >> 3) & 1) * 16;
    float sc[8][4];
    #pragma unroll
    for (int ni = 0; ni < 8; ni++)
        #pragma unroll
        for (int t = 0; t < 4; t++) sc[ni][t] = 0.f;
    #pragma unroll
    for (int ni = 0; ni < 8; ni++) {
        uint32_t ba_h = kb_h + (uint32_t)(ni * 8) * ARS;
        #pragma unroll
        for (int ks = 0; ks < 4; ks++) {
            uint32_t bh0, bh1, bl0, bl1;
            LDSM2(bh0, bh1, ba_h + ks * 32);
            LDSM2(bl0, bl1, ba_h + dKL + ks * 32);
            mma16816(sc[ni], qfh[ks], bh0, bh1);
            mma16816(sc[ni], qfh[ks], bl0, bl1);
            mma16816(sc[ni], qfl[ks], bh0, bh1);
        }
    }
    #pragma unroll
    for (int ni = 0; ni < 8; ni++) {
        sc[ni][0] *= 0.125f; sc[ni][1] *= 0.125f;
        sc[ni][2] *= 0.125f; sc[ni][3] *= 0.125f;
    }
    float bm0 = -1e30f, bm1 = -1e30f;
    #pragma unroll
    for (int ni = 0; ni < 8; ni++) {
        bm0 = fmaxf(bm0, fmaxf(sc[ni][0], sc[ni][1]));
        bm1 = fmaxf(bm1, fmaxf(sc[ni][2], sc[ni][3]));
    }
    bm0 = fmaxf(bm0, __shfl_xor_sync(0xffffffffu, bm0, 1));
    bm0 = fmaxf(bm0, __shfl_xor_sync(0xffffffffu, bm0, 2));
    bm1 = fmaxf(bm1, __shfl_xor_sync(0xffffffffu, bm1, 1));
    bm1 = fmaxf(bm1, __shfl_xor_sync(0xffffffffu, bm1, 2));
    float mn0 = fmaxf(st.m0, bm0), mn1 = fmaxf(st.m1, bm1);
    float corr0 = __expf(st.m0 - mn0), corr1 = __expf(st.m1 - mn1);
    st.m0 = mn0; st.m1 = mn1;
    #pragma unroll
    for (int nd = 0; nd < 8; nd++) {
        st.co[nd][0] *= corr0; st.co[nd][1] *= corr0;
        st.co[nd][2] *= corr1; st.co[nd][3] *= corr1;
    }
    float ls0 = 0.f, ls1 = 0.f;
    #pragma unroll
    for (int ni = 0; ni < 8; ni++) {
        sc[ni][0] = __expf(sc[ni][0] - mn0);
        sc[ni][1] = __expf(sc[ni][1] - mn0);
        sc[ni][2] = __expf(sc[ni][2] - mn1);
        sc[ni][3] = __expf(sc[ni][3] - mn1);
        ls0 += sc[ni][0] + sc[ni][1];
        ls1 += sc[ni][2] + sc[ni][3];
    }
    ls0 += __shfl_xor_sync(0xffffffffu, ls0, 1);
    ls0 += __shfl_xor_sync(0xffffffffu, ls0, 2);
    ls1 += __shfl_xor_sync(0xffffffffu, ls1, 1);
    ls1 += __shfl_xor_sync(0xffffffffu, ls1, 2);
    st.l0 = st.l0 * corr0 + ls0;
    st.l1 = st.l1 * corr1 + ls1;

    uint32_t pah[4][4], pal[4][4];
    #pragma unroll
    for (int ksp = 0; ksp < 4; ksp++) {
        split2h(sc[2*ksp][0],   sc[2*ksp][1],   pah[ksp][0], pal[ksp][0]);
        split2h(sc[2*ksp][2],   sc[2*ksp][3],   pah[ksp][1], pal[ksp][1]);
        split2h(sc[2*ksp+1][0], sc[2*ksp+1][1], pah[ksp][2], pal[ksp][2]);
        split2h(sc[2*ksp+1][2], sc[2*ksp+1][3], pah[ksp][3], pal[ksp][3]);
    }
    #pragma unroll
    for (int nd = 0; nd < 8; nd++) {
        #pragma unroll
        for (int ksp = 0; ksp < 4; ksp++) {
            uint32_t va = sbase + offKH + dVH
                        + (uint32_t)(ksp * 16 + (lane & 15)) * ARS + nd * 16;
            uint32_t vh0, vh1, vl0, vl1;
            LDSM2T(vh0, vh1, va);
            LDSM2T(vl0, vl1, va + (dVL - dVH));
            mma16816(st.co[nd], pah[ksp], vh0, vh1);
            mma16816(st.co[nd], pah[ksp], vl0, vl1);
            mma16816(st.co[nd], pal[ksp], vh0, vh1);
        }
    }
}

__device__ __forceinline__ void load_q_frags(
    uint32_t sbase, int warp_q, int lane, uint32_t qfh[4][4], uint32_t qfl[4][4])
{
    uint32_t qa_h = sbase + A_QH + (uint32_t)(warp_q * 16 + (lane & 15)) * ARS + (lane >> 4) * 16;
    uint32_t qa_l = qa_h + (A_QL - A_QH);
    #pragma unroll
    for (int ks = 0; ks < 4; ks++) {
        LDSM4(qfh[ks], qa_h + ks * 32);
        LDSM4(qfl[ks], qa_l + ks * 32);
    }
}

__device__ __forceinline__ void stage_q(
    const __half* __restrict__ qkvh, const __half* __restrict__ qkvl,
    uint32_t sbase, int b, int qb, int h, int srow, int shalf)
{
    size_t off = ((size_t)(b * SEQ + qb * BLKS + srow)) * QKVD + h * DHd + shalf * 32;
    uint32_t dh = sbase + A_QH + (uint32_t)srow * ARS + shalf * 64;
    uint32_t dl = sbase + A_QL + (uint32_t)srow * ARS + shalf * 64;
    CPA16(dh,      qkvh + off);      CPA16(dh + 16, qkvh + off + 8);
    CPA16(dh + 32, qkvh + off + 16); CPA16(dh + 48, qkvh + off + 24);
    CPA16(dl,      qkvl + off);      CPA16(dl + 16, qkvl + off + 8);
    CPA16(dl + 32, qkvl + off + 16); CPA16(dl + 48, qkvl + off + 24);
    CP_COMMIT(); CP_WAIT(0);
}

// ---------------- sparse attention ----------------
__global__ void __launch_bounds__(128) attn_sparse_kernel(
    const __half* __restrict__ qkvh, const __half* __restrict__ qkvl,
    const int* __restrict__ rb,
    __half* __restrict__ ch_g, __half* __restrict__ cl_g)
{
    extern __shared__ char sb[];
    uint32_t sbase = s2u(sb);
    int b = blockIdx.z, h = blockIdx.y, qb = blockIdx.x + 1;
    int tid = threadIdx.x, lane = tid & 31, w = tid >> 5;
    int srow = tid >> 1, shalf = tid & 1;

    stage_q(qkvh, qkvl, sbase, b, qb, h, srow, shalf);
    __syncthreads();

    uint32_t qfh[4][4], qfl[4][4];
    load_q_frags(sbase, w, lane, qfh, qfl);

    AttnState st;
    st.m0 = st.m1 = -1e30f; st.l0 = st.l1 = 0.f;
    #pragma unroll
    for (int nd = 0; nd < 8; nd++)
        #pragma unroll
        for (int t = 0; t < 4; t++) st.co[nd][t] = 0.f;

    int blist[8];
    blist[0] = 0; blist[1] = qb - 1; blist[2] = qb; blist[3] = qb + 1;
    blist[4] = NB - 1;
    const int* rp = rb + (h * NB + qb) * RR;
    blist[5] = rp[0]; blist[6] = rp[1]; blist[7] = rp[2];

    uint32_t dk  = sbase + A_KH + (uint32_t)srow * ARS + shalf * 64;
    uint32_t dkl = dk + 9216, dv = dk + 18432, dvl = dk + 27648;

    for (int jb = 0; jb < 8; jb++) {
        int kb = blist[jb];
        size_t kbase = ((size_t)(b * SEQ + kb * BLKS + srow)) * QKVD + Dm + h * DHd + shalf * 32;
        __syncthreads();
        stage_kv(qkvh, qkvl, kbase, dk, dkl, dv, dvl);
        __syncthreads();
        attn_block(st, qfh, qfl, sbase, A_KH, lane);
    }

    float inv0 = 1.f / st.l0, inv1 = 1.f / st.l1;
    int g = lane >> 2, t4 = lane & 3;
    size_t rbase = ((size_t)(b * SEQ + qb * BLKS + w * 16 + g)) * Dm + h * DHd;
    #pragma unroll
    for (int nd = 0; nd < 8; nd++) {
        int col = nd * 8 + 2 * t4;
        uint32_t h0, l0w, h1, l1w;
        split2h(st.co[nd][0] * inv0, st.co[nd][1] * inv0, h0, l0w);
        split2h(st.co[nd][2] * inv1, st.co[nd][3] * inv1, h1, l1w);
        *(uint32_t*)(ch_g + rbase + col)          = h0;
        *(uint32_t*)(cl_g + rbase + col)          = l0w;
        *(uint32_t*)(ch_g + rbase + 8 * Dm + col) = h1;
        *(uint32_t*)(cl_g + rbase + 8 * Dm + col) = l1w;
    }
}

// ---------------- dense attention (query blocks 0, NB-1) ----------------
__global__ void __launch_bounds__(256) attn_dense_kernel(
    const __half* __restrict__ qkvh, const __half* __restrict__ qkvl,
    __half* __restrict__ ch_g, __half* __restrict__ cl_g)
{
    extern __shared__ char sb[];
    uint32_t sbase = s2u(sb);
    int b = blockIdx.z, h = blockIdx.y;
    int qb = (blockIdx.x == 0) ? 0 : NB - 1;
    int tid = threadIdx.x, lane = tid & 31;
    int grp = tid >> 7, ltid = tid & 127, w = ltid >> 5;
    int srow = ltid >> 1, shalf = ltid & 1;

    if (grp == 0) stage_q(qkvh, qkvl, sbase, b, qb, h, srow, shalf);
    __syncthreads();

    uint32_t qfh[4][4], qfl[4][4];
    load_q_frags(sbase, w, lane, qfh, qfl);

    AttnState st;
    st.m0 = st.m1 = -1e30f; st.l0 = st.l1 = 0.f;
    #pragma unroll
    for (int nd = 0; nd < 8; nd++)
        #pragma unroll
        for (int t = 0; t < 4; t++) st.co[nd][t] = 0.f;

    uint32_t gbase = D_G0 + grp * D_GRP;
    uint32_t dk  = sbase + gbase + (uint32_t)srow * ARS + shalf * 64;
    uint32_t dkl = dk + 9216, dv = dk + 18432, dvl = dk + 27648;

    for (int jb = 0; jb < 32; jb++) {
        int kb = grp * 32 + jb;
        size_t kbase = ((size_t)(b * SEQ + kb * BLKS + srow)) * QKVD + Dm + h * DHd + shalf * 32;
        __syncthreads();
        stage_kv(qkvh, qkvl, kbase, dk, dkl, dv, dvl);
        __syncthreads();
        attn_block(st, qfh, qfl, sbase, gbase, lane);
    }

    __syncthreads();
    float* mg = (float*)(sb + D_MRG);
    int slot = (w * 32 + lane) * 36;
    if (grp == 1) {
        #pragma unroll
        for (int nd = 0; nd < 8; nd++)
            #pragma unroll
            for (int t = 0; t < 4; t++) mg[slot + nd * 4 + t] = st.co[nd][t];
        mg[slot + 32] = st.m0; mg[slot + 33] = st.m1;
        mg[slot + 34] = st.l0; mg[slot + 35] = st.l1;
    }
    __syncthreads();
    if (grp == 0) {
        float mB0 = mg[slot + 32], mB1 = mg[slot + 33];
        float lB0 = mg[slot + 34], lB1 = mg[slot + 35];
        float M0 = fmaxf(st.m0, mB0), M1 = fmaxf(st.m1, mB1);
        float cA0 = __expf(st.m0 - M0), cB0 = __expf(mB0 - M0);
        float cA1 = __expf(st.m1 - M1), cB1 = __expf(mB1 - M1);
        float L0 = st.l0 * cA0 + lB0 * cB0;
        float L1 = st.l1 * cA1 + lB1 * cB1;
        float inv0 = 1.f / L0, inv1 = 1.f / L1;
        int g = lane >> 2, t4 = lane & 3;
        size_t rbase = ((size_t)(b * SEQ + qb * BLKS + w * 16 + g)) * Dm + h * DHd;
        #pragma unroll
        for (int nd = 0; nd < 8; nd++) {
            float r0 = (st.co[nd][0] * cA0 + mg[slot + nd * 4 + 0] * cB0) * inv0;
            float r1 = (st.co[nd][1] * cA0 + mg[slot + nd * 4 + 1] * cB0) * inv0;
            float r2 = (st.co[nd][2] * cA1 + mg[slot + nd * 4 + 2] * cB1) * inv1;
            float r3 = (st.co[nd][3] * cA1 + mg[slot + nd * 4 + 3] * cB1) * inv1;
            int col = nd * 8 + 2 * t4;
            uint32_t h0, l0w, h1, l1w;
            split2h(r0, r1, h0, l0w);
            split2h(r2, r3, h1, l1w);
            *(uint32_t*)(ch_g + rbase + col)          = h0;
            *(uint32_t*)(cl_g + rbase + col)          = l0w;
            *(uint32_t*)(ch_g + rbase + 8 * Dm + col) = h1;
            *(uint32_t*)(cl_g + rbase + 8 * Dm + col) = l1w;
        }
    }
}

// ---------------- mean pool + linear head ----------------
__global__ void __launch_bounds__(256) pool1_kernel(
    const float* __restrict__ x, const float* __restrict__ w, float* __restrict__ part)
{
    int b = blockIdx.y, sl = blockIdx.x;
    const float* xb = x + ((size_t)b * SEQ + sl * 128) * Dm;
    __shared__ float ws[Dm];
    for (int i = threadIdx.x; i < Dm; i += 256) ws[i] = w[i];
    __syncthreads();
    float acc = 0.f;
    for (int r = 0; r < 128; r++) {
        const float* xr = xb + (size_t)r * Dm;
        for (int i = threadIdx.x; i < Dm; i += 256) acc += xr[i] * ws[i];
    }
    float t = blk_sum256(acc);
    if (threadIdx.x == 0) part[b * 32 + sl] = t;
}
__global__ void pool2_kernel(const float* __restrict__ part,
                             const float* __restrict__ fb, float* __restrict__ out)
{
    int b = threadIdx.x;
    if (b < BB) {
        float s = 0.f;
        for (int i = 0; i < 32; i++) s += part[b * 32 + i];
        out[b] = s * (1.f / (float)SEQ) + fb[0];
    }
}

// ---------------- driver ----------------
extern "C" void kernel_launch(void* const* d_in, const int* in_sizes, int n_in,
                              void* d_out, int out_size)
{
    const int*   ids     = (const int*)  d_in[0];
    const int*   rb      = (const int*)  d_in[1];
    const float* emb_tok = (const float*)d_in[2];
    const float* emb_pos = (const float*)d_in[3];
    const float* lng     = (const float*)d_in[4];
    const float* lnb     = (const float*)d_in[5];
    const float* Wq = (const float*)d_in[6];  const float* bq = (const float*)d_in[7];
    const float* Wk = (const float*)d_in[8];  const float* bk = (const float*)d_in[9];
    const float* Wv = (const float*)d_in[10]; const float* bv = (const float*)d_in[11];
    const float* Wo = (const float*)d_in[12]; const float* bo = (const float*)d_in[13];
    const float* ln1g = (const float*)d_in[14]; const float* ln1b = (const float*)d_in[15];
    const float* W1 = (const float*)d_in[16]; const float* b1 = (const float*)d_in[17];
    const float* W2 = (const float*)d_in[18]; const float* b2 = (const float*)d_in[19];
    const float* ln2g = (const float*)d_in[20]; const float* ln2b = (const float*)d_in[21];
    const float* fcw = (const float*)d_in[22]; const float* fcb = (const float*)d_in[23];

    float *x, *tmp, *part, *bqkv;
    __half *xh, *xl, *qkvh, *qkvl, *ch, *cl, *fh, *fl, *wh;
    cudaGetSymbolAddress((void**)&x,   g_x);
    cudaGetSymbolAddress((void**)&tmp, g_tmp);
    cudaGetSymbolAddress((void**)&xh,  g_xh);
    cudaGetSymbolAddress((void**)&xl,  g_xl);
    cudaGetSymbolAddress((void**)&qkvh, g_qkvh);
    cudaGetSymbolAddress((void**)&qkvl, g_qkvl);
    cudaGetSymbolAddress((void**)&ch,  g_ch);
    cudaGetSymbolAddress((void**)&cl,  g_cl);
    cudaGetSymbolAddress((void**)&fh,  g_fh);
    cudaGetSymbolAddress((void**)&fl,  g_fl);
    cudaGetSymbolAddress((void**)&wh,  g_wh);
    cudaGetSymbolAddress((void**)&bqkv, g_bqkv);
    cudaGetSymbolAddress((void**)&part, g_part);

    const int SMEM_GEMM = 2 * STG3;   // 61440
    cudaFuncSetAttribute((const void*)gemm_mma<0,0,1,24>,
                         cudaFuncAttributeMaxDynamicSharedMemorySize, SMEM_GEMM);
    cudaFuncSetAttribute((const void*)gemm_mma<0,1,0,24>,
                         cudaFuncAttributeMaxDynamicSharedMemorySize, SMEM_GEMM);
    cudaFuncSetAttribute((const void*)gemm_mma<1,0,1,24>,
                         cudaFuncAttributeMaxDynamicSharedMemorySize, SMEM_GEMM);
    cudaFuncSetAttribute((const void*)gemm_mma<0,1,0,96>,
                         cudaFuncAttributeMaxDynamicSharedMemorySize, SMEM_GEMM);
    cudaFuncSetAttribute((const void*)attn_sparse_kernel,
                         cudaFuncAttributeMaxDynamicSharedMemorySize, A_SMEM);
    cudaFuncSetAttribute((const void*)attn_dense_kernel,
                         cudaFuncAttributeMaxDynamicSharedMemorySize, D_SMEM);

    dim3 gQKV(QKVD / 128, NTOK / 128);
    dim3 gO(Dm / 128, NTOK / 128);
    dim3 gF(FF / 128, NTOK / 128);
    dim3 gAttS(NB - 2, Hh, BB);
    dim3 gAttD(2, Hh, BB);
    dim3 gWS(Dm / 32, Dm / 32);

    // launches 0-3: layer-0 weight prep; launch 4: embed; launch 5: QKV GEMM (ncu)
    wsplit3_kernel<<<dim3(Dm / 32, Dm / 32, 3), 256>>>(
        Wq, Wk, Wv, wh, bq, bk, bv, bqkv);
    wsplit_kernel<<<gWS, 256>>>(Wo, wh + 3 * (size_t)WSZ, Dm, Dm);
    wsplit_kernel<<<dim3(FF / 32, Dm / 32), 256>>>(W1, wh + 4 * (size_t)WSZ, Dm, FF);
    wsplit_kernel<<<dim3(Dm / 32, FF / 32), 256>>>(W2, wh + 4 * (size_t)WSZ + W1SZ, FF, Dm);
    embed_ln_kernel<<<NTOK, 256>>>(ids, emb_tok, emb_pos, lng, lnb, x, xh, xl);

    for (int l = 0; l < 2; l++) {
        size_t o = (size_t)l * OFFL;
        gemm_mma<0,0,1,24><<<gQKV, 256, SMEM_GEMM>>>(xh, xl, wh + o, bqkv + l * QKVD,
            nullptr, qkvh, qkvl, NTOK, QKVD);
        attn_sparse_kernel<<<gAttS, 128, A_SMEM>>>(qkvh, qkvl, rb, ch, cl);
        attn_dense_kernel<<<gAttD, 256, D_SMEM>>>(qkvh, qkvl, ch, cl);
        gemm_mma<0,1,0,24><<<gO, 256, SMEM_GEMM>>>(ch, cl, wh + o + 3 * WSZ,
            bo + l * Dm, tmp, nullptr, nullptr, NTOK, Dm);
        add_ln_kernel<<<NTOK, 256>>>(x, tmp, ln1g + l * Dm, ln1b + l * Dm, xh, xl);
        gemm_mma<1,0,1,24><<<gF, 256, SMEM_GEMM>>>(xh, xl, wh + o + 4 * WSZ,
            b1 + l * FF, nullptr, fh, fl, NTOK, FF);
        gemm_mma<0,1,0,96><<<gO, 256, SMEM_GEMM>>>(fh, fl, wh + o + 4 * WSZ + W1SZ,
            b2 + l * Dm, tmp, nullptr, nullptr, NTOK, Dm);
        add_ln_kernel<<<NTOK, 256>>>(x, tmp, ln2g + l * Dm, ln2b + l * Dm, xh, xl);

        if (l == 0) {   // layer-1 weight prep (after profiled window)
            size_t o1 = OFFL;
            wsplit3_kernel<<<dim3(Dm / 32, Dm / 32, 3), 256>>>(
                Wq + WSZ, Wk + WSZ, Wv + WSZ, wh + o1,
                bq + Dm, bk + Dm, bv + Dm, bqkv + QKVD);
            wsplit_kernel<<<gWS, 256>>>(Wo + WSZ, wh + o1 + 3 * (size_t)WSZ, Dm, Dm);
            wsplit_kernel<<<dim3(FF / 32, Dm / 32), 256>>>(W1 + W1SZ, wh + o1 + 4 * (size_t)WSZ, Dm, FF);
            wsplit_kernel<<<dim3(Dm / 32, FF / 32), 256>>>(W2 + W1SZ, wh + o1 + 4 * (size_t)WSZ + W1SZ, FF, Dm);
        }
    }

    pool1_kernel<<<dim3(32, BB), 256>>>(x, fcw, part);
    pool2_kernel<<<1, 32>>>(part, fcb, (float*)d_out);
}

// round 9
// speedup vs baseline: 1.7501x; 1.7501x over previous
#include <cuda_runtime.h>
#include <cuda_fp16.h>
#include <math.h>
#include <stdint.h>

// ---------------- problem constants ----------------
#define Dm   768
#define Hh   12
#define DHd  64
#define BLKS 64
#define NB   64
#define SEQ  4096
#define BB   2
#define NTOK (BB*SEQ)
#define RR   3
#define FF   3072
#define QKVD 2304

#define WSZ   589824
#define W1SZ  2359296
#define OFFL  (4*WSZ + 2*W1SZ)

// ---------------- scratch (device globals) ----------------
__device__ float g_x  [NTOK*Dm];
__device__ float g_tmp[NTOK*Dm];
__device__ __half g_xh [NTOK*Dm];
__device__ __half g_xl [NTOK*Dm];
__device__ __half g_qkvh[NTOK*QKVD];
__device__ __half g_qkvl[NTOK*QKVD];
__device__ __half g_ch [NTOK*Dm];
__device__ __half g_fh [NTOK*FF];
__device__ __half g_wh [2*OFFL];
__device__ float g_bqkv[2*QKVD];
__device__ float g_part[64];

// ---------------- helpers ----------------
__device__ __forceinline__ float gelu_tanh(float x) {
    float x3 = x * x * x;
    return 0.5f * x * (1.f + tanhf(0.7978845608028654f * (x + 0.044715f * x3)));
}

__device__ __forceinline__ float blk_sum256(float v) {
    __shared__ float red[32];
    int lane = threadIdx.x & 31, wid = threadIdx.x >> 5;
    #pragma unroll
    for (int o = 16; o > 0; o >>= 1) v += __shfl_xor_sync(0xffffffffu, v, o);
    if (lane == 0) red[wid] = v;
    __syncthreads();
    if (wid == 0) {
        v = (lane < 8) ? red[lane] : 0.f;
        #pragma unroll
        for (int o = 4; o > 0; o >>= 1) v += __shfl_xor_sync(0xffffffffu, v, o);
        if (lane == 0) red[0] = v;
    }
    __syncthreads();
    float r = red[0];
    __syncthreads();
    return r;
}

__device__ __forceinline__ uint32_t s2u(const void* p) {
    uint32_t a;
    asm("{ .reg .u64 t; cvta.to.shared.u64 t, %1; cvt.u32.u64 %0, t; }" : "=r"(a) : "l"(p));
    return a;
}

#define LDSM4(r, a) \
    asm volatile("ldmatrix.sync.aligned.m8n8.x4.shared.b16 {%0,%1,%2,%3}, [%4];" \
        : "=r"((r)[0]), "=r"((r)[1]), "=r"((r)[2]), "=r"((r)[3]) : "r"(a))
#define LDSM2(r0, r1, a) \
    asm volatile("ldmatrix.sync.aligned.m8n8.x2.shared.b16 {%0,%1}, [%2];" \
        : "=r"(r0), "=r"(r1) : "r"(a))
#define LDSM2T(r0, r1, a) \
    asm volatile("ldmatrix.sync.aligned.m8n8.x2.trans.shared.b16 {%0,%1}, [%2];" \
        : "=r"(r0), "=r"(r1) : "r"(a))

#define CPA16(dst, src) \
    asm volatile("cp.async.cg.shared.global [%0], [%1], 16;" :: "r"(dst), "l"(src))
#define CP_COMMIT() asm volatile("cp.async.commit_group;" ::: "memory")
#define CP_WAIT(n)  asm volatile("cp.async.wait_group %0;" :: "n"(n) : "memory")

__device__ __forceinline__ void mma16816(float* c, const uint32_t* a,
                                         uint32_t b0, uint32_t b1) {
    asm volatile(
        "mma.sync.aligned.m16n8k16.row.col.f32.f16.f16.f32 "
        "{%0,%1,%2,%3}, {%4,%5,%6,%7}, {%8,%9}, {%0,%1,%2,%3};"
        : "+f"(c[0]), "+f"(c[1]), "+f"(c[2]), "+f"(c[3])
        : "r"(a[0]), "r"(a[1]), "r"(a[2]), "r"(a[3]), "r"(b0), "r"(b1));
}

__device__ __forceinline__ void split2h(float a, float b, uint32_t& hi, uint32_t& lo) {
    __half ha = __float2half_rn(a);
    __half hb = __float2half_rn(b);
    __half la = __float2half_rn(a - __half2float(ha));
    __half lb = __float2half_rn(b - __half2float(hb));
    hi = (uint32_t)__half_as_ushort(ha) | ((uint32_t)__half_as_ushort(hb) << 16);
    lo = (uint32_t)__half_as_ushort(la) | ((uint32_t)__half_as_ushort(lb) << 16);
}

__device__ __forceinline__ uint32_t pack2h(float a, float b) {
    __half2 h = __floats2half2_rn(a, b);
    return *(uint32_t*)&h;
}

// ---------------- weight transpose + fp16 convert ----------------
__global__ void __launch_bounds__(256) wsplit_kernel(
    const float* __restrict__ W, __half* __restrict__ hi, int K, int N)
{
    __shared__ float t[32][33];
    int n0 = blockIdx.x * 32, k0 = blockIdx.y * 32;
    int tx = threadIdx.x & 31, ty = threadIdx.x >> 5;
    #pragma unroll
    for (int j = 0; j < 4; j++)
        t[ty + j * 8][tx] = W[(size_t)(k0 + ty + j * 8) * N + n0 + tx];
    __syncthreads();
    #pragma unroll
    for (int j = 0; j < 4; j++) {
        int n = n0 + ty + j * 8, k = k0 + tx;
        hi[(size_t)n * K + k] = __float2half_rn(t[tx][ty + j * 8]);
    }
}

__global__ void __launch_bounds__(256) wsplit3_kernel(
    const float* __restrict__ Wa, const float* __restrict__ Wb,
    const float* __restrict__ Wc, __half* __restrict__ hi,
    const float* __restrict__ ba, const float* __restrict__ bb,
    const float* __restrict__ bc, float* __restrict__ bqkv)
{
    __shared__ float t[32][33];
    int z = blockIdx.z;
    const float* W = (z == 0) ? Wa : (z == 1) ? Wb : Wc;
    __half* hz = hi + (size_t)z * WSZ;
    int n0 = blockIdx.x * 32, k0 = blockIdx.y * 32;
    int tx = threadIdx.x & 31, ty = threadIdx.x >> 5;
    if (blockIdx.x == 0 && blockIdx.y == 0) {
        const float* bz = (z == 0) ? ba : (z == 1) ? bb : bc;
        for (int i = threadIdx.x; i < Dm; i += 256) bqkv[z * Dm + i] = bz[i];
    }
    #pragma unroll
    for (int j = 0; j < 4; j++)
        t[ty + j * 8][tx] = W[(size_t)(k0 + ty + j * 8) * Dm + n0 + tx];
    __syncthreads();
    #pragma unroll
    for (int j = 0; j < 4; j++) {
        int n = n0 + ty + j * 8, k = k0 + tx;
        hz[(size_t)n * Dm + k] = __float2half_rn(t[tx][ty + j * 8]);
    }
}

// ---------------- cp.async warp-MMA GEMM ----------------
// AT2=1: A = hi+lo fp16 (2 MMA terms); AT2=0: A = hi only (1 term).
// WSPL: 0=none, 1=write Chi+Clo (split), 2=write Chi only (fp16 rn).
#define RS_B   80
#define TILE_B (128*RS_B)

template<int GELU, int WF32, int WSPL, int AT2, int KC>
__global__ void __launch_bounds__(256, 2) gemm_mma(
    const __half* __restrict__ Ahi, const __half* __restrict__ Alo,
    const __half* __restrict__ Bh,
    const float* __restrict__ bias, float* __restrict__ C,
    __half* __restrict__ Chi, __half* __restrict__ Clo,
    int M, int N)
{
    const int K = KC * 32;
    const int STG  = (AT2 ? 3 : 2) * TILE_B;
    const int BOFF = (AT2 ? 2 : 1) * TILE_B;
    extern __shared__ char sm[];
    uint32_t sbase = s2u(sm);
    int tid = threadIdx.x, lane = tid & 31, wid = tid >> 5;
    int m0 = blockIdx.y * 128, n0 = blockIdx.x * 128;
    int wm = (wid & 3) * 32, wn = (wid >> 2) * 64;

    int lr = tid & 127, lh = tid >> 7;
    const __half* ah_p = Ahi + (size_t)(m0 + lr) * K + lh * 16;
    const __half* al_p = AT2 ? (Alo + (size_t)(m0 + lr) * K + lh * 16) : nullptr;
    const __half* bh_p = Bh  + (size_t)(n0 + lr) * K + lh * 16;
    uint32_t woff = (uint32_t)lr * RS_B + (uint32_t)lh * 32;

    float acc[2][8][4];
    #pragma unroll
    for (int i = 0; i < 2; i++)
        #pragma unroll
        for (int j = 0; j < 8; j++)
            #pragma unroll
            for (int t = 0; t < 4; t++) acc[i][j][t] = 0.f;

    {
        uint32_t d = sbase + woff;
        CPA16(d,          ah_p);  CPA16(d + 16,        ah_p + 8);
        if (AT2) { CPA16(d + TILE_B, al_p);  CPA16(d + TILE_B + 16, al_p + 8); }
        CPA16(d + BOFF,   bh_p);  CPA16(d + BOFF + 16, bh_p + 8);
        CP_COMMIT();
    }

    int r16 = lane & 15, c16 = lane >> 4;
    int r8  = lane & 7,  c8  = (lane >> 3) & 1;

    #pragma unroll 2
    for (int c = 0; c < KC; c++) {
        if (c + 1 < KC) {
            uint32_t d = sbase + ((c + 1) & 1) * STG + woff;
            int off = (c + 1) * 32;
            CPA16(d,          ah_p + off);  CPA16(d + 16,        ah_p + off + 8);
            if (AT2) { CPA16(d + TILE_B, al_p + off);  CPA16(d + TILE_B + 16, al_p + off + 8); }
            CPA16(d + BOFF,   bh_p + off);  CPA16(d + BOFF + 16, bh_p + off + 8);
            CP_COMMIT();
            CP_WAIT(1);
        } else {
            CP_WAIT(0);
        }
        __syncthreads();
        {
            uint32_t base = sbase + (c & 1) * STG;
            #pragma unroll
            for (int ks = 0; ks < 2; ks++) {
                uint32_t ah[2][4], al[2][4];
                #pragma unroll
                for (int mi = 0; mi < 2; mi++) {
                    uint32_t rel = (uint32_t)(wm + mi * 16 + r16) * RS_B
                                 + ks * 32 + c16 * 16;
                    LDSM4(ah[mi], base + rel);
                    if (AT2) LDSM4(al[mi], base + TILE_B + rel);
                }
                #pragma unroll
                for (int ni = 0; ni < 8; ni++) {
                    uint32_t rel = (uint32_t)(wn + ni * 8 + r8) * RS_B
                                 + ks * 32 + c8 * 16;
                    uint32_t bh0, bh1;
                    LDSM2(bh0, bh1, base + BOFF + rel);
                    #pragma unroll
                    for (int mi = 0; mi < 2; mi++) {
                        mma16816(acc[mi][ni], ah[mi], bh0, bh1);
                        if (AT2) mma16816(acc[mi][ni], al[mi], bh0, bh1);
                    }
                }
            }
        }
        __syncthreads();
    }

    int g = lane >> 2, t4 = lane & 3;
    #pragma unroll
    for (int mi = 0; mi < 2; mi++) {
        int row0 = m0 + wm + mi * 16 + g;
        #pragma unroll
        for (int ni = 0; ni < 8; ni++) {
            int col = n0 + wn + ni * 8 + 2 * t4;
            float2 bi = *(const float2*)(bias + col);
            float2 o0, o1;
            o0.x = acc[mi][ni][0] + bi.x;
            o0.y = acc[mi][ni][1] + bi.y;
            o1.x = acc[mi][ni][2] + bi.x;
            o1.y = acc[mi][ni][3] + bi.y;
            if (GELU) {
                o0.x = gelu_tanh(o0.x); o0.y = gelu_tanh(o0.y);
                o1.x = gelu_tanh(o1.x); o1.y = gelu_tanh(o1.y);
            }
            size_t i0 = (size_t)row0 * N + col;
            size_t i1 = (size_t)(row0 + 8) * N + col;
            if (WF32) {
                *(float2*)(C + i0) = o0;
                *(float2*)(C + i1) = o1;
            }
            if (WSPL == 1) {
                uint32_t h0, l0, h1, l1;
                split2h(o0.x, o0.y, h0, l0);
                split2h(o1.x, o1.y, h1, l1);
                *(uint32_t*)(Chi + i0) = h0;
                *(uint32_t*)(Clo + i0) = l0;
                *(uint32_t*)(Chi + i1) = h1;
                *(uint32_t*)(Clo + i1) = l1;
            }
            if (WSPL == 2) {
                *(uint32_t*)(Chi + i0) = pack2h(o0.x, o0.y);
                *(uint32_t*)(Chi + i1) = pack2h(o1.x, o1.y);
            }
        }
    }
}

// ---------------- embedding + LN ----------------
__global__ void __launch_bounds__(256) embed_ln_kernel(
    const int* __restrict__ ids, const float* __restrict__ tok,
    const float* __restrict__ pos, const float* __restrict__ g,
    const float* __restrict__ b, float* __restrict__ x,
    __half* __restrict__ xh, __half* __restrict__ xl)
{
    int t = blockIdx.x, s = t & (SEQ - 1), id = ids[t];
    float val[3];
    #pragma unroll
    for (int j = 0; j < 3; j++) {
        int i = threadIdx.x + j * 256;
        val[j] = tok[(size_t)id * Dm + i] + pos[(size_t)s * Dm + i];
    }
    float mean = blk_sum256(val[0] + val[1] + val[2]) * (1.f / 768.f);
    float sq = 0.f;
    #pragma unroll
    for (int j = 0; j < 3; j++) { float d = val[j] - mean; sq += d * d; }
    float rstd = rsqrtf(blk_sum256(sq) * (1.f / 768.f) + 1e-12f);
    #pragma unroll
    for (int j = 0; j < 3; j++) {
        int i = threadIdx.x + j * 256;
        float o = (val[j] - mean) * rstd * g[i] + b[i];
        size_t idx = (size_t)t * Dm + i;
        x[idx] = o;
        __half h = __float2half_rn(o);
        xh[idx] = h;
        xl[idx] = __float2half_rn(o - __half2float(h));
    }
}

// ---------------- residual add + LN ----------------
__global__ void __launch_bounds__(256) add_ln_kernel(
    float* __restrict__ x, const float* __restrict__ y,
    const float* __restrict__ g, const float* __restrict__ b,
    __half* __restrict__ xh, __half* __restrict__ xl)
{
    size_t t = blockIdx.x;
    float* xp = x + t * Dm;
    const float* yp = y + t * Dm;
    float val[3];
    #pragma unroll
    for (int j = 0; j < 3; j++) {
        int i = threadIdx.x + j * 256;
        val[j] = xp[i] + yp[i];
    }
    float mean = blk_sum256(val[0] + val[1] + val[2]) * (1.f / 768.f);
    float sq = 0.f;
    #pragma unroll
    for (int j = 0; j < 3; j++) { float d = val[j] - mean; sq += d * d; }
    float rstd = rsqrtf(blk_sum256(sq) * (1.f / 768.f) + 1e-12f);
    #pragma unroll
    for (int j = 0; j < 3; j++) {
        int i = threadIdx.x + j * 256;
        float o = (val[j] - mean) * rstd * g[i] + b[i];
        xp[i] = o;
        __half h = __float2half_rn(o);
        xh[t * Dm + i] = h;
        xl[t * Dm + i] = __float2half_rn(o - __half2float(h));
    }
}

// ================= attention (fp16, 3-term compensated) =================
#define ARS 144
#define A_QH 0
#define A_QL 9216
#define A_KH 18432
#define A_SMEM 55296
#define D_GRP 36864
#define D_G0  18432
#define D_SMEM (18432 + 2*D_GRP)
#define D_MRG 18432

struct AttnState {
    float m0, m1, l0, l1;
    float co[8][4];
};

__device__ __forceinline__ void stage_kv(
    const __half* __restrict__ qkvh, const __half* __restrict__ qkvl,
    size_t kbase, uint32_t dk, uint32_t dkl, uint32_t dv, uint32_t dvl)
{
    size_t vbase = kbase + Dm;
    CPA16(dk,      qkvh + kbase);      CPA16(dk + 16, qkvh + kbase + 8);
    CPA16(dk + 32, qkvh + kbase + 16); CPA16(dk + 48, qkvh + kbase + 24);
    CPA16(dkl,      qkvl + kbase);      CPA16(dkl + 16, qkvl + kbase + 8);
    CPA16(dkl + 32, qkvl + kbase + 16); CPA16(dkl + 48, qkvl + kbase + 24);
    CPA16(dv,      qkvh + vbase);      CPA16(dv + 16, qkvh + vbase + 8);
    CPA16(dv + 32, qkvh + vbase + 16); CPA16(dv + 48, qkvh + vbase + 24);
    CPA16(dvl,      qkvl + vbase);      CPA16(dvl + 16, qkvl + vbase + 8);
    CPA16(dvl + 32, qkvl + vbase + 16); CPA16(dvl + 48, qkvl + vbase + 24);
    CP_COMMIT(); CP_WAIT(0);
}

__device__ __forceinline__ void attn_block(
    AttnState& st, const uint32_t qfh[4][4], const uint32_t qfl[4][4],
    uint32_t sbase, uint32_t offKH, int lane)
{
    const uint32_t dKL = 9216, dVH = 18432, dVL = 27648;
    uint32_t kb_h = sbase + offKH + (uint32_t)(lane & 7) * ARS + ((lane >> 3) & 1) * 16;
    float sc[8][4];
    #pragma unroll
    for (int ni = 0; ni < 8; ni++)
        #pragma unroll
        for (int t = 0; t < 4; t++) sc[ni][t] = 0.f;
    #pragma unroll
    for (int ni = 0; ni < 8; ni++) {
        uint32_t ba_h = kb_h + (uint32_t)(ni * 8) * ARS;
        #pragma unroll
        for (int ks = 0; ks < 4; ks++) {
            uint32_t bh0, bh1, bl0, bl1;
            LDSM2(bh0, bh1, ba_h + ks * 32);
            LDSM2(bl0, bl1, ba_h + dKL + ks * 32);
            mma16816(sc[ni], qfh[ks], bh0, bh1);
            mma16816(sc[ni], qfh[ks], bl0, bl1);
            mma16816(sc[ni], qfl[ks], bh0, bh1);
        }
    }
    #pragma unroll
    for (int ni = 0; ni < 8; ni++) {
        sc[ni][0] *= 0.125f; sc[ni][1] *= 0.125f;
        sc[ni][2] *= 0.125f; sc[ni][3] *= 0.125f;
    }
    float bm0 = -1e30f, bm1 = -1e30f;
    #pragma unroll
    for (int ni = 0; ni < 8; ni++) {
        bm0 = fmaxf(bm0, fmaxf(sc[ni][0], sc[ni][1]));
        bm1 = fmaxf(bm1, fmaxf(sc[ni][2], sc[ni][3]));
    }
    bm0 = fmaxf(bm0, __shfl_xor_sync(0xffffffffu, bm0, 1));
    bm0 = fmaxf(bm0, __shfl_xor_sync(0xffffffffu, bm0, 2));
    bm1 = fmaxf(bm1, __shfl_xor_sync(0xffffffffu, bm1, 1));
    bm1 = fmaxf(bm1, __shfl_xor_sync(0xffffffffu, bm1, 2));
    float mn0 = fmaxf(st.m0, bm0), mn1 = fmaxf(st.m1, bm1);
    float corr0 = __expf(st.m0 - mn0), corr1 = __expf(st.m1 - mn1);
    st.m0 = mn0; st.m1 = mn1;
    #pragma unroll
    for (int nd = 0; nd < 8; nd++) {
        st.co[nd][0] *= corr0; st.co[nd][1] *= corr0;
        st.co[nd][2] *= corr1; st.co[nd][3] *= corr1;
    }
    float ls0 = 0.f, ls1 = 0.f;
    #pragma unroll
    for (int ni = 0; ni < 8; ni++) {
        sc[ni][0] = __expf(sc[ni][0] - mn0);
        sc[ni][1] = __expf(sc[ni][1] - mn0);
        sc[ni][2] = __expf(sc[ni][2] - mn1);
        sc[ni][3] = __expf(sc[ni][3] - mn1);
        ls0 += sc[ni][0] + sc[ni][1];
        ls1 += sc[ni][2] + sc[ni][3];
    }
    ls0 += __shfl_xor_sync(0xffffffffu, ls0, 1);
    ls0 += __shfl_xor_sync(0xffffffffu, ls0, 2);
    ls1 += __shfl_xor_sync(0xffffffffu, ls1, 1);
    ls1 += __shfl_xor_sync(0xffffffffu, ls1, 2);
    st.l0 = st.l0 * corr0 + ls0;
    st.l1 = st.l1 * corr1 + ls1;

    uint32_t pah[4][4], pal[4][4];
    #pragma unroll
    for (int ksp = 0; ksp < 4; ksp++) {
        split2h(sc[2*ksp][0],   sc[2*ksp][1],   pah[ksp][0], pal[ksp][0]);
        split2h(sc[2*ksp][2],   sc[2*ksp][3],   pah[ksp][1], pal[ksp][1]);
        split2h(sc[2*ksp+1][0], sc[2*ksp+1][1], pah[ksp][2], pal[ksp][2]);
        split2h(sc[2*ksp+1][2], sc[2*ksp+1][3], pah[ksp][3], pal[ksp][3]);
    }
    #pragma unroll
    for (int nd = 0; nd < 8; nd++) {
        #pragma unroll
        for (int ksp = 0; ksp < 4; ksp++) {
            uint32_t va = sbase + offKH + dVH
                        + (uint32_t)(ksp * 16 + (lane & 15)) * ARS + nd * 16;
            uint32_t vh0, vh1, vl0, vl1;
            LDSM2T(vh0, vh1, va);
            LDSM2T(vl0, vl1, va + (dVL - dVH));
            mma16816(st.co[nd], pah[ksp], vh0, vh1);
            mma16816(st.co[nd], pah[ksp], vl0, vl1);
            mma16816(st.co[nd], pal[ksp], vh0, vh1);
        }
    }
}

__device__ __forceinline__ void load_q_frags(
    uint32_t sbase, int warp_q, int lane, uint32_t qfh[4][4], uint32_t qfl[4][4])
{
    uint32_t qa_h = sbase + A_QH + (uint32_t)(warp_q * 16 + (lane & 15)) * ARS + (lane >> 4) * 16;
    uint32_t qa_l = qa_h + (A_QL - A_QH);
    #pragma unroll
    for (int ks = 0; ks < 4; ks++) {
        LDSM4(qfh[ks], qa_h + ks * 32);
        LDSM4(qfl[ks], qa_l + ks * 32);
    }
}

__device__ __forceinline__ void stage_q(
    const __half* __restrict__ qkvh, const __half* __restrict__ qkvl,
    uint32_t sbase, int b, int qb, int h, int srow, int shalf)
{
    size_t off = ((size_t)(b * SEQ + qb * BLKS + srow)) * QKVD + h * DHd + shalf * 32;
    uint32_t dh = sbase + A_QH + (uint32_t)srow * ARS + shalf * 64;
    uint32_t dl = sbase + A_QL + (uint32_t)srow * ARS + shalf * 64;
    CPA16(dh,      qkvh + off);      CPA16(dh + 16, qkvh + off + 8);
    CPA16(dh + 32, qkvh + off + 16); CPA16(dh + 48, qkvh + off + 24);
    CPA16(dl,      qkvl + off);      CPA16(dl + 16, qkvl + off + 8);
    CPA16(dl + 32, qkvl + off + 16); CPA16(dl + 48, qkvl + off + 24);
    CP_COMMIT(); CP_WAIT(0);
}

// ---------------- sparse attention ----------------
__global__ void __launch_bounds__(128) attn_sparse_kernel(
    const __half* __restrict__ qkvh, const __half* __restrict__ qkvl,
    const int* __restrict__ rb, __half* __restrict__ ch_g)
{
    extern __shared__ char sb[];
    uint32_t sbase = s2u(sb);
    int b = blockIdx.z, h = blockIdx.y, qb = blockIdx.x + 1;
    int tid = threadIdx.x, lane = tid & 31, w = tid >> 5;
    int srow = tid >> 1, shalf = tid & 1;

    stage_q(qkvh, qkvl, sbase, b, qb, h, srow, shalf);
    __syncthreads();

    uint32_t qfh[4][4], qfl[4][4];
    load_q_frags(sbase, w, lane, qfh, qfl);

    AttnState st;
    st.m0 = st.m1 = -1e30f; st.l0 = st.l1 = 0.f;
    #pragma unroll
    for (int nd = 0; nd < 8; nd++)
        #pragma unroll
        for (int t = 0; t < 4; t++) st.co[nd][t] = 0.f;

    int blist[8];
    blist[0] = 0; blist[1] = qb - 1; blist[2] = qb; blist[3] = qb + 1;
    blist[4] = NB - 1;
    const int* rp = rb + (h * NB + qb) * RR;
    blist[5] = rp[0]; blist[6] = rp[1]; blist[7] = rp[2];

    uint32_t dk  = sbase + A_KH + (uint32_t)srow * ARS + shalf * 64;
    uint32_t dkl = dk + 9216, dv = dk + 18432, dvl = dk + 27648;

    for (int jb = 0; jb < 8; jb++) {
        int kb = blist[jb];
        size_t kbase = ((size_t)(b * SEQ + kb * BLKS + srow)) * QKVD + Dm + h * DHd + shalf * 32;
        __syncthreads();
        stage_kv(qkvh, qkvl, kbase, dk, dkl, dv, dvl);
        __syncthreads();
        attn_block(st, qfh, qfl, sbase, A_KH, lane);
    }

    float inv0 = 1.f / st.l0, inv1 = 1.f / st.l1;
    int g = lane >> 2, t4 = lane & 3;
    size_t rbase = ((size_t)(b * SEQ + qb * BLKS + w * 16 + g)) * Dm + h * DHd;
    #pragma unroll
    for (int nd = 0; nd < 8; nd++) {
        int col = nd * 8 + 2 * t4;
        *(uint32_t*)(ch_g + rbase + col) =
            pack2h(st.co[nd][0] * inv0, st.co[nd][1] * inv0);
        *(uint32_t*)(ch_g + rbase + 8 * Dm + col) =
            pack2h(st.co[nd][2] * inv1, st.co[nd][3] * inv1);
    }
}

// ---------------- dense attention (query blocks 0, NB-1) ----------------
__global__ void __launch_bounds__(256) attn_dense_kernel(
    const __half* __restrict__ qkvh, const __half* __restrict__ qkvl,
    __half* __restrict__ ch_g)
{
    extern __shared__ char sb[];
    uint32_t sbase = s2u(sb);
    int b = blockIdx.z, h = blockIdx.y;
    int qb = (blockIdx.x == 0) ? 0 : NB - 1;
    int tid = threadIdx.x, lane = tid & 31;
    int grp = tid >> 7, ltid = tid & 127, w = ltid >> 5;
    int srow = ltid >> 1, shalf = ltid & 1;

    if (grp == 0) stage_q(qkvh, qkvl, sbase, b, qb, h, srow, shalf);
    __syncthreads();

    uint32_t qfh[4][4], qfl[4][4];
    load_q_frags(sbase, w, lane, qfh, qfl);

    AttnState st;
    st.m0 = st.m1 = -1e30f; st.l0 = st.l1 = 0.f;
    #pragma unroll
    for (int nd = 0; nd < 8; nd++)
        #pragma unroll
        for (int t = 0; t < 4; t++) st.co[nd][t] = 0.f;

    uint32_t gbase = D_G0 + grp * D_GRP;
    uint32_t dk  = sbase + gbase + (uint32_t)srow * ARS + shalf * 64;
    uint32_t dkl = dk + 9216, dv = dk + 18432, dvl = dk + 27648;

    for (int jb = 0; jb < 32; jb++) {
        int kb = grp * 32 + jb;
        size_t kbase = ((size_t)(b * SEQ + kb * BLKS + srow)) * QKVD + Dm + h * DHd + shalf * 32;
        __syncthreads();
        stage_kv(qkvh, qkvl, kbase, dk, dkl, dv, dvl);
        __syncthreads();
        attn_block(st, qfh, qfl, sbase, gbase, lane);
    }

    __syncthreads();
    float* mg = (float*)(sb + D_MRG);
    int slot = (w * 32 + lane) * 36;
    if (grp == 1) {
        #pragma unroll
        for (int nd = 0; nd < 8; nd++)
            #pragma unroll
            for (int t = 0; t < 4; t++) mg[slot + nd * 4 + t] = st.co[nd][t];
        mg[slot + 32] = st.m0; mg[slot + 33] = st.m1;
        mg[slot + 34] = st.l0; mg[slot + 35] = st.l1;
    }
    __syncthreads();
    if (grp == 0) {
        float mB0 = mg[slot + 32], mB1 = mg[slot + 33];
        float lB0 = mg[slot + 34], lB1 = mg[slot + 35];
        float M0 = fmaxf(st.m0, mB0), M1 = fmaxf(st.m1, mB1);
        float cA0 = __expf(st.m0 - M0), cB0 = __expf(mB0 - M0);
        float cA1 = __expf(st.m1 - M1), cB1 = __expf(mB1 - M1);
        float L0 = st.l0 * cA0 + lB0 * cB0;
        float L1 = st.l1 * cA1 + lB1 * cB1;
        float inv0 = 1.f / L0, inv1 = 1.f / L1;
        int g = lane >> 2, t4 = lane & 3;
        size_t rbase = ((size_t)(b * SEQ + qb * BLKS + w * 16 + g)) * Dm + h * DHd;
        #pragma unroll
        for (int nd = 0; nd < 8; nd++) {
            float r0 = (st.co[nd][0] * cA0 + mg[slot + nd * 4 + 0] * cB0) * inv0;
            float r1 = (st.co[nd][1] * cA0 + mg[slot + nd * 4 + 1] * cB0) * inv0;
            float r2 = (st.co[nd][2] * cA1 + mg[slot + nd * 4 + 2] * cB1) * inv1;
            float r3 = (st.co[nd][3] * cA1 + mg[slot + nd * 4 + 3] * cB1) * inv1;
            int col = nd * 8 + 2 * t4;
            *(uint32_t*)(ch_g + rbase + col)          = pack2h(r0, r1);
            *(uint32_t*)(ch_g + rbase + 8 * Dm + col) = pack2h(r2, r3);
        }
    }
}

// ---------------- mean pool + linear head ----------------
__global__ void __launch_bounds__(256) pool1_kernel(
    const float* __restrict__ x, const float* __restrict__ w, float* __restrict__ part)
{
    int b = blockIdx.y, sl = blockIdx.x;
    const float* xb = x + ((size_t)b * SEQ + sl * 128) * Dm;
    __shared__ float ws[Dm];
    for (int i = threadIdx.x; i < Dm; i += 256) ws[i] = w[i];
    __syncthreads();
    float acc = 0.f;
    for (int r = 0; r < 128; r++) {
        const float* xr = xb + (size_t)r * Dm;
        for (int i = threadIdx.x; i < Dm; i += 256) acc += xr[i] * ws[i];
    }
    float t = blk_sum256(acc);
    if (threadIdx.x == 0) part[b * 32 + sl] = t;
}
__global__ void pool2_kernel(const float* __restrict__ part,
                             const float* __restrict__ fb, float* __restrict__ out)
{
    int b = threadIdx.x;
    if (b < BB) {
        float s = 0.f;
        for (int i = 0; i < 32; i++) s += part[b * 32 + i];
        out[b] = s * (1.f / (float)SEQ) + fb[0];
    }
}

// ---------------- driver ----------------
extern "C" void kernel_launch(void* const* d_in, const int* in_sizes, int n_in,
                              void* d_out, int out_size)
{
    const int*   ids     = (const int*)  d_in[0];
    const int*   rb      = (const int*)  d_in[1];
    const float* emb_tok = (const float*)d_in[2];
    const float* emb_pos = (const float*)d_in[3];
    const float* lng     = (const float*)d_in[4];
    const float* lnb     = (const float*)d_in[5];
    const float* Wq = (const float*)d_in[6];  const float* bq = (const float*)d_in[7];
    const float* Wk = (const float*)d_in[8];  const float* bk = (const float*)d_in[9];
    const float* Wv = (const float*)d_in[10]; const float* bv = (const float*)d_in[11];
    const float* Wo = (const float*)d_in[12]; const float* bo = (const float*)d_in[13];
    const float* ln1g = (const float*)d_in[14]; const float* ln1b = (const float*)d_in[15];
    const float* W1 = (const float*)d_in[16]; const float* b1 = (const float*)d_in[17];
    const float* W2 = (const float*)d_in[18]; const float* b2 = (const float*)d_in[19];
    const float* ln2g = (const float*)d_in[20]; const float* ln2b = (const float*)d_in[21];
    const float* fcw = (const float*)d_in[22]; const float* fcb = (const float*)d_in[23];

    float *x, *tmp, *part, *bqkv;
    __half *xh, *xl, *qkvh, *qkvl, *ch, *fh, *wh;
    cudaGetSymbolAddress((void**)&x,   g_x);
    cudaGetSymbolAddress((void**)&tmp, g_tmp);
    cudaGetSymbolAddress((void**)&xh,  g_xh);
    cudaGetSymbolAddress((void**)&xl,  g_xl);
    cudaGetSymbolAddress((void**)&qkvh, g_qkvh);
    cudaGetSymbolAddress((void**)&qkvl, g_qkvl);
    cudaGetSymbolAddress((void**)&ch,  g_ch);
    cudaGetSymbolAddress((void**)&fh,  g_fh);
    cudaGetSymbolAddress((void**)&wh,  g_wh);
    cudaGetSymbolAddress((void**)&bqkv, g_bqkv);
    cudaGetSymbolAddress((void**)&part, g_part);

    const int SM_A2 = 2 * 3 * TILE_B;   // 61440 (2-term A)
    const int SM_A1 = 2 * 2 * TILE_B;   // 40960 (1-term A)
    cudaFuncSetAttribute((const void*)gemm_mma<0,0,1,1,24>,
                         cudaFuncAttributeMaxDynamicSharedMemorySize, SM_A2);
    cudaFuncSetAttribute((const void*)gemm_mma<0,1,0,0,24>,
                         cudaFuncAttributeMaxDynamicSharedMemorySize, SM_A1);
    cudaFuncSetAttribute((const void*)gemm_mma<1,0,2,1,24>,
                         cudaFuncAttributeMaxDynamicSharedMemorySize, SM_A2);
    cudaFuncSetAttribute((const void*)gemm_mma<0,1,0,0,96>,
                         cudaFuncAttributeMaxDynamicSharedMemorySize, SM_A1);
    cudaFuncSetAttribute((const void*)attn_sparse_kernel,
                         cudaFuncAttributeMaxDynamicSharedMemorySize, A_SMEM);
    cudaFuncSetAttribute((const void*)attn_dense_kernel,
                         cudaFuncAttributeMaxDynamicSharedMemorySize, D_SMEM);

    dim3 gQKV(QKVD / 128, NTOK / 128);
    dim3 gO(Dm / 128, NTOK / 128);
    dim3 gF(FF / 128, NTOK / 128);
    dim3 gAttS(NB - 2, Hh, BB);
    dim3 gAttD(2, Hh, BB);
    dim3 gWS(Dm / 32, Dm / 32);

    wsplit3_kernel<<<dim3(Dm / 32, Dm / 32, 3), 256>>>(
        Wq, Wk, Wv, wh, bq, bk, bv, bqkv);
    wsplit_kernel<<<gWS, 256>>>(Wo, wh + 3 * (size_t)WSZ, Dm, Dm);
    wsplit_kernel<<<dim3(FF / 32, Dm / 32), 256>>>(W1, wh + 4 * (size_t)WSZ, Dm, FF);
    wsplit_kernel<<<dim3(Dm / 32, FF / 32), 256>>>(W2, wh + 4 * (size_t)WSZ + W1SZ, FF, Dm);
    embed_ln_kernel<<<NTOK, 256>>>(ids, emb_tok, emb_pos, lng, lnb, x, xh, xl);

    for (int l = 0; l < 2; l++) {
        size_t o = (size_t)l * OFFL;
        gemm_mma<0,0,1,1,24><<<gQKV, 256, SM_A2>>>(xh, xl, wh + o, bqkv + l * QKVD,
            nullptr, qkvh, qkvl, NTOK, QKVD);
        attn_sparse_kernel<<<gAttS, 128, A_SMEM>>>(qkvh, qkvl, rb, ch);
        attn_dense_kernel<<<gAttD, 256, D_SMEM>>>(qkvh, qkvl, ch);
        gemm_mma<0,1,0,0,24><<<gO, 256, SM_A1>>>(ch, nullptr, wh + o + 3 * WSZ,
            bo + l * Dm, tmp, nullptr, nullptr, NTOK, Dm);
        add_ln_kernel<<<NTOK, 256>>>(x, tmp, ln1g + l * Dm, ln1b + l * Dm, xh, xl);
        gemm_mma<1,0,2,1,24><<<gF, 256, SM_A2>>>(xh, xl, wh + o + 4 * WSZ,
            b1 + l * FF, nullptr, fh, nullptr, NTOK, FF);
        gemm_mma<0,1,0,0,96><<<gO, 256, SM_A1>>>(fh, nullptr, wh + o + 4 * WSZ + W1SZ,
            b2 + l * Dm, tmp, nullptr, nullptr, NTOK, Dm);
        add_ln_kernel<<<NTOK, 256>>>(x, tmp, ln2g + l * Dm, ln2b + l * Dm, xh, xl);

        if (l == 0) {
            size_t o1 = OFFL;
            wsplit3_kernel<<<dim3(Dm / 32, Dm / 32, 3), 256>>>(
                Wq + WSZ, Wk + WSZ, Wv + WSZ, wh + o1,
                bq + Dm, bk + Dm, bv + Dm, bqkv + QKVD);
            wsplit_kernel<<<gWS, 256>>>(Wo + WSZ, wh + o1 + 3 * (size_t)WSZ, Dm, Dm);
            wsplit_kernel<<<dim3(FF / 32, Dm / 32), 256>>>(W1 + W1SZ, wh + o1 + 4 * (size_t)WSZ, Dm, FF);
            wsplit_kernel<<<dim3(Dm / 32, FF / 32), 256>>>(W2 + W1SZ, wh + o1 + 4 * (size_t)WSZ + W1SZ, FF, Dm);
        }
    }

    pool1_kernel<<<dim3(32, BB), 256>>>(x, fcw, part);
    pool2_kernel<<<1, 32>>>(part, fcb, (float*)d_out);
}

// round 10
// speedup vs baseline: 1.9324x; 1.1042x over previous
#include <cuda_runtime.h>
#include <cuda_fp16.h>
#include <math.h>
#include <stdint.h>

// ---------------- problem constants ----------------
#define Dm   768
#define Hh   12
#define DHd  64
#define BLKS 64
#define NB   64
#define SEQ  4096
#define BB   2
#define NTOK (BB*SEQ)
#define RR   3
#define FF   3072
#define QKVD 2304

#define WSZ   589824
#define W1SZ  2359296
#define OFFL  (4*WSZ + 2*W1SZ)

// ---------------- scratch (device globals) ----------------
__device__ float g_x  [NTOK*Dm];
__device__ float g_tmp[NTOK*Dm];
__device__ __half g_xh [NTOK*Dm];
__device__ __half g_xl [NTOK*Dm];
__device__ __half g_qkvh[NTOK*QKVD];
__device__ __half g_qkvl[NTOK*QKVD];
__device__ __half g_ch [NTOK*Dm];
__device__ __half g_fh [NTOK*FF];
__device__ __half g_wh [2*OFFL];
__device__ float g_bqkv[2*QKVD];
__device__ float g_part[64];

// ---------------- helpers ----------------
__device__ __forceinline__ float gelu_tanh(float x) {
    float x3 = x * x * x;
    return 0.5f * x * (1.f + tanhf(0.7978845608028654f * (x + 0.044715f * x3)));
}

__device__ __forceinline__ float blk_sum256(float v) {
    __shared__ float red[32];
    int lane = threadIdx.x & 31, wid = threadIdx.x >> 5;
    #pragma unroll
    for (int o = 16; o > 0; o >>= 1) v += __shfl_xor_sync(0xffffffffu, v, o);
    if (lane == 0) red[wid] = v;
    __syncthreads();
    if (wid == 0) {
        v = (lane < 8) ? red[lane] : 0.f;
        #pragma unroll
        for (int o = 4; o > 0; o >>= 1) v += __shfl_xor_sync(0xffffffffu, v, o);
        if (lane == 0) red[0] = v;
    }
    __syncthreads();
    float r = red[0];
    __syncthreads();
    return r;
}

__device__ __forceinline__ uint32_t s2u(const void* p) {
    uint32_t a;
    asm("{ .reg .u64 t; cvta.to.shared.u64 t, %1; cvt.u32.u64 %0, t; }" : "=r"(a) : "l"(p));
    return a;
}

#define LDSM4(r, a) \
    asm volatile("ldmatrix.sync.aligned.m8n8.x4.shared.b16 {%0,%1,%2,%3}, [%4];" \
        : "=r"((r)[0]), "=r"((r)[1]), "=r"((r)[2]), "=r"((r)[3]) : "r"(a))
#define LDSM2(r0, r1, a) \
    asm volatile("ldmatrix.sync.aligned.m8n8.x2.shared.b16 {%0,%1}, [%2];" \
        : "=r"(r0), "=r"(r1) : "r"(a))
#define LDSM2T(r0, r1, a) \
    asm volatile("ldmatrix.sync.aligned.m8n8.x2.trans.shared.b16 {%0,%1}, [%2];" \
        : "=r"(r0), "=r"(r1) : "r"(a))

#define CPA16(dst, src) \
    asm volatile("cp.async.cg.shared.global [%0], [%1], 16;" :: "r"(dst), "l"(src))
#define CP_COMMIT() asm volatile("cp.async.commit_group;" ::: "memory")
#define CP_WAIT(n)  asm volatile("cp.async.wait_group %0;" :: "n"(n) : "memory")

__device__ __forceinline__ void mma16816(float* c, const uint32_t* a,
                                         uint32_t b0, uint32_t b1) {
    asm volatile(
        "mma.sync.aligned.m16n8k16.row.col.f32.f16.f16.f32 "
        "{%0,%1,%2,%3}, {%4,%5,%6,%7}, {%8,%9}, {%0,%1,%2,%3};"
        : "+f"(c[0]), "+f"(c[1]), "+f"(c[2]), "+f"(c[3])
        : "r"(a[0]), "r"(a[1]), "r"(a[2]), "r"(a[3]), "r"(b0), "r"(b1));
}

__device__ __forceinline__ void split2h(float a, float b, uint32_t& hi, uint32_t& lo) {
    __half ha = __float2half_rn(a);
    __half hb = __float2half_rn(b);
    __half la = __float2half_rn(a - __half2float(ha));
    __half lb = __float2half_rn(b - __half2float(hb));
    hi = (uint32_t)__half_as_ushort(ha) | ((uint32_t)__half_as_ushort(hb) << 16);
    lo = (uint32_t)__half_as_ushort(la) | ((uint32_t)__half_as_ushort(lb) << 16);
}

__device__ __forceinline__ uint32_t pack2h(float a, float b) {
    __half2 h = __floats2half2_rn(a, b);
    return *(uint32_t*)&h;
}

// ---------------- weight transpose + fp16 convert ----------------
__global__ void __launch_bounds__(256) wsplit_kernel(
    const float* __restrict__ W, __half* __restrict__ hi, int K, int N)
{
    __shared__ float t[32][33];
    int n0 = blockIdx.x * 32, k0 = blockIdx.y * 32;
    int tx = threadIdx.x & 31, ty = threadIdx.x >> 5;
    #pragma unroll
    for (int j = 0; j < 4; j++)
        t[ty + j * 8][tx] = W[(size_t)(k0 + ty + j * 8) * N + n0 + tx];
    __syncthreads();
    #pragma unroll
    for (int j = 0; j < 4; j++) {
        int n = n0 + ty + j * 8, k = k0 + tx;
        hi[(size_t)n * K + k] = __float2half_rn(t[tx][ty + j * 8]);
    }
}

__global__ void __launch_bounds__(256) wsplit3_kernel(
    const float* __restrict__ Wa, const float* __restrict__ Wb,
    const float* __restrict__ Wc, __half* __restrict__ hi,
    const float* __restrict__ ba, const float* __restrict__ bb,
    const float* __restrict__ bc, float* __restrict__ bqkv)
{
    __shared__ float t[32][33];
    int z = blockIdx.z;
    const float* W = (z == 0) ? Wa : (z == 1) ? Wb : Wc;
    __half* hz = hi + (size_t)z * WSZ;
    int n0 = blockIdx.x * 32, k0 = blockIdx.y * 32;
    int tx = threadIdx.x & 31, ty = threadIdx.x >> 5;
    if (blockIdx.x == 0 && blockIdx.y == 0) {
        const float* bz = (z == 0) ? ba : (z == 1) ? bb : bc;
        for (int i = threadIdx.x; i < Dm; i += 256) bqkv[z * Dm + i] = bz[i];
    }
    #pragma unroll
    for (int j = 0; j < 4; j++)
        t[ty + j * 8][tx] = W[(size_t)(k0 + ty + j * 8) * Dm + n0 + tx];
    __syncthreads();
    #pragma unroll
    for (int j = 0; j < 4; j++) {
        int n = n0 + ty + j * 8, k = k0 + tx;
        hz[(size_t)n * Dm + k] = __float2half_rn(t[tx][ty + j * 8]);
    }
}

// ---------------- cp.async warp-MMA GEMM (BK=64) ----------------
// AT2=1: A = hi+lo fp16 (2 MMA terms); AT2=0: A = hi only (1 term).
// WSPL: 0=none, 1=write Chi+Clo (split), 2=write Chi only (fp16 rn).
#define RS64  144
#define TL64  (128*RS64)        // 18432

template<int GELU, int WF32, int WSPL, int AT2, int KC>
__global__ void __launch_bounds__(256, 2) gemm_mma(
    const __half* __restrict__ Ahi, const __half* __restrict__ Alo,
    const __half* __restrict__ Bh,
    const float* __restrict__ bias, float* __restrict__ C,
    __half* __restrict__ Chi, __half* __restrict__ Clo,
    int M, int N)
{
    const int K = KC * 64;
    const int STG  = (AT2 ? 3 : 2) * TL64;
    const int BOFF = (AT2 ? 2 : 1) * TL64;
    extern __shared__ char sm[];
    uint32_t sbase = s2u(sm);
    int tid = threadIdx.x, lane = tid & 31, wid = tid >> 5;
    int m0 = blockIdx.y * 128, n0 = blockIdx.x * 128;
    int wm = (wid & 3) * 32, wn = (wid >> 2) * 64;

    int lr = tid & 127, lh = tid >> 7;          // row, 64-byte half
    const __half* ah_p = Ahi + (size_t)(m0 + lr) * K + lh * 32;
    const __half* al_p = AT2 ? (Alo + (size_t)(m0 + lr) * K + lh * 32) : nullptr;
    const __half* bh_p = Bh  + (size_t)(n0 + lr) * K + lh * 32;
    uint32_t woff = (uint32_t)lr * RS64 + (uint32_t)lh * 64;

    float acc[2][8][4];
    #pragma unroll
    for (int i = 0; i < 2; i++)
        #pragma unroll
        for (int j = 0; j < 8; j++)
            #pragma unroll
            for (int t = 0; t < 4; t++) acc[i][j][t] = 0.f;

    {
        uint32_t d = sbase + woff;
        #pragma unroll
        for (int q = 0; q < 4; q++) CPA16(d + q * 16, ah_p + q * 8);
        if (AT2) {
            #pragma unroll
            for (int q = 0; q < 4; q++) CPA16(d + TL64 + q * 16, al_p + q * 8);
        }
        #pragma unroll
        for (int q = 0; q < 4; q++) CPA16(d + BOFF + q * 16, bh_p + q * 8);
        CP_COMMIT();
    }

    int r16 = lane & 15, c16 = lane >> 4;
    int r8  = lane & 7,  c8  = (lane >> 3) & 1;

    for (int c = 0; c < KC; c++) {
        if (c + 1 < KC) {
            uint32_t d = sbase + ((c + 1) & 1) * STG + woff;
            int off = (c + 1) * 64;
            #pragma unroll
            for (int q = 0; q < 4; q++) CPA16(d + q * 16, ah_p + off + q * 8);
            if (AT2) {
                #pragma unroll
                for (int q = 0; q < 4; q++) CPA16(d + TL64 + q * 16, al_p + off + q * 8);
            }
            #pragma unroll
            for (int q = 0; q < 4; q++) CPA16(d + BOFF + q * 16, bh_p + off + q * 8);
            CP_COMMIT();
            CP_WAIT(1);
        } else {
            CP_WAIT(0);
        }
        __syncthreads();
        {
            uint32_t base = sbase + (c & 1) * STG;
            #pragma unroll
            for (int ks = 0; ks < 4; ks++) {
                uint32_t ah[2][4], al[2][4];
                #pragma unroll
                for (int mi = 0; mi < 2; mi++) {
                    uint32_t rel = (uint32_t)(wm + mi * 16 + r16) * RS64
                                 + ks * 32 + c16 * 16;
                    LDSM4(ah[mi], base + rel);
                    if (AT2) LDSM4(al[mi], base + TL64 + rel);
                }
                #pragma unroll
                for (int ni = 0; ni < 8; ni++) {
                    uint32_t rel = (uint32_t)(wn + ni * 8 + r8) * RS64
                                 + ks * 32 + c8 * 16;
                    uint32_t bh0, bh1;
                    LDSM2(bh0, bh1, base + BOFF + rel);
                    #pragma unroll
                    for (int mi = 0; mi < 2; mi++) {
                        mma16816(acc[mi][ni], ah[mi], bh0, bh1);
                        if (AT2) mma16816(acc[mi][ni], al[mi], bh0, bh1);
                    }
                }
            }
        }
        __syncthreads();
    }

    int g = lane >> 2, t4 = lane & 3;
    #pragma unroll
    for (int mi = 0; mi < 2; mi++) {
        int row0 = m0 + wm + mi * 16 + g;
        #pragma unroll
        for (int ni = 0; ni < 8; ni++) {
            int col = n0 + wn + ni * 8 + 2 * t4;
            float2 bi = *(const float2*)(bias + col);
            float2 o0, o1;
            o0.x = acc[mi][ni][0] + bi.x;
            o0.y = acc[mi][ni][1] + bi.y;
            o1.x = acc[mi][ni][2] + bi.x;
            o1.y = acc[mi][ni][3] + bi.y;
            if (GELU) {
                o0.x = gelu_tanh(o0.x); o0.y = gelu_tanh(o0.y);
                o1.x = gelu_tanh(o1.x); o1.y = gelu_tanh(o1.y);
            }
            size_t i0 = (size_t)row0 * N + col;
            size_t i1 = (size_t)(row0 + 8) * N + col;
            if (WF32) {
                *(float2*)(C + i0) = o0;
                *(float2*)(C + i1) = o1;
            }
            if (WSPL == 1) {
                uint32_t h0, l0, h1, l1;
                split2h(o0.x, o0.y, h0, l0);
                split2h(o1.x, o1.y, h1, l1);
                *(uint32_t*)(Chi + i0) = h0;
                *(uint32_t*)(Clo + i0) = l0;
                *(uint32_t*)(Chi + i1) = h1;
                *(uint32_t*)(Clo + i1) = l1;
            }
            if (WSPL == 2) {
                *(uint32_t*)(Chi + i0) = pack2h(o0.x, o0.y);
                *(uint32_t*)(Chi + i1) = pack2h(o1.x, o1.y);
            }
        }
    }
}

// ---------------- embedding + LN ----------------
__global__ void __launch_bounds__(256) embed_ln_kernel(
    const int* __restrict__ ids, const float* __restrict__ tok,
    const float* __restrict__ pos, const float* __restrict__ g,
    const float* __restrict__ b, float* __restrict__ x,
    __half* __restrict__ xh, __half* __restrict__ xl)
{
    int t = blockIdx.x, s = t & (SEQ - 1), id = ids[t];
    float val[3];
    #pragma unroll
    for (int j = 0; j < 3; j++) {
        int i = threadIdx.x + j * 256;
        val[j] = tok[(size_t)id * Dm + i] + pos[(size_t)s * Dm + i];
    }
    float mean = blk_sum256(val[0] + val[1] + val[2]) * (1.f / 768.f);
    float sq = 0.f;
    #pragma unroll
    for (int j = 0; j < 3; j++) { float d = val[j] - mean; sq += d * d; }
    float rstd = rsqrtf(blk_sum256(sq) * (1.f / 768.f) + 1e-12f);
    #pragma unroll
    for (int j = 0; j < 3; j++) {
        int i = threadIdx.x + j * 256;
        float o = (val[j] - mean) * rstd * g[i] + b[i];
        size_t idx = (size_t)t * Dm + i;
        x[idx] = o;
        __half h = __float2half_rn(o);
        xh[idx] = h;
        xl[idx] = __float2half_rn(o - __half2float(h));
    }
}

// ---------------- residual add + LN ----------------
__global__ void __launch_bounds__(256) add_ln_kernel(
    float* __restrict__ x, const float* __restrict__ y,
    const float* __restrict__ g, const float* __restrict__ b,
    __half* __restrict__ xh, __half* __restrict__ xl)
{
    size_t t = blockIdx.x;
    float* xp = x + t * Dm;
    const float* yp = y + t * Dm;
    float val[3];
    #pragma unroll
    for (int j = 0; j < 3; j++) {
        int i = threadIdx.x + j * 256;
        val[j] = xp[i] + yp[i];
    }
    float mean = blk_sum256(val[0] + val[1] + val[2]) * (1.f / 768.f);
    float sq = 0.f;
    #pragma unroll
    for (int j = 0; j < 3; j++) { float d = val[j] - mean; sq += d * d; }
    float rstd = rsqrtf(blk_sum256(sq) * (1.f / 768.f) + 1e-12f);
    #pragma unroll
    for (int j = 0; j < 3; j++) {
        int i = threadIdx.x + j * 256;
        float o = (val[j] - mean) * rstd * g[i] + b[i];
        xp[i] = o;
        __half h = __float2half_rn(o);
        xh[t * Dm + i] = h;
        xl[t * Dm + i] = __float2half_rn(o - __half2float(h));
    }
}

// ================= attention (fp16, 3-term compensated) =================
#define ARS 144
#define A_QH 0
#define A_QL 9216
#define A_KH 18432
#define A_SMEM 55296
#define D_GRP 36864
#define D_G0  18432
#define D_SMEM (18432 + 2*D_GRP)
#define D_MRG 18432

struct AttnState {
    float m0, m1, l0, l1;
    float co[8][4];
};

__device__ __forceinline__ void stage_kv(
    const __half* __restrict__ qkvh, const __half* __restrict__ qkvl,
    size_t kbase, uint32_t dk, uint32_t dkl, uint32_t dv, uint32_t dvl)
{
    size_t vbase = kbase + Dm;
    CPA16(dk,      qkvh + kbase);      CPA16(dk + 16, qkvh + kbase + 8);
    CPA16(dk + 32, qkvh + kbase + 16); CPA16(dk + 48, qkvh + kbase + 24);
    CPA16(dkl,      qkvl + kbase);      CPA16(dkl + 16, qkvl + kbase + 8);
    CPA16(dkl + 32, qkvl + kbase + 16); CPA16(dkl + 48, qkvl + kbase + 24);
    CPA16(dv,      qkvh + vbase);      CPA16(dv + 16, qkvh + vbase + 8);
    CPA16(dv + 32, qkvh + vbase + 16); CPA16(dv + 48, qkvh + vbase + 24);
    CPA16(dvl,      qkvl + vbase);      CPA16(dvl + 16, qkvl + vbase + 8);
    CPA16(dvl + 32, qkvl + vbase + 16); CPA16(dvl + 48, qkvl + vbase + 24);
    CP_COMMIT(); CP_WAIT(0);
}

__device__ __forceinline__ void attn_block(
    AttnState& st, const uint32_t qfh[4][4], const uint32_t qfl[4][4],
    uint32_t sbase, uint32_t offKH, int lane)
{
    const uint32_t dKL = 9216, dVH = 18432, dVL = 27648;
    uint32_t kb_h = sbase + offKH + (uint32_t)(lane & 7) * ARS + ((lane >> 3) & 1) * 16;
    float sc[8][4];
    #pragma unroll
    for (int ni = 0; ni < 8; ni++)
        #pragma unroll
        for (int t = 0; t < 4; t++) sc[ni][t] = 0.f;
    #pragma unroll
    for (int ni = 0; ni < 8; ni++) {
        uint32_t ba_h = kb_h + (uint32_t)(ni * 8) * ARS;
        #pragma unroll
        for (int ks = 0; ks < 4; ks++) {
            uint32_t bh0, bh1, bl0, bl1;
            LDSM2(bh0, bh1, ba_h + ks * 32);
            LDSM2(bl0, bl1, ba_h + dKL + ks * 32);
            mma16816(sc[ni], qfh[ks], bh0, bh1);
            mma16816(sc[ni], qfh[ks], bl0, bl1);
            mma16816(sc[ni], qfl[ks], bh0, bh1);
        }
    }
    #pragma unroll
    for (int ni = 0; ni < 8; ni++) {
        sc[ni][0] *= 0.125f; sc[ni][1] *= 0.125f;
        sc[ni][2] *= 0.125f; sc[ni][3] *= 0.125f;
    }
    float bm0 = -1e30f, bm1 = -1e30f;
    #pragma unroll
    for (int ni = 0; ni < 8; ni++) {
        bm0 = fmaxf(bm0, fmaxf(sc[ni][0], sc[ni][1]));
        bm1 = fmaxf(bm1, fmaxf(sc[ni][2], sc[ni][3]));
    }
    bm0 = fmaxf(bm0, __shfl_xor_sync(0xffffffffu, bm0, 1));
    bm0 = fmaxf(bm0, __shfl_xor_sync(0xffffffffu, bm0, 2));
    bm1 = fmaxf(bm1, __shfl_xor_sync(0xffffffffu, bm1, 1));
    bm1 = fmaxf(bm1, __shfl_xor_sync(0xffffffffu, bm1, 2));
    float mn0 = fmaxf(st.m0, bm0), mn1 = fmaxf(st.m1, bm1);
    float corr0 = __expf(st.m0 - mn0), corr1 = __expf(st.m1 - mn1);
    st.m0 = mn0; st.m1 = mn1;
    #pragma unroll
    for (int nd = 0; nd < 8; nd++) {
        st.co[nd][0] *= corr0; st.co[nd][1] *= corr0;
        st.co[nd][2] *= corr1; st.co[nd][3] *= corr1;
    }
    float ls0 = 0.f, ls1 = 0.f;
    #pragma unroll
    for (int ni = 0; ni < 8; ni++) {
        sc[ni][0] = __expf(sc[ni][0] - mn0);
        sc[ni][1] = __expf(sc[ni][1] - mn0);
        sc[ni][2] = __expf(sc[ni][2] - mn1);
        sc[ni][3] = __expf(sc[ni][3] - mn1);
        ls0 += sc[ni][0] + sc[ni][1];
        ls1 += sc[ni][2] + sc[ni][3];
    }
    ls0 += __shfl_xor_sync(0xffffffffu, ls0, 1);
    ls0 += __shfl_xor_sync(0xffffffffu, ls0, 2);
    ls1 += __shfl_xor_sync(0xffffffffu, ls1, 1);
    ls1 += __shfl_xor_sync(0xffffffffu, ls1, 2);
    st.l0 = st.l0 * corr0 + ls0;
    st.l1 = st.l1 * corr1 + ls1;

    uint32_t pah[4][4], pal[4][4];
    #pragma unroll
    for (int ksp = 0; ksp < 4; ksp++) {
        split2h(sc[2*ksp][0],   sc[2*ksp][1],   pah[ksp][0], pal[ksp][0]);
        split2h(sc[2*ksp][2],   sc[2*ksp][3],   pah[ksp][1], pal[ksp][1]);
        split2h(sc[2*ksp+1][0], sc[2*ksp+1][1], pah[ksp][2], pal[ksp][2]);
        split2h(sc[2*ksp+1][2], sc[2*ksp+1][3], pah[ksp][3], pal[ksp][3]);
    }
    #pragma unroll
    for (int nd = 0; nd < 8; nd++) {
        #pragma unroll
        for (int ksp = 0; ksp < 4; ksp++) {
            uint32_t va = sbase + offKH + dVH
                        + (uint32_t)(ksp * 16 + (lane & 15)) * ARS + nd * 16;
            uint32_t vh0, vh1, vl0, vl1;
            LDSM2T(vh0, vh1, va);
            LDSM2T(vl0, vl1, va + (dVL - dVH));
            mma16816(st.co[nd], pah[ksp], vh0, vh1);
            mma16816(st.co[nd], pah[ksp], vl0, vl1);
            mma16816(st.co[nd], pal[ksp], vh0, vh1);
        }
    }
}

__device__ __forceinline__ void load_q_frags(
    uint32_t sbase, int warp_q, int lane, uint32_t qfh[4][4], uint32_t qfl[4][4])
{
    uint32_t qa_h = sbase + A_QH + (uint32_t)(warp_q * 16 + (lane & 15)) * ARS + (lane >> 4) * 16;
    uint32_t qa_l = qa_h + (A_QL - A_QH);
    #pragma unroll
    for (int ks = 0; ks < 4; ks++) {
        LDSM4(qfh[ks], qa_h + ks * 32);
        LDSM4(qfl[ks], qa_l + ks * 32);
    }
}

__device__ __forceinline__ void stage_q(
    const __half* __restrict__ qkvh, const __half* __restrict__ qkvl,
    uint32_t sbase, int b, int qb, int h, int srow, int shalf)
{
    size_t off = ((size_t)(b * SEQ + qb * BLKS + srow)) * QKVD + h * DHd + shalf * 32;
    uint32_t dh = sbase + A_QH + (uint32_t)srow * ARS + shalf * 64;
    uint32_t dl = sbase + A_QL + (uint32_t)srow * ARS + shalf * 64;
    CPA16(dh,      qkvh + off);      CPA16(dh + 16, qkvh + off + 8);
    CPA16(dh + 32, qkvh + off + 16); CPA16(dh + 48, qkvh + off + 24);
    CPA16(dl,      qkvl + off);      CPA16(dl + 16, qkvl + off + 8);
    CPA16(dl + 32, qkvl + off + 16); CPA16(dl + 48, qkvl + off + 24);
    CP_COMMIT(); CP_WAIT(0);
}

// ---------------- sparse attention ----------------
__global__ void __launch_bounds__(128) attn_sparse_kernel(
    const __half* __restrict__ qkvh, const __half* __restrict__ qkvl,
    const int* __restrict__ rb, __half* __restrict__ ch_g)
{
    extern __shared__ char sb[];
    uint32_t sbase = s2u(sb);
    int b = blockIdx.z, h = blockIdx.y, qb = blockIdx.x + 1;
    int tid = threadIdx.x, lane = tid & 31, w = tid >> 5;
    int srow = tid >> 1, shalf = tid & 1;

    stage_q(qkvh, qkvl, sbase, b, qb, h, srow, shalf);
    __syncthreads();

    uint32_t qfh[4][4], qfl[4][4];
    load_q_frags(sbase, w, lane, qfh, qfl);

    AttnState st;
    st.m0 = st.m1 = -1e30f; st.l0 = st.l1 = 0.f;
    #pragma unroll
    for (int nd = 0; nd < 8; nd++)
        #pragma unroll
        for (int t = 0; t < 4; t++) st.co[nd][t] = 0.f;

    int blist[8];
    blist[0] = 0; blist[1] = qb - 1; blist[2] = qb; blist[3] = qb + 1;
    blist[4] = NB - 1;
    const int* rp = rb + (h * NB + qb) * RR;
    blist[5] = rp[0]; blist[6] = rp[1]; blist[7] = rp[2];

    uint32_t dk  = sbase + A_KH + (uint32_t)srow * ARS + shalf * 64;
    uint32_t dkl = dk + 9216, dv = dk + 18432, dvl = dk + 27648;

    for (int jb = 0; jb < 8; jb++) {
        int kb = blist[jb];
        size_t kbase = ((size_t)(b * SEQ + kb * BLKS + srow)) * QKVD + Dm + h * DHd + shalf * 32;
        __syncthreads();
        stage_kv(qkvh, qkvl, kbase, dk, dkl, dv, dvl);
        __syncthreads();
        attn_block(st, qfh, qfl, sbase, A_KH, lane);
    }

    float inv0 = 1.f / st.l0, inv1 = 1.f / st.l1;
    int g = lane >> 2, t4 = lane & 3;
    size_t rbase = ((size_t)(b * SEQ + qb * BLKS + w * 16 + g)) * Dm + h * DHd;
    #pragma unroll
    for (int nd = 0; nd < 8; nd++) {
        int col = nd * 8 + 2 * t4;
        *(uint32_t*)(ch_g + rbase + col) =
            pack2h(st.co[nd][0] * inv0, st.co[nd][1] * inv0);
        *(uint32_t*)(ch_g + rbase + 8 * Dm + col) =
            pack2h(st.co[nd][2] * inv1, st.co[nd][3] * inv1);
    }
}

// ---------------- dense attention (query blocks 0, NB-1) ----------------
__global__ void __launch_bounds__(256) attn_dense_kernel(
    const __half* __restrict__ qkvh, const __half* __restrict__ qkvl,
    __half* __restrict__ ch_g)
{
    extern __shared__ char sb[];
    uint32_t sbase = s2u(sb);
    int b = blockIdx.z, h = blockIdx.y;
    int qb = (blockIdx.x == 0) ? 0 : NB - 1;
    int tid = threadIdx.x, lane = tid & 31;
    int grp = tid >> 7, ltid = tid & 127, w = ltid >> 5;
    int srow = ltid >> 1, shalf = ltid & 1;

    if (grp == 0) stage_q(qkvh, qkvl, sbase, b, qb, h, srow, shalf);
    __syncthreads();

    uint32_t qfh[4][4], qfl[4][4];
    load_q_frags(sbase, w, lane, qfh, qfl);

    AttnState st;
    st.m0 = st.m1 = -1e30f; st.l0 = st.l1 = 0.f;
    #pragma unroll
    for (int nd = 0; nd < 8; nd++)
        #pragma unroll
        for (int t = 0; t < 4; t++) st.co[nd][t] = 0.f;

    uint32_t gbase = D_G0 + grp * D_GRP;
    uint32_t dk  = sbase + gbase + (uint32_t)srow * ARS + shalf * 64;
    uint32_t dkl = dk + 9216, dv = dk + 18432, dvl = dk + 27648;

    for (int jb = 0; jb < 32; jb++) {
        int kb = grp * 32 + jb;
        size_t kbase = ((size_t)(b * SEQ + kb * BLKS + srow)) * QKVD + Dm + h * DHd + shalf * 32;
        __syncthreads();
        stage_kv(qkvh, qkvl, kbase, dk, dkl, dv, dvl);
        __syncthreads();
        attn_block(st, qfh, qfl, sbase, gbase, lane);
    }

    __syncthreads();
    float* mg = (float*)(sb + D_MRG);
    int slot = (w * 32 + lane) * 36;
    if (grp == 1) {
        #pragma unroll
        for (int nd = 0; nd < 8; nd++)
            #pragma unroll
            for (int t = 0; t < 4; t++) mg[slot + nd * 4 + t] = st.co[nd][t];
        mg[slot + 32] = st.m0; mg[slot + 33] = st.m1;
        mg[slot + 34] = st.l0; mg[slot + 35] = st.l1;
    }
    __syncthreads();
    if (grp == 0) {
        float mB0 = mg[slot + 32], mB1 = mg[slot + 33];
        float lB0 = mg[slot + 34], lB1 = mg[slot + 35];
        float M0 = fmaxf(st.m0, mB0), M1 = fmaxf(st.m1, mB1);
        float cA0 = __expf(st.m0 - M0), cB0 = __expf(mB0 - M0);
        float cA1 = __expf(st.m1 - M1), cB1 = __expf(mB1 - M1);
        float L0 = st.l0 * cA0 + lB0 * cB0;
        float L1 = st.l1 * cA1 + lB1 * cB1;
        float inv0 = 1.f / L0, inv1 = 1.f / L1;
        int g = lane >> 2, t4 = lane & 3;
        size_t rbase = ((size_t)(b * SEQ + qb * BLKS + w * 16 + g)) * Dm + h * DHd;
        #pragma unroll
        for (int nd = 0; nd < 8; nd++) {
            float r0 = (st.co[nd][0] * cA0 + mg[slot + nd * 4 + 0] * cB0) * inv0;
            float r1 = (st.co[nd][1] * cA0 + mg[slot + nd * 4 + 1] * cB0) * inv0;
            float r2 = (st.co[nd][2] * cA1 + mg[slot + nd * 4 + 2] * cB1) * inv1;
            float r3 = (st.co[nd][3] * cA1 + mg[slot + nd * 4 + 3] * cB1) * inv1;
            int col = nd * 8 + 2 * t4;
            *(uint32_t*)(ch_g + rbase + col)          = pack2h(r0, r1);
            *(uint32_t*)(ch_g + rbase + 8 * Dm + col) = pack2h(r2, r3);
        }
    }
}

// ---------------- mean pool + linear head ----------------
__global__ void __launch_bounds__(256) pool1_kernel(
    const float* __restrict__ x, const float* __restrict__ w, float* __restrict__ part)
{
    int b = blockIdx.y, sl = blockIdx.x;
    const float* xb = x + ((size_t)b * SEQ + sl * 128) * Dm;
    __shared__ float ws[Dm];
    for (int i = threadIdx.x; i < Dm; i += 256) ws[i] = w[i];
    __syncthreads();
    float acc = 0.f;
    for (int r = 0; r < 128; r++) {
        const float* xr = xb + (size_t)r * Dm;
        for (int i = threadIdx.x; i < Dm; i += 256) acc += xr[i] * ws[i];
    }
    float t = blk_sum256(acc);
    if (threadIdx.x == 0) part[b * 32 + sl] = t;
}
__global__ void pool2_kernel(const float* __restrict__ part,
                             const float* __restrict__ fb, float* __restrict__ out)
{
    int b = threadIdx.x;
    if (b < BB) {
        float s = 0.f;
        for (int i = 0; i < 32; i++) s += part[b * 32 + i];
        out[b] = s * (1.f / (float)SEQ) + fb[0];
    }
}

// ---------------- driver ----------------
extern "C" void kernel_launch(void* const* d_in, const int* in_sizes, int n_in,
                              void* d_out, int out_size)
{
    const int*   ids     = (const int*)  d_in[0];
    const int*   rb      = (const int*)  d_in[1];
    const float* emb_tok = (const float*)d_in[2];
    const float* emb_pos = (const float*)d_in[3];
    const float* lng     = (const float*)d_in[4];
    const float* lnb     = (const float*)d_in[5];
    const float* Wq = (const float*)d_in[6];  const float* bq = (const float*)d_in[7];
    const float* Wk = (const float*)d_in[8];  const float* bk = (const float*)d_in[9];
    const float* Wv = (const float*)d_in[10]; const float* bv = (const float*)d_in[11];
    const float* Wo = (const float*)d_in[12]; const float* bo = (const float*)d_in[13];
    const float* ln1g = (const float*)d_in[14]; const float* ln1b = (const float*)d_in[15];
    const float* W1 = (const float*)d_in[16]; const float* b1 = (const float*)d_in[17];
    const float* W2 = (const float*)d_in[18]; const float* b2 = (const float*)d_in[19];
    const float* ln2g = (const float*)d_in[20]; const float* ln2b = (const float*)d_in[21];
    const float* fcw = (const float*)d_in[22]; const float* fcb = (const float*)d_in[23];

    float *x, *tmp, *part, *bqkv;
    __half *xh, *xl, *qkvh, *qkvl, *ch, *fh, *wh;
    cudaGetSymbolAddress((void**)&x,   g_x);
    cudaGetSymbolAddress((void**)&tmp, g_tmp);
    cudaGetSymbolAddress((void**)&xh,  g_xh);
    cudaGetSymbolAddress((void**)&xl,  g_xl);
    cudaGetSymbolAddress((void**)&qkvh, g_qkvh);
    cudaGetSymbolAddress((void**)&qkvl, g_qkvl);
    cudaGetSymbolAddress((void**)&ch,  g_ch);
    cudaGetSymbolAddress((void**)&fh,  g_fh);
    cudaGetSymbolAddress((void**)&wh,  g_wh);
    cudaGetSymbolAddress((void**)&bqkv, g_bqkv);
    cudaGetSymbolAddress((void**)&part, g_part);

    const int SM_A2 = 2 * 3 * TL64;   // 110592 (2-term A)
    const int SM_A1 = 2 * 2 * TL64;   // 73728  (1-term A)
    cudaFuncSetAttribute((const void*)gemm_mma<0,0,1,1,12>,
                         cudaFuncAttributeMaxDynamicSharedMemorySize, SM_A2);
    cudaFuncSetAttribute((const void*)gemm_mma<0,1,0,0,12>,
                         cudaFuncAttributeMaxDynamicSharedMemorySize, SM_A1);
    cudaFuncSetAttribute((const void*)gemm_mma<1,0,2,0,12>,
                         cudaFuncAttributeMaxDynamicSharedMemorySize, SM_A1);
    cudaFuncSetAttribute((const void*)gemm_mma<0,1,0,0,48>,
                         cudaFuncAttributeMaxDynamicSharedMemorySize, SM_A1);
    cudaFuncSetAttribute((const void*)attn_sparse_kernel,
                         cudaFuncAttributeMaxDynamicSharedMemorySize, A_SMEM);
    cudaFuncSetAttribute((const void*)attn_dense_kernel,
                         cudaFuncAttributeMaxDynamicSharedMemorySize, D_SMEM);

    dim3 gQKV(QKVD / 128, NTOK / 128);
    dim3 gO(Dm / 128, NTOK / 128);
    dim3 gF(FF / 128, NTOK / 128);
    dim3 gAttS(NB - 2, Hh, BB);
    dim3 gAttD(2, Hh, BB);
    dim3 gWS(Dm / 32, Dm / 32);

    wsplit3_kernel<<<dim3(Dm / 32, Dm / 32, 3), 256>>>(
        Wq, Wk, Wv, wh, bq, bk, bv, bqkv);
    wsplit_kernel<<<gWS, 256>>>(Wo, wh + 3 * (size_t)WSZ, Dm, Dm);
    wsplit_kernel<<<dim3(FF / 32, Dm / 32), 256>>>(W1, wh + 4 * (size_t)WSZ, Dm, FF);
    wsplit_kernel<<<dim3(Dm / 32, FF / 32), 256>>>(W2, wh + 4 * (size_t)WSZ + W1SZ, FF, Dm);
    embed_ln_kernel<<<NTOK, 256>>>(ids, emb_tok, emb_pos, lng, lnb, x, xh, xl);

    for (int l = 0; l < 2; l++) {
        size_t o = (size_t)l * OFFL;
        gemm_mma<0,0,1,1,12><<<gQKV, 256, SM_A2>>>(xh, xl, wh + o, bqkv + l * QKVD,
            nullptr, qkvh, qkvl, NTOK, QKVD);
        attn_sparse_kernel<<<gAttS, 128, A_SMEM>>>(qkvh, qkvl, rb, ch);
        attn_dense_kernel<<<gAttD, 256, D_SMEM>>>(qkvh, qkvl, ch);
        gemm_mma<0,1,0,0,12><<<gO, 256, SM_A1>>>(ch, nullptr, wh + o + 3 * WSZ,
            bo + l * Dm, tmp, nullptr, nullptr, NTOK, Dm);
        add_ln_kernel<<<NTOK, 256>>>(x, tmp, ln1g + l * Dm, ln1b + l * Dm, xh, xl);
        gemm_mma<1,0,2,0,12><<<gF, 256, SM_A1>>>(xh, nullptr, wh + o + 4 * WSZ,
            b1 + l * FF, nullptr, fh, nullptr, NTOK, FF);
        gemm_mma<0,1,0,0,48><<<gO, 256, SM_A1>>>(fh, nullptr, wh + o + 4 * WSZ + W1SZ,
            b2 + l * Dm, tmp, nullptr, nullptr, NTOK, Dm);
        add_ln_kernel<<<NTOK, 256>>>(x, tmp, ln2g + l * Dm, ln2b + l * Dm, xh, xl);

        if (l == 0) {
            size_t o1 = OFFL;
            wsplit3_kernel<<<dim3(Dm / 32, Dm / 32, 3), 256>>>(
                Wq + WSZ, Wk + WSZ, Wv + WSZ, wh + o1,
                bq + Dm, bk + Dm, bv + Dm, bqkv + QKVD);
            wsplit_kernel<<<gWS, 256>>>(Wo + WSZ, wh + o1 + 3 * (size_t)WSZ, Dm, Dm);
            wsplit_kernel<<<dim3(FF / 32, Dm / 32), 256>>>(W1 + W1SZ, wh + o1 + 4 * (size_t)WSZ, Dm, FF);
            wsplit_kernel<<<dim3(Dm / 32, FF / 32), 256>>>(W2 + W1SZ, wh + o1 + 4 * (size_t)WSZ + W1SZ, FF, Dm);
        }
    }

    pool1_kernel<<<dim3(32, BB), 256>>>(x, fcw, part);
    pool2_kernel<<<1, 32>>>(part, fcb, (float*)d_out);
}

// round 15
// speedup vs baseline: 2.0135x; 1.0419x over previous
#include <cuda_runtime.h>
#include <cuda_fp16.h>
#include <math.h>
#include <stdint.h>

// ---------------- problem constants ----------------
#define Dm   768
#define Hh   12
#define DHd  64
#define BLKS 64
#define NB   64
#define SEQ  4096
#define BB   2
#define NTOK (BB*SEQ)
#define RR   3
#define FF   3072
#define QKVD 2304

#define WSZ   589824
#define W1SZ  2359296
#define OFFL  (4*WSZ + 2*W1SZ)

// ---------------- scratch (device globals) ----------------
__device__ float g_x  [NTOK*Dm];
__device__ float g_tmp[NTOK*Dm];
__device__ __half g_xh [NTOK*Dm];
__device__ __half g_xl [NTOK*Dm];
__device__ __half g_qkvh[NTOK*QKVD];
__device__ __half g_qkvl[NTOK*QKVD];
__device__ __half g_ch [NTOK*Dm];
__device__ __half g_fh [NTOK*FF];
__device__ __half g_wh [2*OFFL];
__device__ float g_bqkv[2*QKVD];
__device__ float g_part[64];

// ---------------- helpers ----------------
__device__ __forceinline__ float gelu_tanh(float x) {
    float x3 = x * x * x;
    return 0.5f * x * (1.f + tanhf(0.7978845608028654f * (x + 0.044715f * x3)));
}

__device__ __forceinline__ float blk_sum256(float v) {
    __shared__ float red[32];
    int lane = threadIdx.x & 31, wid = threadIdx.x >> 5;
    #pragma unroll
    for (int o = 16; o > 0; o >>= 1) v += __shfl_xor_sync(0xffffffffu, v, o);
    if (lane == 0) red[wid] = v;
    __syncthreads();
    if (wid == 0) {
        v = (lane < 8) ? red[lane] : 0.f;
        #pragma unroll
        for (int o = 4; o > 0; o >>= 1) v += __shfl_xor_sync(0xffffffffu, v, o);
        if (lane == 0) red[0] = v;
    }
    __syncthreads();
    float r = red[0];
    __syncthreads();
    return r;
}

__device__ __forceinline__ uint32_t s2u(const void* p) {
    uint32_t a;
    asm("{ .reg .u64 t; cvta.to.shared.u64 t, %1; cvt.u32.u64 %0, t; }" : "=r"(a) : "l"(p));
    return a;
}

#define LDSM4(r, a) \
    asm volatile("ldmatrix.sync.aligned.m8n8.x4.shared.b16 {%0,%1,%2,%3}, [%4];" \
        : "=r"((r)[0]), "=r"((r)[1]), "=r"((r)[2]), "=r"((r)[3]) : "r"(a))
#define LDSM2(r0, r1, a) \
    asm volatile("ldmatrix.sync.aligned.m8n8.x2.shared.b16 {%0,%1}, [%2];" \
        : "=r"(r0), "=r"(r1) : "r"(a))
#define LDSM2T(r0, r1, a) \
    asm volatile("ldmatrix.sync.aligned.m8n8.x2.trans.shared.b16 {%0,%1}, [%2];" \
        : "=r"(r0), "=r"(r1) : "r"(a))

#define CPA16(dst, src) \
    asm volatile("cp.async.cg.shared.global [%0], [%1], 16;" :: "r"(dst), "l"(src))
#define CP_COMMIT() asm volatile("cp.async.commit_group;" ::: "memory")
#define CP_WAIT(n)  asm volatile("cp.async.wait_group %0;" :: "n"(n) : "memory")

__device__ __forceinline__ void mma16816(float* c, const uint32_t* a,
                                         uint32_t b0, uint32_t b1) {
    asm volatile(
        "mma.sync.aligned.m16n8k16.row.col.f32.f16.f16.f32 "
        "{%0,%1,%2,%3}, {%4,%5,%6,%7}, {%8,%9}, {%0,%1,%2,%3};"
        : "+f"(c[0]), "+f"(c[1]), "+f"(c[2]), "+f"(c[3])
        : "r"(a[0]), "r"(a[1]), "r"(a[2]), "r"(a[3]), "r"(b0), "r"(b1));
}

__device__ __forceinline__ void split2h(float a, float b, uint32_t& hi, uint32_t& lo) {
    __half ha = __float2half_rn(a);
    __half hb = __float2half_rn(b);
    __half la = __float2half_rn(a - __half2float(ha));
    __half lb = __float2half_rn(b - __half2float(hb));
    hi = (uint32_t)__half_as_ushort(ha) | ((uint32_t)__half_as_ushort(hb) << 16);
    lo = (uint32_t)__half_as_ushort(la) | ((uint32_t)__half_as_ushort(lb) << 16);
}

__device__ __forceinline__ uint32_t pack2h(float a, float b) {
    __half2 h = __floats2half2_rn(a, b);
    return *(uint32_t*)&h;
}

// ---------------- weight transpose + fp16 convert ----------------
__global__ void __launch_bounds__(256) wsplit_kernel(
    const float* __restrict__ W, __half* __restrict__ hi, int K, int N)
{
    __shared__ float t[32][33];
    int n0 = blockIdx.x * 32, k0 = blockIdx.y * 32;
    int tx = threadIdx.x & 31, ty = threadIdx.x >> 5;
    #pragma unroll
    for (int j = 0; j < 4; j++)
        t[ty + j * 8][tx] = W[(size_t)(k0 + ty + j * 8) * N + n0 + tx];
    __syncthreads();
    #pragma unroll
    for (int j = 0; j < 4; j++) {
        int n = n0 + ty + j * 8, k = k0 + tx;
        hi[(size_t)n * K + k] = __float2half_rn(t[tx][ty + j * 8]);
    }
}

__global__ void __launch_bounds__(256) wsplit3_kernel(
    const float* __restrict__ Wa, const float* __restrict__ Wb,
    const float* __restrict__ Wc, __half* __restrict__ hi,
    const float* __restrict__ ba, const float* __restrict__ bb,
    const float* __restrict__ bc, float* __restrict__ bqkv)
{
    __shared__ float t[32][33];
    int z = blockIdx.z;
    const float* W = (z == 0) ? Wa : (z == 1) ? Wb : Wc;
    __half* hz = hi + (size_t)z * WSZ;
    int n0 = blockIdx.x * 32, k0 = blockIdx.y * 32;
    int tx = threadIdx.x & 31, ty = threadIdx.x >> 5;
    if (blockIdx.x == 0 && blockIdx.y == 0) {
        const float* bz = (z == 0) ? ba : (z == 1) ? bb : bc;
        for (int i = threadIdx.x; i < Dm; i += 256) bqkv[z * Dm + i] = bz[i];
    }
    #pragma unroll
    for (int j = 0; j < 4; j++)
        t[ty + j * 8][tx] = W[(size_t)(k0 + ty + j * 8) * Dm + n0 + tx];
    __syncthreads();
    #pragma unroll
    for (int j = 0; j < 4; j++) {
        int n = n0 + ty + j * 8, k = k0 + tx;
        hz[(size_t)n * Dm + k] = __float2half_rn(t[tx][ty + j * 8]);
    }
}

// ---------------- cp.async warp-MMA GEMM (BK=64, x4 B-loads, 1 barrier/chunk) ----------------
// AT2=1: A = hi+lo fp16 (2 MMA terms); AT2=0: A = hi only (1 term).
// WSPL: 0=none, 1=write Chi+Clo (split), 2=write Chi only (fp16 rn).
#define RS64  144
#define TL64  (128*RS64)        // 18432

template<int GELU, int WF32, int WSPL, int AT2, int KC>
__global__ void __launch_bounds__(256, 2) gemm_mma(
    const __half* __restrict__ Ahi, const __half* __restrict__ Alo,
    const __half* __restrict__ Bh,
    const float* __restrict__ bias, float* __restrict__ C,
    __half* __restrict__ Chi, __half* __restrict__ Clo,
    int M, int N)
{
    const int K = KC * 64;
    const int STG  = (AT2 ? 3 : 2) * TL64;
    const int BOFF = (AT2 ? 2 : 1) * TL64;
    extern __shared__ char sm[];
    uint32_t sbase = s2u(sm);
    int tid = threadIdx.x, lane = tid & 31, wid = tid >> 5;
    int m0 = blockIdx.y * 128, n0 = blockIdx.x * 128;
    int wm = (wid & 3) * 32, wn = (wid >> 2) * 64;

    int lr = tid & 127, lh = tid >> 7;          // row, 64-byte half
    const __half* ah_p = Ahi + (size_t)(m0 + lr) * K + lh * 32;
    const __half* al_p = AT2 ? (Alo + (size_t)(m0 + lr) * K + lh * 32) : nullptr;
    const __half* bh_p = Bh  + (size_t)(n0 + lr) * K + lh * 32;
    uint32_t woff = (uint32_t)lr * RS64 + (uint32_t)lh * 64;

    float acc[2][8][4];
    #pragma unroll
    for (int i = 0; i < 2; i++)
        #pragma unroll
        for (int j = 0; j < 8; j++)
            #pragma unroll
            for (int t = 0; t < 4; t++) acc[i][j][t] = 0.f;

    {   // prologue: issue chunk 0
        uint32_t d = sbase + woff;
        #pragma unroll
        for (int q = 0; q < 4; q++) CPA16(d + q * 16, ah_p + q * 8);
        if (AT2) {
            #pragma unroll
            for (int q = 0; q < 4; q++) CPA16(d + TL64 + q * 16, al_p + q * 8);
        }
        #pragma unroll
        for (int q = 0; q < 4; q++) CPA16(d + BOFF + q * 16, bh_p + q * 8);
        CP_COMMIT();
    }

    int r16 = lane & 15, c16 = lane >> 4;
    // B x4 fragment address: pairs of ni; lane groups -> {ni,k0},{ni,k16},{ni+1,k0},{ni+1,k16}
    uint32_t brow = (uint32_t)(wn + (lane & 7) + ((lane >> 4) & 1) * 8);
    uint32_t bcol16 = ((lane >> 3) & 1) * 16;

    for (int c = 0; c < KC; c++) {
        CP_WAIT(0);
        __syncthreads();
        if (c + 1 < KC) {   // issue next chunk; overlaps compute below
            uint32_t d = sbase + ((c + 1) & 1) * STG + woff;
            int off = (c + 1) * 64;
            #pragma unroll
            for (int q = 0; q < 4; q++) CPA16(d + q * 16, ah_p + off + q * 8);
            if (AT2) {
                #pragma unroll
                for (int q = 0; q < 4; q++) CPA16(d + TL64 + q * 16, al_p + off + q * 8);
            }
            #pragma unroll
            for (int q = 0; q < 4; q++) CPA16(d + BOFF + q * 16, bh_p + off + q * 8);
            CP_COMMIT();
        }
        {
            uint32_t base = sbase + (c & 1) * STG;
            #pragma unroll
            for (int ks = 0; ks < 4; ks++) {
                uint32_t ah[2][4], al[2][4];
                #pragma unroll
                for (int mi = 0; mi < 2; mi++) {
                    uint32_t rel = (uint32_t)(wm + mi * 16 + r16) * RS64
                                 + ks * 32 + c16 * 16;
                    LDSM4(ah[mi], base + rel);
                    if (AT2) LDSM4(al[mi], base + TL64 + rel);
                }
                #pragma unroll
                for (int nip = 0; nip < 4; nip++) {
                    uint32_t bb[4];
                    uint32_t rel = (brow + nip * 16) * RS64 + ks * 32 + bcol16;
                    LDSM4(bb, base + BOFF + rel);
                    #pragma unroll
                    for (int mi = 0; mi < 2; mi++) {
                        mma16816(acc[mi][2 * nip],     ah[mi], bb[0], bb[1]);
                        mma16816(acc[mi][2 * nip + 1], ah[mi], bb[2], bb[3]);
                        if (AT2) {
                            mma16816(acc[mi][2 * nip],     al[mi], bb[0], bb[1]);
                            mma16816(acc[mi][2 * nip + 1], al[mi], bb[2], bb[3]);
                        }
                    }
                }
            }
        }
    }

    int g = lane >> 2, t4 = lane & 3;
    #pragma unroll
    for (int mi = 0; mi < 2; mi++) {
        int row0 = m0 + wm + mi * 16 + g;
        #pragma unroll
        for (int ni = 0; ni < 8; ni++) {
            int col = n0 + wn + ni * 8 + 2 * t4;
            float2 bi = *(const float2*)(bias + col);
            float2 o0, o1;
            o0.x = acc[mi][ni][0] + bi.x;
            o0.y = acc[mi][ni][1] + bi.y;
            o1.x = acc[mi][ni][2] + bi.x;
            o1.y = acc[mi][ni][3] + bi.y;
            if (GELU) {
                o0.x = gelu_tanh(o0.x); o0.y = gelu_tanh(o0.y);
                o1.x = gelu_tanh(o1.x); o1.y = gelu_tanh(o1.y);
            }
            size_t i0 = (size_t)row0 * N + col;
            size_t i1 = (size_t)(row0 + 8) * N + col;
            if (WF32) {
                *(float2*)(C + i0) = o0;
                *(float2*)(C + i1) = o1;
            }
            if (WSPL == 1) {
                uint32_t h0, l0, h1, l1;
                split2h(o0.x, o0.y, h0, l0);
                split2h(o1.x, o1.y, h1, l1);
                *(uint32_t*)(Chi + i0) = h0;
                *(uint32_t*)(Clo + i0) = l0;
                *(uint32_t*)(Chi + i1) = h1;
                *(uint32_t*)(Clo + i1) = l1;
            }
            if (WSPL == 2) {
                *(uint32_t*)(Chi + i0) = pack2h(o0.x, o0.y);
                *(uint32_t*)(Chi + i1) = pack2h(o1.x, o1.y);
            }
        }
    }
}

// ---------------- embedding + LN ----------------
__global__ void __launch_bounds__(256) embed_ln_kernel(
    const int* __restrict__ ids, const float* __restrict__ tok,
    const float* __restrict__ pos, const float* __restrict__ g,
    const float* __restrict__ b, float* __restrict__ x,
    __half* __restrict__ xh, __half* __restrict__ xl)
{
    int t = blockIdx.x, s = t & (SEQ - 1), id = ids[t];
    float val[3];
    #pragma unroll
    for (int j = 0; j < 3; j++) {
        int i = threadIdx.x + j * 256;
        val[j] = tok[(size_t)id * Dm + i] + pos[(size_t)s * Dm + i];
    }
    float mean = blk_sum256(val[0] + val[1] + val[2]) * (1.f / 768.f);
    float sq = 0.f;
    #pragma unroll
    for (int j = 0; j < 3; j++) { float d = val[j] - mean; sq += d * d; }
    float rstd = rsqrtf(blk_sum256(sq) * (1.f / 768.f) + 1e-12f);
    #pragma unroll
    for (int j = 0; j < 3; j++) {
        int i = threadIdx.x + j * 256;
        float o = (val[j] - mean) * rstd * g[i] + b[i];
        size_t idx = (size_t)t * Dm + i;
        x[idx] = o;
        __half h = __float2half_rn(o);
        xh[idx] = h;
        xl[idx] = __float2half_rn(o - __half2float(h));
    }
}

// ---------------- residual add + LN ----------------
__global__ void __launch_bounds__(256) add_ln_kernel(
    float* __restrict__ x, const float* __restrict__ y,
    const float* __restrict__ g, const float* __restrict__ b,
    __half* __restrict__ xh, __half* __restrict__ xl)
{
    size_t t = blockIdx.x;
    float* xp = x + t * Dm;
    const float* yp = y + t * Dm;
    float val[3];
    #pragma unroll
    for (int j = 0; j < 3; j++) {
        int i = threadIdx.x + j * 256;
        val[j] = xp[i] + yp[i];
    }
    float mean = blk_sum256(val[0] + val[1] + val[2]) * (1.f / 768.f);
    float sq = 0.f;
    #pragma unroll
    for (int j = 0; j < 3; j++) { float d = val[j] - mean; sq += d * d; }
    float rstd = rsqrtf(blk_sum256(sq) * (1.f / 768.f) + 1e-12f);
    #pragma unroll
    for (int j = 0; j < 3; j++) {
        int i = threadIdx.x + j * 256;
        float o = (val[j] - mean) * rstd * g[i] + b[i];
        xp[i] = o;
        __half h = __float2half_rn(o);
        xh[t * Dm + i] = h;
        xl[t * Dm + i] = __float2half_rn(o - __half2float(h));
    }
}

// ================= attention (fp16, 3-term compensated) =================
#define ARS 144
#define A_QH 0
#define A_QL 9216
#define A_KH 18432
#define A_SMEM 55296
#define D_GRP 36864
#define D_G0  18432
#define D_SMEM (18432 + 2*D_GRP)
#define D_MRG 18432

struct AttnState {
    float m0, m1, l0, l1;
    float co[8][4];
};

__device__ __forceinline__ void stage_kv(
    const __half* __restrict__ qkvh, const __half* __restrict__ qkvl,
    size_t kbase, uint32_t dk, uint32_t dkl, uint32_t dv, uint32_t dvl)
{
    size_t vbase = kbase + Dm;
    CPA16(dk,      qkvh + kbase);      CPA16(dk + 16, qkvh + kbase + 8);
    CPA16(dk + 32, qkvh + kbase + 16); CPA16(dk + 48, qkvh + kbase + 24);
    CPA16(dkl,      qkvl + kbase);      CPA16(dkl + 16, qkvl + kbase + 8);
    CPA16(dkl + 32, qkvl + kbase + 16); CPA16(dkl + 48, qkvl + kbase + 24);
    CPA16(dv,      qkvh + vbase);      CPA16(dv + 16, qkvh + vbase + 8);
    CPA16(dv + 32, qkvh + vbase + 16); CPA16(dv + 48, qkvh + vbase + 24);
    CPA16(dvl,      qkvl + vbase);      CPA16(dvl + 16, qkvl + vbase + 8);
    CPA16(dvl + 32, qkvl + vbase + 16); CPA16(dvl + 48, qkvl + vbase + 24);
    CP_COMMIT(); CP_WAIT(0);
}

__device__ __forceinline__ void attn_block(
    AttnState& st, const uint32_t qfh[4][4], const uint32_t qfl[4][4],
    uint32_t sbase, uint32_t offKH, int lane)
{
    const uint32_t dKL = 9216, dVH = 18432, dVL = 27648;
    uint32_t kb_h = sbase + offKH + (uint32_t)(lane & 7) * ARS + ((lane >> 3) & 1) * 16;
    float sc[8][4];
    #pragma unroll
    for (int ni = 0; ni < 8; ni++)
        #pragma unroll
        for (int t = 0; t < 4; t++) sc[ni][t] = 0.f;
    #pragma unroll
    for (int ni = 0; ni < 8; ni++) {
        uint32_t ba_h = kb_h + (uint32_t)(ni * 8) * ARS;
        #pragma unroll
        for (int ks = 0; ks < 4; ks++) {
            uint32_t bh0, bh1, bl0, bl1;
            LDSM2(bh0, bh1, ba_h + ks * 32);
            LDSM2(bl0, bl1, ba_h + dKL + ks * 32);
            mma16816(sc[ni], qfh[ks], bh0, bh1);
            mma16816(sc[ni], qfh[ks], bl0, bl1);
            mma16816(sc[ni], qfl[ks], bh0, bh1);
        }
    }
    #pragma unroll
    for (int ni = 0; ni < 8; ni++) {
        sc[ni][0] *= 0.125f; sc[ni][1] *= 0.125f;
        sc[ni][2] *= 0.125f; sc[ni][3] *= 0.125f;
    }
    float bm0 = -1e30f, bm1 = -1e30f;
    #pragma unroll
    for (int ni = 0; ni < 8; ni++) {
        bm0 = fmaxf(bm0, fmaxf(sc[ni][0], sc[ni][1]));
        bm1 = fmaxf(bm1, fmaxf(sc[ni][2], sc[ni][3]));
    }
    bm0 = fmaxf(bm0, __shfl_xor_sync(0xffffffffu, bm0, 1));
    bm0 = fmaxf(bm0, __shfl_xor_sync(0xffffffffu, bm0, 2));
    bm1 = fmaxf(bm1, __shfl_xor_sync(0xffffffffu, bm1, 1));
    bm1 = fmaxf(bm1, __shfl_xor_sync(0xffffffffu, bm1, 2));
    float mn0 = fmaxf(st.m0, bm0), mn1 = fmaxf(st.m1, bm1);
    float corr0 = __expf(st.m0 - mn0), corr1 = __expf(st.m1 - mn1);
    st.m0 = mn0; st.m1 = mn1;
    #pragma unroll
    for (int nd = 0; nd < 8; nd++) {
        st.co[nd][0] *= corr0; st.co[nd][1] *= corr0;
        st.co[nd][2] *= corr1; st.co[nd][3] *= corr1;
    }
    float ls0 = 0.f, ls1 = 0.f;
    #pragma unroll
    for (int ni = 0; ni < 8; ni++) {
        sc[ni][0] = __expf(sc[ni][0] - mn0);
        sc[ni][1] = __expf(sc[ni][1] - mn0);
        sc[ni][2] = __expf(sc[ni][2] - mn1);
        sc[ni][3] = __expf(sc[ni][3] - mn1);
        ls0 += sc[ni][0] + sc[ni][1];
        ls1 += sc[ni][2] + sc[ni][3];
    }
    ls0 += __shfl_xor_sync(0xffffffffu, ls0, 1);
    ls0 += __shfl_xor_sync(0xffffffffu, ls0, 2);
    ls1 += __shfl_xor_sync(0xffffffffu, ls1, 1);
    ls1 += __shfl_xor_sync(0xffffffffu, ls1, 2);
    st.l0 = st.l0 * corr0 + ls0;
    st.l1 = st.l1 * corr1 + ls1;

    uint32_t pah[4][4], pal[4][4];
    #pragma unroll
    for (int ksp = 0; ksp < 4; ksp++) {
        split2h(sc[2*ksp][0],   sc[2*ksp][1],   pah[ksp][0], pal[ksp][0]);
        split2h(sc[2*ksp][2],   sc[2*ksp][3],   pah[ksp][1], pal[ksp][1]);
        split2h(sc[2*ksp+1][0], sc[2*ksp+1][1], pah[ksp][2], pal[ksp][2]);
        split2h(sc[2*ksp+1][2], sc[2*ksp+1][3], pah[ksp][3], pal[ksp][3]);
    }
    #pragma unroll
    for (int nd = 0; nd < 8; nd++) {
        #pragma unroll
        for (int ksp = 0; ksp < 4; ksp++) {
            uint32_t va = sbase + offKH + dVH
                        + (uint32_t)(ksp * 16 + (lane & 15)) * ARS + nd * 16;
            uint32_t vh0, vh1, vl0, vl1;
            LDSM2T(vh0, vh1, va);
            LDSM2T(vl0, vl1, va + (dVL - dVH));
            mma16816(st.co[nd], pah[ksp], vh0, vh1);
            mma16816(st.co[nd], pah[ksp], vl0, vl1);
            mma16816(st.co[nd], pal[ksp], vh0, vh1);
        }
    }
}

__device__ __forceinline__ void load_q_frags(
    uint32_t sbase, int warp_q, int lane, uint32_t qfh[4][4], uint32_t qfl[4][4])
{
    uint32_t qa_h = sbase + A_QH + (uint32_t)(warp_q * 16 + (lane & 15)) * ARS + (lane >> 4) * 16;
    uint32_t qa_l = qa_h + (A_QL - A_QH);
    #pragma unroll
    for (int ks = 0; ks < 4; ks++) {
        LDSM4(qfh[ks], qa_h + ks * 32);
        LDSM4(qfl[ks], qa_l + ks * 32);
    }
}

__device__ __forceinline__ void stage_q(
    const __half* __restrict__ qkvh, const __half* __restrict__ qkvl,
    uint32_t sbase, int b, int qb, int h, int srow, int shalf)
{
    size_t off = ((size_t)(b * SEQ + qb * BLKS + srow)) * QKVD + h * DHd + shalf * 32;
    uint32_t dh = sbase + A_QH + (uint32_t)srow * ARS + shalf * 64;
    uint32_t dl = sbase + A_QL + (uint32_t)srow * ARS + shalf * 64;
    CPA16(dh,      qkvh + off);      CPA16(dh + 16, qkvh + off + 8);
    CPA16(dh + 32, qkvh + off + 16); CPA16(dh + 48, qkvh + off + 24);
    CPA16(dl,      qkvl + off);      CPA16(dl + 16, qkvl + off + 8);
    CPA16(dl + 32, qkvl + off + 16); CPA16(dl + 48, qkvl + off + 24);
    CP_COMMIT(); CP_WAIT(0);
}

// ---------------- sparse attention ----------------
__global__ void __launch_bounds__(128) attn_sparse_kernel(
    const __half* __restrict__ qkvh, const __half* __restrict__ qkvl,
    const int* __restrict__ rb, __half* __restrict__ ch_g)
{
    extern __shared__ char sb[];
    uint32_t sbase = s2u(sb);
    int b = blockIdx.z, h = blockIdx.y, qb = blockIdx.x + 1;
    int tid = threadIdx.x, lane = tid & 31, w = tid >> 5;
    int srow = tid >> 1, shalf = tid & 1;

    stage_q(qkvh, qkvl, sbase, b, qb, h, srow, shalf);
    __syncthreads();

    uint32_t qfh[4][4], qfl[4][4];
    load_q_frags(sbase, w, lane, qfh, qfl);

    AttnState st;
    st.m0 = st.m1 = -1e30f; st.l0 = st.l1 = 0.f;
    #pragma unroll
    for (int nd = 0; nd < 8; nd++)
        #pragma unroll
        for (int t = 0; t < 4; t++) st.co[nd][t] = 0.f;

    int blist[8];
    blist[0] = 0; blist[1] = qb - 1; blist[2] = qb; blist[3] = qb + 1;
    blist[4] = NB - 1;
    const int* rp = rb + (h * NB + qb) * RR;
    blist[5] = rp[0]; blist[6] = rp[1]; blist[7] = rp[2];

    uint32_t dk  = sbase + A_KH + (uint32_t)srow * ARS + shalf * 64;
    uint32_t dkl = dk + 9216, dv = dk + 18432, dvl = dk + 27648;

    for (int jb = 0; jb < 8; jb++) {
        int kb = blist[jb];
        size_t kbase = ((size_t)(b * SEQ + kb * BLKS + srow)) * QKVD + Dm + h * DHd + shalf * 32;
        __syncthreads();
        stage_kv(qkvh, qkvl, kbase, dk, dkl, dv, dvl);
        __syncthreads();
        attn_block(st, qfh, qfl, sbase, A_KH, lane);
    }

    float inv0 = 1.f / st.l0, inv1 = 1.f / st.l1;
    int g = lane >> 2, t4 = lane & 3;
    size_t rbase = ((size_t)(b * SEQ + qb * BLKS + w * 16 + g)) * Dm + h * DHd;
    #pragma unroll
    for (int nd = 0; nd < 8; nd++) {
        int col = nd * 8 + 2 * t4;
        *(uint32_t*)(ch_g + rbase + col) =
            pack2h(st.co[nd][0] * inv0, st.co[nd][1] * inv0);
        *(uint32_t*)(ch_g + rbase + 8 * Dm + col) =
            pack2h(st.co[nd][2] * inv1, st.co[nd][3] * inv1);
    }
}

// ---------------- dense attention (query blocks 0, NB-1) ----------------
__global__ void __launch_bounds__(256) attn_dense_kernel(
    const __half* __restrict__ qkvh, const __half* __restrict__ qkvl,
    __half* __restrict__ ch_g)
{
    extern __shared__ char sb[];
    uint32_t sbase = s2u(sb);
    int b = blockIdx.z, h = blockIdx.y;
    int qb = (blockIdx.x == 0) ? 0 : NB - 1;
    int tid = threadIdx.x, lane = tid & 31;
    int grp = tid >> 7, ltid = tid & 127, w = ltid >> 5;
    int srow = ltid >> 1, shalf = ltid & 1;

    if (grp == 0) stage_q(qkvh, qkvl, sbase, b, qb, h, srow, shalf);
    __syncthreads();

    uint32_t qfh[4][4], qfl[4][4];
    load_q_frags(sbase, w, lane, qfh, qfl);

    AttnState st;
    st.m0 = st.m1 = -1e30f; st.l0 = st.l1 = 0.f;
    #pragma unroll
    for (int nd = 0; nd < 8; nd++)
        #pragma unroll
        for (int t = 0; t < 4; t++) st.co[nd][t] = 0.f;

    uint32_t gbase = D_G0 + grp * D_GRP;
    uint32_t dk  = sbase + gbase + (uint32_t)srow * ARS + shalf * 64;
    uint32_t dkl = dk + 9216, dv = dk + 18432, dvl = dk + 27648;

    for (int jb = 0; jb < 32; jb++) {
        int kb = grp * 32 + jb;
        size_t kbase = ((size_t)(b * SEQ + kb * BLKS + srow)) * QKVD + Dm + h * DHd + shalf * 32;
        __syncthreads();
        stage_kv(qkvh, qkvl, kbase, dk, dkl, dv, dvl);
        __syncthreads();
        attn_block(st, qfh, qfl, sbase, gbase, lane);
    }

    __syncthreads();
    float* mg = (float*)(sb + D_MRG);
    int slot = (w * 32 + lane) * 36;
    if (grp == 1) {
        #pragma unroll
        for (int nd = 0; nd < 8; nd++)
            #pragma unroll
            for (int t = 0; t < 4; t++) mg[slot + nd * 4 + t] = st.co[nd][t];
        mg[slot + 32] = st.m0; mg[slot + 33] = st.m1;
        mg[slot + 34] = st.l0; mg[slot + 35] = st.l1;
    }
    __syncthreads();
    if (grp == 0) {
        float mB0 = mg[slot + 32], mB1 = mg[slot + 33];
        float lB0 = mg[slot + 34], lB1 = mg[slot + 35];
        float M0 = fmaxf(st.m0, mB0), M1 = fmaxf(st.m1, mB1);
        float cA0 = __expf(st.m0 - M0), cB0 = __expf(mB0 - M0);
        float cA1 = __expf(st.m1 - M1), cB1 = __expf(mB1 - M1);
        float L0 = st.l0 * cA0 + lB0 * cB0;
        float L1 = st.l1 * cA1 + lB1 * cB1;
        float inv0 = 1.f / L0, inv1 = 1.f / L1;
        int g = lane >> 2, t4 = lane & 3;
        size_t rbase = ((size_t)(b * SEQ + qb * BLKS + w * 16 + g)) * Dm + h * DHd;
        #pragma unroll
        for (int nd = 0; nd < 8; nd++) {
            float r0 = (st.co[nd][0] * cA0 + mg[slot + nd * 4 + 0] * cB0) * inv0;
            float r1 = (st.co[nd][1] * cA0 + mg[slot + nd * 4 + 1] * cB0) * inv0;
            float r2 = (st.co[nd][2] * cA1 + mg[slot + nd * 4 + 2] * cB1) * inv1;
            float r3 = (st.co[nd][3] * cA1 + mg[slot + nd * 4 + 3] * cB1) * inv1;
            int col = nd * 8 + 2 * t4;
            *(uint32_t*)(ch_g + rbase + col)          = pack2h(r0, r1);
            *(uint32_t*)(ch_g + rbase + 8 * Dm + col) = pack2h(r2, r3);
        }
    }
}

// ---------------- mean pool + linear head ----------------
__global__ void __launch_bounds__(256) pool1_kernel(
    const float* __restrict__ x, const float* __restrict__ w, float* __restrict__ part)
{
    int b = blockIdx.y, sl = blockIdx.x;
    const float* xb = x + ((size_t)b * SEQ + sl * 128) * Dm;
    __shared__ float ws[Dm];
    for (int i = threadIdx.x; i < Dm; i += 256) ws[i] = w[i];
    __syncthreads();
    float acc = 0.f;
    for (int r = 0; r < 128; r++) {
        const float* xr = xb + (size_t)r * Dm;
        for (int i = threadIdx.x; i < Dm; i += 256) acc += xr[i] * ws[i];
    }
    float t = blk_sum256(acc);
    if (threadIdx.x == 0) part[b * 32 + sl] = t;
}
__global__ void pool2_kernel(const float* __restrict__ part,
                             const float* __restrict__ fb, float* __restrict__ out)
{
    int b = threadIdx.x;
    if (b < BB) {
        float s = 0.f;
        for (int i = 0; i < 32; i++) s += part[b * 32 + i];
        out[b] = s * (1.f / (float)SEQ) + fb[0];
    }
}

// ---------------- driver ----------------
extern "C" void kernel_launch(void* const* d_in, const int* in_sizes, int n_in,
                              void* d_out, int out_size)
{
    const int*   ids     = (const int*)  d_in[0];
    const int*   rb      = (const int*)  d_in[1];
    const float* emb_tok = (const float*)d_in[2];
    const float* emb_pos = (const float*)d_in[3];
    const float* lng     = (const float*)d_in[4];
    const float* lnb     = (const float*)d_in[5];
    const float* Wq = (const float*)d_in[6];  const float* bq = (const float*)d_in[7];
    const float* Wk = (const float*)d_in[8];  const float* bk = (const float*)d_in[9];
    const float* Wv = (const float*)d_in[10]; const float* bv = (const float*)d_in[11];
    const float* Wo = (const float*)d_in[12]; const float* bo = (const float*)d_in[13];
    const float* ln1g = (const float*)d_in[14]; const float* ln1b = (const float*)d_in[15];
    const float* W1 = (const float*)d_in[16]; const float* b1 = (const float*)d_in[17];
    const float* W2 = (const float*)d_in[18]; const float* b2 = (const float*)d_in[19];
    const float* ln2g = (const float*)d_in[20]; const float* ln2b = (const float*)d_in[21];
    const float* fcw = (const float*)d_in[22]; const float* fcb = (const float*)d_in[23];

    float *x, *tmp, *part, *bqkv;
    __half *xh, *xl, *qkvh, *qkvl, *ch, *fh, *wh;
    cudaGetSymbolAddress((void**)&x,   g_x);
    cudaGetSymbolAddress((void**)&tmp, g_tmp);
    cudaGetSymbolAddress((void**)&xh,  g_xh);
    cudaGetSymbolAddress((void**)&xl,  g_xl);
    cudaGetSymbolAddress((void**)&qkvh, g_qkvh);
    cudaGetSymbolAddress((void**)&qkvl, g_qkvl);
    cudaGetSymbolAddress((void**)&ch,  g_ch);
    cudaGetSymbolAddress((void**)&fh,  g_fh);
    cudaGetSymbolAddress((void**)&wh,  g_wh);
    cudaGetSymbolAddress((void**)&bqkv, g_bqkv);
    cudaGetSymbolAddress((void**)&part, g_part);

    const int SM_A2 = 2 * 3 * TL64;   // 110592 (2-term A)
    const int SM_A1 = 2 * 2 * TL64;   // 73728  (1-term A)
    cudaFuncSetAttribute((const void*)gemm_mma<0,0,1,1,12>,
                         cudaFuncAttributeMaxDynamicSharedMemorySize, SM_A2);
    cudaFuncSetAttribute((const void*)gemm_mma<0,1,0,0,12>,
                         cudaFuncAttributeMaxDynamicSharedMemorySize, SM_A1);
    cudaFuncSetAttribute((const void*)gemm_mma<1,0,2,0,12>,
                         cudaFuncAttributeMaxDynamicSharedMemorySize, SM_A1);
    cudaFuncSetAttribute((const void*)gemm_mma<0,1,0,0,48>,
                         cudaFuncAttributeMaxDynamicSharedMemorySize, SM_A1);
    cudaFuncSetAttribute((const void*)attn_sparse_kernel,
                         cudaFuncAttributeMaxDynamicSharedMemorySize, A_SMEM);
    cudaFuncSetAttribute((const void*)attn_dense_kernel,
                         cudaFuncAttributeMaxDynamicSharedMemorySize, D_SMEM);

    dim3 gQKV(QKVD / 128, NTOK / 128);
    dim3 gO(Dm / 128, NTOK / 128);
    dim3 gF(FF / 128, NTOK / 128);
    dim3 gAttS(NB - 2, Hh, BB);
    dim3 gAttD(2, Hh, BB);
    dim3 gWS(Dm / 32, Dm / 32);

    wsplit3_kernel<<<dim3(Dm / 32, Dm / 32, 3), 256>>>(
        Wq, Wk, Wv, wh, bq, bk, bv, bqkv);
    wsplit_kernel<<<gWS, 256>>>(Wo, wh + 3 * (size_t)WSZ, Dm, Dm);
    wsplit_kernel<<<dim3(FF / 32, Dm / 32), 256>>>(W1, wh + 4 * (size_t)WSZ, Dm, FF);
    wsplit_kernel<<<dim3(Dm / 32, FF / 32), 256>>>(W2, wh + 4 * (size_t)WSZ + W1SZ, FF, Dm);
    embed_ln_kernel<<<NTOK, 256>>>(ids, emb_tok, emb_pos, lng, lnb, x, xh, xl);

    for (int l = 0; l < 2; l++) {
        size_t o = (size_t)l * OFFL;
        gemm_mma<0,0,1,1,12><<<gQKV, 256, SM_A2>>>(xh, xl, wh + o, bqkv + l * QKVD,
            nullptr, qkvh, qkvl, NTOK, QKVD);
        attn_sparse_kernel<<<gAttS, 128, A_SMEM>>>(qkvh, qkvl, rb, ch);
        attn_dense_kernel<<<gAttD, 256, D_SMEM>>>(qkvh, qkvl, ch);
        gemm_mma<0,1,0,0,12><<<gO, 256, SM_A1>>>(ch, nullptr, wh + o + 3 * WSZ,
            bo + l * Dm, tmp, nullptr, nullptr, NTOK, Dm);
        add_ln_kernel<<<NTOK, 256>>>(x, tmp, ln1g + l * Dm, ln1b + l * Dm, xh, xl);
        gemm_mma<1,0,2,0,12><<<gF, 256, SM_A1>>>(xh, nullptr, wh + o + 4 * WSZ,
            b1 + l * FF, nullptr, fh, nullptr, NTOK, FF);
        gemm_mma<0,1,0,0,48><<<gO, 256, SM_A1>>>(fh, nullptr, wh + o + 4 * WSZ + W1SZ,
            b2 + l * Dm, tmp, nullptr, nullptr, NTOK, Dm);
        add_ln_kernel<<<NTOK, 256>>>(x, tmp, ln2g + l * Dm, ln2b + l * Dm, xh, xl);

        if (l == 0) {
            size_t o1 = OFFL;
            wsplit3_kernel<<<dim3(Dm / 32, Dm / 32, 3), 256>>>(
                Wq + WSZ, Wk + WSZ, Wv + WSZ, wh + o1,
                bq + Dm, bk + Dm, bv + Dm, bqkv + QKVD);
            wsplit_kernel<<<gWS, 256>>>(Wo + WSZ, wh + o1 + 3 * (size_t)WSZ, Dm, Dm);
            wsplit_kernel<<<dim3(FF / 32, Dm / 32), 256>>>(W1 + W1SZ, wh + o1 + 4 * (size_t)WSZ, Dm, FF);
            wsplit_kernel<<<dim3(Dm / 32, FF / 32), 256>>>(W2 + W1SZ, wh + o1 + 4 * (size_t)WSZ + W1SZ, FF, Dm);
        }
    }

    pool1_kernel<<<dim3(32, BB), 256>>>(x, fcw, part);
    pool2_kernel<<<1, 32>>>(part, fcb, (float*)d_out);
}

// round 16
// speedup vs baseline: 2.2315x; 1.1083x over previous
#include <cuda_runtime.h>
#include <cuda_fp16.h>
#include <math.h>
#include <stdint.h>

// ---------------- problem constants ----------------
#define Dm   768
#define Hh   12
#define DHd  64
#define BLKS 64
#define NB   64
#define SEQ  4096
#define BB   2
#define NTOK (BB*SEQ)
#define RR   3
#define FF   3072
#define QKVD 2304

#define WSZ   589824
#define W1SZ  2359296
#define OFFL  (4*WSZ + 2*W1SZ)

// ---------------- scratch (device globals) ----------------
__device__ float g_x  [NTOK*Dm];
__device__ __half g_tmph[NTOK*Dm];
__device__ __half g_xh [NTOK*Dm];
__device__ __half g_xl [NTOK*Dm];
__device__ __half g_qkvh[NTOK*QKVD];
__device__ __half g_qkvl[NTOK*QKVD];
__device__ __half g_ch [NTOK*Dm];
__device__ __half g_fh [NTOK*FF];
__device__ __half g_wh [2*OFFL];
__device__ float g_bqkv[2*QKVD];
__device__ float g_part[64];

// ---------------- helpers ----------------
__device__ __forceinline__ float gelu_tanh(float x) {
    float x3 = x * x * x;
    return 0.5f * x * (1.f + tanhf(0.7978845608028654f * (x + 0.044715f * x3)));
}

__device__ __forceinline__ float blk_sum256(float v) {
    __shared__ float red[32];
    int lane = threadIdx.x & 31, wid = threadIdx.x >> 5;
    #pragma unroll
    for (int o = 16; o > 0; o >>= 1) v += __shfl_xor_sync(0xffffffffu, v, o);
    if (lane == 0) red[wid] = v;
    __syncthreads();
    if (wid == 0) {
        v = (lane < 8) ? red[lane] : 0.f;
        #pragma unroll
        for (int o = 4; o > 0; o >>= 1) v += __shfl_xor_sync(0xffffffffu, v, o);
        if (lane == 0) red[0] = v;
    }
    __syncthreads();
    float r = red[0];
    __syncthreads();
    return r;
}

__device__ __forceinline__ uint32_t s2u(const void* p) {
    uint32_t a;
    asm("{ .reg .u64 t; cvta.to.shared.u64 t, %1; cvt.u32.u64 %0, t; }" : "=r"(a) : "l"(p));
    return a;
}

#define LDSM4(r, a) \
    asm volatile("ldmatrix.sync.aligned.m8n8.x4.shared.b16 {%0,%1,%2,%3}, [%4];" \
        : "=r"((r)[0]), "=r"((r)[1]), "=r"((r)[2]), "=r"((r)[3]) : "r"(a))
#define LDSM2(r0, r1, a) \
    asm volatile("ldmatrix.sync.aligned.m8n8.x2.shared.b16 {%0,%1}, [%2];" \
        : "=r"(r0), "=r"(r1) : "r"(a))
#define LDSM2T(r0, r1, a) \
    asm volatile("ldmatrix.sync.aligned.m8n8.x2.trans.shared.b16 {%0,%1}, [%2];" \
        : "=r"(r0), "=r"(r1) : "r"(a))

#define CPA16(dst, src) \
    asm volatile("cp.async.cg.shared.global [%0], [%1], 16;" :: "r"(dst), "l"(src))
#define CP_COMMIT() asm volatile("cp.async.commit_group;" ::: "memory")
#define CP_WAIT(n)  asm volatile("cp.async.wait_group %0;" :: "n"(n) : "memory")

__device__ __forceinline__ void mma16816(float* c, const uint32_t* a,
                                         uint32_t b0, uint32_t b1) {
    asm volatile(
        "mma.sync.aligned.m16n8k16.row.col.f32.f16.f16.f32 "
        "{%0,%1,%2,%3}, {%4,%5,%6,%7}, {%8,%9}, {%0,%1,%2,%3};"
        : "+f"(c[0]), "+f"(c[1]), "+f"(c[2]), "+f"(c[3])
        : "r"(a[0]), "r"(a[1]), "r"(a[2]), "r"(a[3]), "r"(b0), "r"(b1));
}

__device__ __forceinline__ void split2h(float a, float b, uint32_t& hi, uint32_t& lo) {
    __half ha = __float2half_rn(a);
    __half hb = __float2half_rn(b);
    __half la = __float2half_rn(a - __half2float(ha));
    __half lb = __float2half_rn(b - __half2float(hb));
    hi = (uint32_t)__half_as_ushort(ha) | ((uint32_t)__half_as_ushort(hb) << 16);
    lo = (uint32_t)__half_as_ushort(la) | ((uint32_t)__half_as_ushort(lb) << 16);
}

__device__ __forceinline__ uint32_t pack2h(float a, float b) {
    __half2 h = __floats2half2_rn(a, b);
    return *(uint32_t*)&h;
}

// ---------------- weight transpose + fp16 convert ----------------
__global__ void __launch_bounds__(256) wsplit_kernel(
    const float* __restrict__ W, __half* __restrict__ hi, int K, int N)
{
    __shared__ float t[32][33];
    int n0 = blockIdx.x * 32, k0 = blockIdx.y * 32;
    int tx = threadIdx.x & 31, ty = threadIdx.x >> 5;
    #pragma unroll
    for (int j = 0; j < 4; j++)
        t[ty + j * 8][tx] = W[(size_t)(k0 + ty + j * 8) * N + n0 + tx];
    __syncthreads();
    #pragma unroll
    for (int j = 0; j < 4; j++) {
        int n = n0 + ty + j * 8, k = k0 + tx;
        hi[(size_t)n * K + k] = __float2half_rn(t[tx][ty + j * 8]);
    }
}

__global__ void __launch_bounds__(256) wsplit3_kernel(
    const float* __restrict__ Wa, const float* __restrict__ Wb,
    const float* __restrict__ Wc, __half* __restrict__ hi,
    const float* __restrict__ ba, const float* __restrict__ bb,
    const float* __restrict__ bc, float* __restrict__ bqkv)
{
    __shared__ float t[32][33];
    int z = blockIdx.z;
    const float* W = (z == 0) ? Wa : (z == 1) ? Wb : Wc;
    __half* hz = hi + (size_t)z * WSZ;
    int n0 = blockIdx.x * 32, k0 = blockIdx.y * 32;
    int tx = threadIdx.x & 31, ty = threadIdx.x >> 5;
    if (blockIdx.x == 0 && blockIdx.y == 0) {
        const float* bz = (z == 0) ? ba : (z == 1) ? bb : bc;
        for (int i = threadIdx.x; i < Dm; i += 256) bqkv[z * Dm + i] = bz[i];
    }
    #pragma unroll
    for (int j = 0; j < 4; j++)
        t[ty + j * 8][tx] = W[(size_t)(k0 + ty + j * 8) * Dm + n0 + tx];
    __syncthreads();
    #pragma unroll
    for (int j = 0; j < 4; j++) {
        int n = n0 + ty + j * 8, k = k0 + tx;
        hz[(size_t)n * Dm + k] = __float2half_rn(t[tx][ty + j * 8]);
    }
}

// ---------------- cp.async warp-MMA GEMM (BK=64, x4 B-loads, 1 barrier/chunk) ----------------
// AT2=1: A = hi+lo fp16 (2 MMA terms); AT2=0: A = hi only (1 term).
// WSPL: 0=none, 1=write Chi+Clo (split), 2=write Chi only (fp16 rn).
#define RS64  144
#define TL64  (128*RS64)        // 18432

template<int GELU, int WF32, int WSPL, int AT2, int KC>
__global__ void __launch_bounds__(256, 2) gemm_mma(
    const __half* __restrict__ Ahi, const __half* __restrict__ Alo,
    const __half* __restrict__ Bh,
    const float* __restrict__ bias, float* __restrict__ C,
    __half* __restrict__ Chi, __half* __restrict__ Clo,
    int M, int N)
{
    const int K = KC * 64;
    const int STG  = (AT2 ? 3 : 2) * TL64;
    const int BOFF = (AT2 ? 2 : 1) * TL64;
    extern __shared__ char sm[];
    uint32_t sbase = s2u(sm);
    int tid = threadIdx.x, lane = tid & 31, wid = tid >> 5;
    int m0 = blockIdx.y * 128, n0 = blockIdx.x * 128;
    int wm = (wid & 3) * 32, wn = (wid >> 2) * 64;

    int lr = tid & 127, lh = tid >> 7;
    const __half* ah_p = Ahi + (size_t)(m0 + lr) * K + lh * 32;
    const __half* al_p = AT2 ? (Alo + (size_t)(m0 + lr) * K + lh * 32) : nullptr;
    const __half* bh_p = Bh  + (size_t)(n0 + lr) * K + lh * 32;
    uint32_t woff = (uint32_t)lr * RS64 + (uint32_t)lh * 64;

    float acc[2][8][4];
    #pragma unroll
    for (int i = 0; i < 2; i++)
        #pragma unroll
        for (int j = 0; j < 8; j++)
            #pragma unroll
            for (int t = 0; t < 4; t++) acc[i][j][t] = 0.f;

    {   // prologue: issue chunk 0
        uint32_t d = sbase + woff;
        #pragma unroll
        for (int q = 0; q < 4; q++) CPA16(d + q * 16, ah_p + q * 8);
        if (AT2) {
            #pragma unroll
            for (int q = 0; q < 4; q++) CPA16(d + TL64 + q * 16, al_p + q * 8);
        }
        #pragma unroll
        for (int q = 0; q < 4; q++) CPA16(d + BOFF + q * 16, bh_p + q * 8);
        CP_COMMIT();
    }

    int r16 = lane & 15, c16 = lane >> 4;
    uint32_t brow = (uint32_t)(wn + (lane & 7) + ((lane >> 4) & 1) * 8);
    uint32_t bcol16 = ((lane >> 3) & 1) * 16;

    for (int c = 0; c < KC; c++) {
        CP_WAIT(0);
        __syncthreads();
        if (c + 1 < KC) {
            uint32_t d = sbase + ((c + 1) & 1) * STG + woff;
            int off = (c + 1) * 64;
            #pragma unroll
            for (int q = 0; q < 4; q++) CPA16(d + q * 16, ah_p + off + q * 8);
            if (AT2) {
                #pragma unroll
                for (int q = 0; q < 4; q++) CPA16(d + TL64 + q * 16, al_p + off + q * 8);
            }
            #pragma unroll
            for (int q = 0; q < 4; q++) CPA16(d + BOFF + q * 16, bh_p + off + q * 8);
            CP_COMMIT();
        }
        {
            uint32_t base = sbase + (c & 1) * STG;
            #pragma unroll
            for (int ks = 0; ks < 4; ks++) {
                uint32_t ah[2][4], al[2][4];
                #pragma unroll
                for (int mi = 0; mi < 2; mi++) {
                    uint32_t rel = (uint32_t)(wm + mi * 16 + r16) * RS64
                                 + ks * 32 + c16 * 16;
                    LDSM4(ah[mi], base + rel);
                    if (AT2) LDSM4(al[mi], base + TL64 + rel);
                }
                #pragma unroll
                for (int nip = 0; nip < 4; nip++) {
                    uint32_t bb[4];
                    uint32_t rel = (brow + nip * 16) * RS64 + ks * 32 + bcol16;
                    LDSM4(bb, base + BOFF + rel);
                    #pragma unroll
                    for (int mi = 0; mi < 2; mi++) {
                        mma16816(acc[mi][2 * nip],     ah[mi], bb[0], bb[1]);
                        mma16816(acc[mi][2 * nip + 1], ah[mi], bb[2], bb[3]);
                        if (AT2) {
                            mma16816(acc[mi][2 * nip],     al[mi], bb[0], bb[1]);
                            mma16816(acc[mi][2 * nip + 1], al[mi], bb[2], bb[3]);
                        }
                    }
                }
            }
        }
    }

    int g = lane >> 2, t4 = lane & 3;
    #pragma unroll
    for (int mi = 0; mi < 2; mi++) {
        int row0 = m0 + wm + mi * 16 + g;
        #pragma unroll
        for (int ni = 0; ni < 8; ni++) {
            int col = n0 + wn + ni * 8 + 2 * t4;
            float2 bi = *(const float2*)(bias + col);
            float2 o0, o1;
            o0.x = acc[mi][ni][0] + bi.x;
            o0.y = acc[mi][ni][1] + bi.y;
            o1.x = acc[mi][ni][2] + bi.x;
            o1.y = acc[mi][ni][3] + bi.y;
            if (GELU) {
                o0.x = gelu_tanh(o0.x); o0.y = gelu_tanh(o0.y);
                o1.x = gelu_tanh(o1.x); o1.y = gelu_tanh(o1.y);
            }
            size_t i0 = (size_t)row0 * N + col;
            size_t i1 = (size_t)(row0 + 8) * N + col;
            if (WF32) {
                *(float2*)(C + i0) = o0;
                *(float2*)(C + i1) = o1;
            }
            if (WSPL == 1) {
                uint32_t h0, l0, h1, l1;
                split2h(o0.x, o0.y, h0, l0);
                split2h(o1.x, o1.y, h1, l1);
                *(uint32_t*)(Chi + i0) = h0;
                *(uint32_t*)(Clo + i0) = l0;
                *(uint32_t*)(Chi + i1) = h1;
                *(uint32_t*)(Clo + i1) = l1;
            }
            if (WSPL == 2) {
                *(uint32_t*)(Chi + i0) = pack2h(o0.x, o0.y);
                *(uint32_t*)(Chi + i1) = pack2h(o1.x, o1.y);
            }
        }
    }
}

// ---------------- embedding + LN ----------------
__global__ void __launch_bounds__(256) embed_ln_kernel(
    const int* __restrict__ ids, const float* __restrict__ tok,
    const float* __restrict__ pos, const float* __restrict__ g,
    const float* __restrict__ b, float* __restrict__ x,
    __half* __restrict__ xh, __half* __restrict__ xl)
{
    int t = blockIdx.x, s = t & (SEQ - 1), id = ids[t];
    float val[3];
    #pragma unroll
    for (int j = 0; j < 3; j++) {
        int i = threadIdx.x + j * 256;
        val[j] = tok[(size_t)id * Dm + i] + pos[(size_t)s * Dm + i];
    }
    float mean = blk_sum256(val[0] + val[1] + val[2]) * (1.f / 768.f);
    float sq = 0.f;
    #pragma unroll
    for (int j = 0; j < 3; j++) { float d = val[j] - mean; sq += d * d; }
    float rstd = rsqrtf(blk_sum256(sq) * (1.f / 768.f) + 1e-12f);
    #pragma unroll
    for (int j = 0; j < 3; j++) {
        int i = threadIdx.x + j * 256;
        float o = (val[j] - mean) * rstd * g[i] + b[i];
        size_t idx = (size_t)t * Dm + i;
        x[idx] = o;
        __half h = __float2half_rn(o);
        xh[idx] = h;
        xl[idx] = __float2half_rn(o - __half2float(h));
    }
}

// ---------------- residual add + LN (residual branch now fp16) ----------------
__global__ void __launch_bounds__(256) add_ln_kernel(
    float* __restrict__ x, const __half* __restrict__ y,
    const float* __restrict__ g, const float* __restrict__ b,
    __half* __restrict__ xh, __half* __restrict__ xl)
{
    size_t t = blockIdx.x;
    float* xp = x + t * Dm;
    const __half* yp = y + t * Dm;
    float val[3];
    #pragma unroll
    for (int j = 0; j < 3; j++) {
        int i = threadIdx.x + j * 256;
        val[j] = xp[i] + __half2float(yp[i]);
    }
    float mean = blk_sum256(val[0] + val[1] + val[2]) * (1.f / 768.f);
    float sq = 0.f;
    #pragma unroll
    for (int j = 0; j < 3; j++) { float d = val[j] - mean; sq += d * d; }
    float rstd = rsqrtf(blk_sum256(sq) * (1.f / 768.f) + 1e-12f);
    #pragma unroll
    for (int j = 0; j < 3; j++) {
        int i = threadIdx.x + j * 256;
        float o = (val[j] - mean) * rstd * g[i] + b[i];
        xp[i] = o;
        __half h = __float2half_rn(o);
        xh[t * Dm + i] = h;
        xl[t * Dm + i] = __float2half_rn(o - __half2float(h));
    }
}

// ================= attention (S 3-term, P*V 1-term) =================
#define ARS 144
#define A_QH 0
#define A_QL 9216
#define A_KH 18432
#define A_BLK 27648                   // KH + KL + VH
#define A_SMEM (18432 + A_BLK)        // 46080
#define D_G0  18432
#define D_SMEM (18432 + 2*A_BLK)      // 73728
#define D_MRG 18432

struct AttnState {
    float m0, m1, l0, l1;
    float co[8][4];
};

__device__ __forceinline__ void stage_kv(
    const __half* __restrict__ qkvh, const __half* __restrict__ qkvl,
    size_t kbase, uint32_t dk, uint32_t dkl, uint32_t dv)
{
    size_t vbase = kbase + Dm;
    CPA16(dk,      qkvh + kbase);      CPA16(dk + 16, qkvh + kbase + 8);
    CPA16(dk + 32, qkvh + kbase + 16); CPA16(dk + 48, qkvh + kbase + 24);
    CPA16(dkl,      qkvl + kbase);      CPA16(dkl + 16, qkvl + kbase + 8);
    CPA16(dkl + 32, qkvl + kbase + 16); CPA16(dkl + 48, qkvl + kbase + 24);
    CPA16(dv,      qkvh + vbase);      CPA16(dv + 16, qkvh + vbase + 8);
    CPA16(dv + 32, qkvh + vbase + 16); CPA16(dv + 48, qkvh + vbase + 24);
    CP_COMMIT(); CP_WAIT(0);
}

__device__ __forceinline__ void attn_block(
    AttnState& st, const uint32_t qfh[4][4], const uint32_t qfl[4][4],
    uint32_t sbase, uint32_t offKH, int lane)
{
    const uint32_t dKL = 9216, dVH = 18432;
    uint32_t kb_h = sbase + offKH + (uint32_t)(lane & 7) * ARS + ((lane >> 3) & 1) * 16;
    float sc[8][4];
    #pragma unroll
    for (int ni = 0; ni < 8; ni++)
        #pragma unroll
        for (int t = 0; t < 4; t++) sc[ni][t] = 0.f;
    #pragma unroll
    for (int ni = 0; ni < 8; ni++) {
        uint32_t ba_h = kb_h + (uint32_t)(ni * 8) * ARS;
        #pragma unroll
        for (int ks = 0; ks < 4; ks++) {
            uint32_t bh0, bh1, bl0, bl1;
            LDSM2(bh0, bh1, ba_h + ks * 32);
            LDSM2(bl0, bl1, ba_h + dKL + ks * 32);
            mma16816(sc[ni], qfh[ks], bh0, bh1);
            mma16816(sc[ni], qfh[ks], bl0, bl1);
            mma16816(sc[ni], qfl[ks], bh0, bh1);
        }
    }
    #pragma unroll
    for (int ni = 0; ni < 8; ni++) {
        sc[ni][0] *= 0.125f; sc[ni][1] *= 0.125f;
        sc[ni][2] *= 0.125f; sc[ni][3] *= 0.125f;
    }
    float bm0 = -1e30f, bm1 = -1e30f;
    #pragma unroll
    for (int ni = 0; ni < 8; ni++) {
        bm0 = fmaxf(bm0, fmaxf(sc[ni][0], sc[ni][1]));
        bm1 = fmaxf(bm1, fmaxf(sc[ni][2], sc[ni][3]));
    }
    bm0 = fmaxf(bm0, __shfl_xor_sync(0xffffffffu, bm0, 1));
    bm0 = fmaxf(bm0, __shfl_xor_sync(0xffffffffu, bm0, 2));
    bm1 = fmaxf(bm1, __shfl_xor_sync(0xffffffffu, bm1, 1));
    bm1 = fmaxf(bm1, __shfl_xor_sync(0xffffffffu, bm1, 2));
    float mn0 = fmaxf(st.m0, bm0), mn1 = fmaxf(st.m1, bm1);
    float corr0 = __expf(st.m0 - mn0), corr1 = __expf(st.m1 - mn1);
    st.m0 = mn0; st.m1 = mn1;
    #pragma unroll
    for (int nd = 0; nd < 8; nd++) {
        st.co[nd][0] *= corr0; st.co[nd][1] *= corr0;
        st.co[nd][2] *= corr1; st.co[nd][3] *= corr1;
    }
    float ls0 = 0.f, ls1 = 0.f;
    #pragma unroll
    for (int ni = 0; ni < 8; ni++) {
        sc[ni][0] = __expf(sc[ni][0] - mn0);
        sc[ni][1] = __expf(sc[ni][1] - mn0);
        sc[ni][2] = __expf(sc[ni][2] - mn1);
        sc[ni][3] = __expf(sc[ni][3] - mn1);
        ls0 += sc[ni][0] + sc[ni][1];
        ls1 += sc[ni][2] + sc[ni][3];
    }
    ls0 += __shfl_xor_sync(0xffffffffu, ls0, 1);
    ls0 += __shfl_xor_sync(0xffffffffu, ls0, 2);
    ls1 += __shfl_xor_sync(0xffffffffu, ls1, 1);
    ls1 += __shfl_xor_sync(0xffffffffu, ls1, 2);
    st.l0 = st.l0 * corr0 + ls0;
    st.l1 = st.l1 * corr1 + ls1;

    uint32_t pah[4][4];
    #pragma unroll
    for (int ksp = 0; ksp < 4; ksp++) {
        pah[ksp][0] = pack2h(sc[2*ksp][0],   sc[2*ksp][1]);
        pah[ksp][1] = pack2h(sc[2*ksp][2],   sc[2*ksp][3]);
        pah[ksp][2] = pack2h(sc[2*ksp+1][0], sc[2*ksp+1][1]);
        pah[ksp][3] = pack2h(sc[2*ksp+1][2], sc[2*ksp+1][3]);
    }
    #pragma unroll
    for (int nd = 0; nd < 8; nd++) {
        #pragma unroll
        for (int ksp = 0; ksp < 4; ksp++) {
            uint32_t va = sbase + offKH + dVH
                        + (uint32_t)(ksp * 16 + (lane & 15)) * ARS + nd * 16;
            uint32_t vh0, vh1;
            LDSM2T(vh0, vh1, va);
            mma16816(st.co[nd], pah[ksp], vh0, vh1);
        }
    }
}

__device__ __forceinline__ void load_q_frags(
    uint32_t sbase, int warp_q, int lane, uint32_t qfh[4][4], uint32_t qfl[4][4])
{
    uint32_t qa_h = sbase + A_QH + (uint32_t)(warp_q * 16 + (lane & 15)) * ARS + (lane >> 4) * 16;
    uint32_t qa_l = qa_h + (A_QL - A_QH);
    #pragma unroll
    for (int ks = 0; ks < 4; ks++) {
        LDSM4(qfh[ks], qa_h + ks * 32);
        LDSM4(qfl[ks], qa_l + ks * 32);
    }
}

__device__ __forceinline__ void stage_q(
    const __half* __restrict__ qkvh, const __half* __restrict__ qkvl,
    uint32_t sbase, int b, int qb, int h, int srow, int shalf)
{
    size_t off = ((size_t)(b * SEQ + qb * BLKS + srow)) * QKVD + h * DHd + shalf * 32;
    uint32_t dh = sbase + A_QH + (uint32_t)srow * ARS + shalf * 64;
    uint32_t dl = sbase + A_QL + (uint32_t)srow * ARS + shalf * 64;
    CPA16(dh,      qkvh + off);      CPA16(dh + 16, qkvh + off + 8);
    CPA16(dh + 32, qkvh + off + 16); CPA16(dh + 48, qkvh + off + 24);
    CPA16(dl,      qkvl + off);      CPA16(dl + 16, qkvl + off + 8);
    CPA16(dl + 32, qkvl + off + 16); CPA16(dl + 48, qkvl + off + 24);
    CP_COMMIT(); CP_WAIT(0);
}

// ---------------- sparse attention ----------------
__global__ void __launch_bounds__(128) attn_sparse_kernel(
    const __half* __restrict__ qkvh, const __half* __restrict__ qkvl,
    const int* __restrict__ rb, __half* __restrict__ ch_g)
{
    extern __shared__ char sb[];
    uint32_t sbase = s2u(sb);
    int b = blockIdx.z, h = blockIdx.y, qb = blockIdx.x + 1;
    int tid = threadIdx.x, lane = tid & 31, w = tid >> 5;
    int srow = tid >> 1, shalf = tid & 1;

    stage_q(qkvh, qkvl, sbase, b, qb, h, srow, shalf);
    __syncthreads();

    uint32_t qfh[4][4], qfl[4][4];
    load_q_frags(sbase, w, lane, qfh, qfl);

    AttnState st;
    st.m0 = st.m1 = -1e30f; st.l0 = st.l1 = 0.f;
    #pragma unroll
    for (int nd = 0; nd < 8; nd++)
        #pragma unroll
        for (int t = 0; t < 4; t++) st.co[nd][t] = 0.f;

    int blist[8];
    blist[0] = 0; blist[1] = qb - 1; blist[2] = qb; blist[3] = qb + 1;
    blist[4] = NB - 1;
    const int* rp = rb + (h * NB + qb) * RR;
    blist[5] = rp[0]; blist[6] = rp[1]; blist[7] = rp[2];

    uint32_t dk  = sbase + A_KH + (uint32_t)srow * ARS + shalf * 64;
    uint32_t dkl = dk + 9216, dv = dk + 18432;

    for (int jb = 0; jb < 8; jb++) {
        int kb = blist[jb];
        size_t kbase = ((size_t)(b * SEQ + kb * BLKS + srow)) * QKVD + Dm + h * DHd + shalf * 32;
        __syncthreads();
        stage_kv(qkvh, qkvl, kbase, dk, dkl, dv);
        __syncthreads();
        attn_block(st, qfh, qfl, sbase, A_KH, lane);
    }

    float inv0 = 1.f / st.l0, inv1 = 1.f / st.l1;
    int g = lane >> 2, t4 = lane & 3;
    size_t rbase = ((size_t)(b * SEQ + qb * BLKS + w * 16 + g)) * Dm + h * DHd;
    #pragma unroll
    for (int nd = 0; nd < 8; nd++) {
        int col = nd * 8 + 2 * t4;
        *(uint32_t*)(ch_g + rbase + col) =
            pack2h(st.co[nd][0] * inv0, st.co[nd][1] * inv0);
        *(uint32_t*)(ch_g + rbase + 8 * Dm + col) =
            pack2h(st.co[nd][2] * inv1, st.co[nd][3] * inv1);
    }
}

// ---------------- dense attention (query blocks 0, NB-1) ----------------
__global__ void __launch_bounds__(256) attn_dense_kernel(
    const __half* __restrict__ qkvh, const __half* __restrict__ qkvl,
    __half* __restrict__ ch_g)
{
    extern __shared__ char sb[];
    uint32_t sbase = s2u(sb);
    int b = blockIdx.z, h = blockIdx.y;
    int qb = (blockIdx.x == 0) ? 0 : NB - 1;
    int tid = threadIdx.x, lane = tid & 31;
    int grp = tid >> 7, ltid = tid & 127, w = ltid >> 5;
    int srow = ltid >> 1, shalf = ltid & 1;

    if (grp == 0) stage_q(qkvh, qkvl, sbase, b, qb, h, srow, shalf);
    __syncthreads();

    uint32_t qfh[4][4], qfl[4][4];
    load_q_frags(sbase, w, lane, qfh, qfl);

    AttnState st;
    st.m0 = st.m1 = -1e30f; st.l0 = st.l1 = 0.f;
    #pragma unroll
    for (int nd = 0; nd < 8; nd++)
        #pragma unroll
        for (int t = 0; t < 4; t++) st.co[nd][t] = 0.f;

    uint32_t gbase = D_G0 + grp * A_BLK;
    uint32_t dk  = sbase + gbase + (uint32_t)srow * ARS + shalf * 64;
    uint32_t dkl = dk + 9216, dv = dk + 18432;

    for (int jb = 0; jb < 32; jb++) {
        int kb = grp * 32 + jb;
        size_t kbase = ((size_t)(b * SEQ + kb * BLKS + srow)) * QKVD + Dm + h * DHd + shalf * 32;
        __syncthreads();
        stage_kv(qkvh, qkvl, kbase, dk, dkl, dv);
        __syncthreads();
        attn_block(st, qfh, qfl, sbase, gbase, lane);
    }

    __syncthreads();
    float* mg = (float*)(sb + D_MRG);
    int slot = (w * 32 + lane) * 36;
    if (grp == 1) {
        #pragma unroll
        for (int nd = 0; nd < 8; nd++)
            #pragma unroll
            for (int t = 0; t < 4; t++) mg[slot + nd * 4 + t] = st.co[nd][t];
        mg[slot + 32] = st.m0; mg[slot + 33] = st.m1;
        mg[slot + 34] = st.l0; mg[slot + 35] = st.l1;
    }
    __syncthreads();
    if (grp == 0) {
        float mB0 = mg[slot + 32], mB1 = mg[slot + 33];
        float lB0 = mg[slot + 34], lB1 = mg[slot + 35];
        float M0 = fmaxf(st.m0, mB0), M1 = fmaxf(st.m1, mB1);
        float cA0 = __expf(st.m0 - M0), cB0 = __expf(mB0 - M0);
        float cA1 = __expf(st.m1 - M1), cB1 = __expf(mB1 - M1);
        float L0 = st.l0 * cA0 + lB0 * cB0;
        float L1 = st.l1 * cA1 + lB1 * cB1;
        float inv0 = 1.f / L0, inv1 = 1.f / L1;
        int g = lane >> 2, t4 = lane & 3;
        size_t rbase = ((size_t)(b * SEQ + qb * BLKS + w * 16 + g)) * Dm + h * DHd;
        #pragma unroll
        for (int nd = 0; nd < 8; nd++) {
            float r0 = (st.co[nd][0] * cA0 + mg[slot + nd * 4 + 0] * cB0) * inv0;
            float r1 = (st.co[nd][1] * cA0 + mg[slot + nd * 4 + 1] * cB0) * inv0;
            float r2 = (st.co[nd][2] * cA1 + mg[slot + nd * 4 + 2] * cB1) * inv1;
            float r3 = (st.co[nd][3] * cA1 + mg[slot + nd * 4 + 3] * cB1) * inv1;
            int col = nd * 8 + 2 * t4;
            *(uint32_t*)(ch_g + rbase + col)          = pack2h(r0, r1);
            *(uint32_t*)(ch_g + rbase + 8 * Dm + col) = pack2h(r2, r3);
        }
    }
}

// ---------------- mean pool + linear head ----------------
__global__ void __launch_bounds__(256) pool1_kernel(
    const float* __restrict__ x, const float* __restrict__ w, float* __restrict__ part)
{
    int b = blockIdx.y, sl = blockIdx.x;
    const float* xb = x + ((size_t)b * SEQ + sl * 128) * Dm;
    __shared__ float ws[Dm];
    for (int i = threadIdx.x; i < Dm; i += 256) ws[i] = w[i];
    __syncthreads();
    float acc = 0.f;
    for (int r = 0; r < 128; r++) {
        const float* xr = xb + (size_t)r * Dm;
        for (int i = threadIdx.x; i < Dm; i += 256) acc += xr[i] * ws[i];
    }
    float t = blk_sum256(acc);
    if (threadIdx.x == 0) part[b * 32 + sl] = t;
}
__global__ void pool2_kernel(const float* __restrict__ part,
                             const float* __restrict__ fb, float* __restrict__ out)
{
    int b = threadIdx.x;
    if (b < BB) {
        float s = 0.f;
        for (int i = 0; i < 32; i++) s += part[b * 32 + i];
        out[b] = s * (1.f / (float)SEQ) + fb[0];
    }
}

// ---------------- driver ----------------
extern "C" void kernel_launch(void* const* d_in, const int* in_sizes, int n_in,
                              void* d_out, int out_size)
{
    const int*   ids     = (const int*)  d_in[0];
    const int*   rb      = (const int*)  d_in[1];
    const float* emb_tok = (const float*)d_in[2];
    const float* emb_pos = (const float*)d_in[3];
    const float* lng     = (const float*)d_in[4];
    const float* lnb     = (const float*)d_in[5];
    const float* Wq = (const float*)d_in[6];  const float* bq = (const float*)d_in[7];
    const float* Wk = (const float*)d_in[8];  const float* bk = (const float*)d_in[9];
    const float* Wv = (const float*)d_in[10]; const float* bv = (const float*)d_in[11];
    const float* Wo = (const float*)d_in[12]; const float* bo = (const float*)d_in[13];
    const float* ln1g = (const float*)d_in[14]; const float* ln1b = (const float*)d_in[15];
    const float* W1 = (const float*)d_in[16]; const float* b1 = (const float*)d_in[17];
    const float* W2 = (const float*)d_in[18]; const float* b2 = (const float*)d_in[19];
    const float* ln2g = (const float*)d_in[20]; const float* ln2b = (const float*)d_in[21];
    const float* fcw = (const float*)d_in[22]; const float* fcb = (const float*)d_in[23];

    float *x, *part, *bqkv;
    __half *tmph, *xh, *xl, *qkvh, *qkvl, *ch, *fh, *wh;
    cudaGetSymbolAddress((void**)&x,    g_x);
    cudaGetSymbolAddress((void**)&tmph, g_tmph);
    cudaGetSymbolAddress((void**)&xh,   g_xh);
    cudaGetSymbolAddress((void**)&xl,   g_xl);
    cudaGetSymbolAddress((void**)&qkvh, g_qkvh);
    cudaGetSymbolAddress((void**)&qkvl, g_qkvl);
    cudaGetSymbolAddress((void**)&ch,   g_ch);
    cudaGetSymbolAddress((void**)&fh,   g_fh);
    cudaGetSymbolAddress((void**)&wh,   g_wh);
    cudaGetSymbolAddress((void**)&bqkv, g_bqkv);
    cudaGetSymbolAddress((void**)&part, g_part);

    const int SM_A2 = 2 * 3 * TL64;
    const int SM_A1 = 2 * 2 * TL64;
    cudaFuncSetAttribute((const void*)gemm_mma<0,0,1,1,12>,
                         cudaFuncAttributeMaxDynamicSharedMemorySize, SM_A2);
    cudaFuncSetAttribute((const void*)gemm_mma<0,0,2,0,12>,
                         cudaFuncAttributeMaxDynamicSharedMemorySize, SM_A1);
    cudaFuncSetAttribute((const void*)gemm_mma<1,0,2,0,12>,
                         cudaFuncAttributeMaxDynamicSharedMemorySize, SM_A1);
    cudaFuncSetAttribute((const void*)gemm_mma<0,0,2,0,48>,
                         cudaFuncAttributeMaxDynamicSharedMemorySize, SM_A1);
    cudaFuncSetAttribute((const void*)attn_sparse_kernel,
                         cudaFuncAttributeMaxDynamicSharedMemorySize, A_SMEM);
    cudaFuncSetAttribute((const void*)attn_dense_kernel,
                         cudaFuncAttributeMaxDynamicSharedMemorySize, D_SMEM);

    dim3 gQKV(QKVD / 128, NTOK / 128);
    dim3 gO(Dm / 128, NTOK / 128);
    dim3 gF(FF / 128, NTOK / 128);
    dim3 gAttS(NB - 2, Hh, BB);
    dim3 gAttD(2, Hh, BB);
    dim3 gWS(Dm / 32, Dm / 32);

    wsplit3_kernel<<<dim3(Dm / 32, Dm / 32, 3), 256>>>(
        Wq, Wk, Wv, wh, bq, bk, bv, bqkv);
    wsplit_kernel<<<gWS, 256>>>(Wo, wh + 3 * (size_t)WSZ, Dm, Dm);
    wsplit_kernel<<<dim3(FF / 32, Dm / 32), 256>>>(W1, wh + 4 * (size_t)WSZ, Dm, FF);
    wsplit_kernel<<<dim3(Dm / 32, FF / 32), 256>>>(W2, wh + 4 * (size_t)WSZ + W1SZ, FF, Dm);
    embed_ln_kernel<<<NTOK, 256>>>(ids, emb_tok, emb_pos, lng, lnb, x, xh, xl);

    for (int l = 0; l < 2; l++) {
        size_t o = (size_t)l * OFFL;
        gemm_mma<0,0,1,1,12><<<gQKV, 256, SM_A2>>>(xh, xl, wh + o, bqkv + l * QKVD,
            nullptr, qkvh, qkvl, NTOK, QKVD);
        attn_sparse_kernel<<<gAttS, 128, A_SMEM>>>(qkvh, qkvl, rb, ch);
        attn_dense_kernel<<<gAttD, 256, D_SMEM>>>(qkvh, qkvl, ch);
        gemm_mma<0,0,2,0,12><<<gO, 256, SM_A1>>>(ch, nullptr, wh + o + 3 * WSZ,
            bo + l * Dm, nullptr, tmph, nullptr, NTOK, Dm);
        add_ln_kernel<<<NTOK, 256>>>(x, tmph, ln1g + l * Dm, ln1b + l * Dm, xh, xl);
        gemm_mma<1,0,2,0,12><<<gF, 256, SM_A1>>>(xh, nullptr, wh + o + 4 * WSZ,
            b1 + l * FF, nullptr, fh, nullptr, NTOK, FF);
        gemm_mma<0,0,2,0,48><<<gO, 256, SM_A1>>>(fh, nullptr, wh + o + 4 * WSZ + W1SZ,
            b2 + l * Dm, nullptr, tmph, nullptr, NTOK, Dm);
        add_ln_kernel<<<NTOK, 256>>>(x, tmph, ln2g + l * Dm, ln2b + l * Dm, xh, xl);

        if (l == 0) {
            size_t o1 = OFFL;
            wsplit3_kernel<<<dim3(Dm / 32, Dm / 32, 3), 256>>>(
                Wq + WSZ, Wk + WSZ, Wv + WSZ, wh + o1,
                bq + Dm, bk + Dm, bv + Dm, bqkv + QKVD);
            wsplit_kernel<<<gWS, 256>>>(Wo + WSZ, wh + o1 + 3 * (size_t)WSZ, Dm, Dm);
            wsplit_kernel<<<dim3(FF / 32, Dm / 32), 256>>>(W1 + W1SZ, wh + o1 + 4 * (size_t)WSZ, Dm, FF);
            wsplit_kernel<<<dim3(Dm / 32, FF / 32), 256>>>(W2 + W1SZ, wh + o1 + 4 * (size_t)WSZ + W1SZ, FF, Dm);
        }
    }

    pool1_kernel<<<dim3(32, BB), 256>>>(x, fcw, part);
    pool2_kernel<<<1, 32>>>(part, fcb, (float*)d_out);
}

// round 17
// speedup vs baseline: 2.6714x; 1.1971x over previous
#include <cuda_runtime.h>
#include <cuda_fp16.h>
#include <math.h>
#include <stdint.h>

// ---------------- problem constants ----------------
#define Dm   768
#define Hh   12
#define DHd  64
#define BLKS 64
#define NB   64
#define SEQ  4096
#define BB   2
#define NTOK (BB*SEQ)
#define RR   3
#define FF   3072
#define QKVD 2304

#define WSZ   589824
#define W1SZ  2359296
#define OFFL  (4*WSZ + 2*W1SZ)

// ---------------- scratch (device globals) ----------------
__device__ __half g_tmph[NTOK*Dm];
__device__ __half g_xh [NTOK*Dm];
__device__ __half g_xl [NTOK*Dm];
__device__ __half g_qkvh[NTOK*QKVD];
__device__ __half g_ch [NTOK*Dm];
__device__ __half g_fh [NTOK*FF];
__device__ __half g_wh [2*OFFL];
__device__ float g_bqkv[2*QKVD];
__device__ float g_part[64];

// ---------------- helpers ----------------
__device__ __forceinline__ float gelu_tanh(float x) {
    float x3 = x * x * x;
    return 0.5f * x * (1.f + tanhf(0.7978845608028654f * (x + 0.044715f * x3)));
}

__device__ __forceinline__ float blk_sum256(float v) {
    __shared__ float red[32];
    int lane = threadIdx.x & 31, wid = threadIdx.x >> 5;
    #pragma unroll
    for (int o = 16; o > 0; o >>= 1) v += __shfl_xor_sync(0xffffffffu, v, o);
    if (lane == 0) red[wid] = v;
    __syncthreads();
    if (wid == 0) {
        v = (lane < 8) ? red[lane] : 0.f;
        #pragma unroll
        for (int o = 4; o > 0; o >>= 1) v += __shfl_xor_sync(0xffffffffu, v, o);
        if (lane == 0) red[0] = v;
    }
    __syncthreads();
    float r = red[0];
    __syncthreads();
    return r;
}

__device__ __forceinline__ uint32_t s2u(const void* p) {
    uint32_t a;
    asm("{ .reg .u64 t; cvta.to.shared.u64 t, %1; cvt.u32.u64 %0, t; }" : "=r"(a) : "l"(p));
    return a;
}

#define LDSM4(r, a) \
    asm volatile("ldmatrix.sync.aligned.m8n8.x4.shared.b16 {%0,%1,%2,%3}, [%4];" \
        : "=r"((r)[0]), "=r"((r)[1]), "=r"((r)[2]), "=r"((r)[3]) : "r"(a))
#define LDSM2(r0, r1, a) \
    asm volatile("ldmatrix.sync.aligned.m8n8.x2.shared.b16 {%0,%1}, [%2];" \
        : "=r"(r0), "=r"(r1) : "r"(a))
#define LDSM2T(r0, r1, a) \
    asm volatile("ldmatrix.sync.aligned.m8n8.x2.trans.shared.b16 {%0,%1}, [%2];" \
        : "=r"(r0), "=r"(r1) : "r"(a))

#define CPA16(dst, src) \
    asm volatile("cp.async.cg.shared.global [%0], [%1], 16;" :: "r"(dst), "l"(src))
#define CP_COMMIT() asm volatile("cp.async.commit_group;" ::: "memory")
#define CP_WAIT(n)  asm volatile("cp.async.wait_group %0;" :: "n"(n) : "memory")

__device__ __forceinline__ void mma16816(float* c, const uint32_t* a,
                                         uint32_t b0, uint32_t b1) {
    asm volatile(
        "mma.sync.aligned.m16n8k16.row.col.f32.f16.f16.f32 "
        "{%0,%1,%2,%3}, {%4,%5,%6,%7}, {%8,%9}, {%0,%1,%2,%3};"
        : "+f"(c[0]), "+f"(c[1]), "+f"(c[2]), "+f"(c[3])
        : "r"(a[0]), "r"(a[1]), "r"(a[2]), "r"(a[3]), "r"(b0), "r"(b1));
}

__device__ __forceinline__ void split2h(float a, float b, uint32_t& hi, uint32_t& lo) {
    __half ha = __float2half_rn(a);
    __half hb = __float2half_rn(b);
    __half la = __float2half_rn(a - __half2float(ha));
    __half lb = __float2half_rn(b - __half2float(hb));
    hi = (uint32_t)__half_as_ushort(ha) | ((uint32_t)__half_as_ushort(hb) << 16);
    lo = (uint32_t)__half_as_ushort(la) | ((uint32_t)__half_as_ushort(lb) << 16);
}

__device__ __forceinline__ uint32_t pack2h(float a, float b) {
    __half2 h = __floats2half2_rn(a, b);
    return *(uint32_t*)&h;
}

// ---------------- weight transpose + fp16 convert ----------------
__global__ void __launch_bounds__(256) wsplit_kernel(
    const float* __restrict__ W, __half* __restrict__ hi, int K, int N)
{
    __shared__ float t[32][33];
    int n0 = blockIdx.x * 32, k0 = blockIdx.y * 32;
    int tx = threadIdx.x & 31, ty = threadIdx.x >> 5;
    #pragma unroll
    for (int j = 0; j < 4; j++)
        t[ty + j * 8][tx] = W[(size_t)(k0 + ty + j * 8) * N + n0 + tx];
    __syncthreads();
    #pragma unroll
    for (int j = 0; j < 4; j++) {
        int n = n0 + ty + j * 8, k = k0 + tx;
        hi[(size_t)n * K + k] = __float2half_rn(t[tx][ty + j * 8]);
    }
}

__global__ void __launch_bounds__(256) wsplit3_kernel(
    const float* __restrict__ Wa, const float* __restrict__ Wb,
    const float* __restrict__ Wc, __half* __restrict__ hi,
    const float* __restrict__ ba, const float* __restrict__ bb,
    const float* __restrict__ bc, float* __restrict__ bqkv)
{
    __shared__ float t[32][33];
    int z = blockIdx.z;
    const float* W = (z == 0) ? Wa : (z == 1) ? Wb : Wc;
    __half* hz = hi + (size_t)z * WSZ;
    int n0 = blockIdx.x * 32, k0 = blockIdx.y * 32;
    int tx = threadIdx.x & 31, ty = threadIdx.x >> 5;
    if (blockIdx.x == 0 && blockIdx.y == 0) {
        const float* bz = (z == 0) ? ba : (z == 1) ? bb : bc;
        for (int i = threadIdx.x; i < Dm; i += 256) bqkv[z * Dm + i] = bz[i];
    }
    #pragma unroll
    for (int j = 0; j < 4; j++)
        t[ty + j * 8][tx] = W[(size_t)(k0 + ty + j * 8) * Dm + n0 + tx];
    __syncthreads();
    #pragma unroll
    for (int j = 0; j < 4; j++) {
        int n = n0 + ty + j * 8, k = k0 + tx;
        hz[(size_t)n * Dm + k] = __float2half_rn(t[tx][ty + j * 8]);
    }
}

// ---------------- cp.async warp-MMA GEMM (BK=64, x4 B-loads, 1 barrier/chunk) ----------------
// AT2=1: A = hi+lo fp16 (2 MMA terms); AT2=0: A = hi only (1 term).
// WSPL: 0=none, 1=write Chi+Clo (split), 2=write Chi only (fp16 rn).
#define RS64  144
#define TL64  (128*RS64)        // 18432

template<int GELU, int WF32, int WSPL, int AT2, int KC>
__global__ void __launch_bounds__(256, 2) gemm_mma(
    const __half* __restrict__ Ahi, const __half* __restrict__ Alo,
    const __half* __restrict__ Bh,
    const float* __restrict__ bias, float* __restrict__ C,
    __half* __restrict__ Chi, __half* __restrict__ Clo,
    int M, int N)
{
    const int K = KC * 64;
    const int STG  = (AT2 ? 3 : 2) * TL64;
    const int BOFF = (AT2 ? 2 : 1) * TL64;
    extern __shared__ char sm[];
    uint32_t sbase = s2u(sm);
    int tid = threadIdx.x, lane = tid & 31, wid = tid >> 5;
    int m0 = blockIdx.y * 128, n0 = blockIdx.x * 128;
    int wm = (wid & 3) * 32, wn = (wid >> 2) * 64;

    int lr = tid & 127, lh = tid >> 7;
    const __half* ah_p = Ahi + (size_t)(m0 + lr) * K + lh * 32;
    const __half* al_p = AT2 ? (Alo + (size_t)(m0 + lr) * K + lh * 32) : nullptr;
    const __half* bh_p = Bh  + (size_t)(n0 + lr) * K + lh * 32;
    uint32_t woff = (uint32_t)lr * RS64 + (uint32_t)lh * 64;

    float acc[2][8][4];
    #pragma unroll
    for (int i = 0; i < 2; i++)
        #pragma unroll
        for (int j = 0; j < 8; j++)
            #pragma unroll
            for (int t = 0; t < 4; t++) acc[i][j][t] = 0.f;

    {   // prologue: issue chunk 0
        uint32_t d = sbase + woff;
        #pragma unroll
        for (int q = 0; q < 4; q++) CPA16(d + q * 16, ah_p + q * 8);
        if (AT2) {
            #pragma unroll
            for (int q = 0; q < 4; q++) CPA16(d + TL64 + q * 16, al_p + q * 8);
        }
        #pragma unroll
        for (int q = 0; q < 4; q++) CPA16(d + BOFF + q * 16, bh_p + q * 8);
        CP_COMMIT();
    }

    int r16 = lane & 15, c16 = lane >> 4;
    uint32_t brow = (uint32_t)(wn + (lane & 7) + ((lane >> 4) & 1) * 8);
    uint32_t bcol16 = ((lane >> 3) & 1) * 16;

    for (int c = 0; c < KC; c++) {
        CP_WAIT(0);
        __syncthreads();
        if (c + 1 < KC) {
            uint32_t d = sbase + ((c + 1) & 1) * STG + woff;
            int off = (c + 1) * 64;
            #pragma unroll
            for (int q = 0; q < 4; q++) CPA16(d + q * 16, ah_p + off + q * 8);
            if (AT2) {
                #pragma unroll
                for (int q = 0; q < 4; q++) CPA16(d + TL64 + q * 16, al_p + off + q * 8);
            }
            #pragma unroll
            for (int q = 0; q < 4; q++) CPA16(d + BOFF + q * 16, bh_p + off + q * 8);
            CP_COMMIT();
        }
        {
            uint32_t base = sbase + (c & 1) * STG;
            #pragma unroll
            for (int ks = 0; ks < 4; ks++) {
                uint32_t ah[2][4], al[2][4];
                #pragma unroll
                for (int mi = 0; mi < 2; mi++) {
                    uint32_t rel = (uint32_t)(wm + mi * 16 + r16) * RS64
                                 + ks * 32 + c16 * 16;
                    LDSM4(ah[mi], base + rel);
                    if (AT2) LDSM4(al[mi], base + TL64 + rel);
                }
                #pragma unroll
                for (int nip = 0; nip < 4; nip++) {
                    uint32_t bb[4];
                    uint32_t rel = (brow + nip * 16) * RS64 + ks * 32 + bcol16;
                    LDSM4(bb, base + BOFF + rel);
                    #pragma unroll
                    for (int mi = 0; mi < 2; mi++) {
                        mma16816(acc[mi][2 * nip],     ah[mi], bb[0], bb[1]);
                        mma16816(acc[mi][2 * nip + 1], ah[mi], bb[2], bb[3]);
                        if (AT2) {
                            mma16816(acc[mi][2 * nip],     al[mi], bb[0], bb[1]);
                            mma16816(acc[mi][2 * nip + 1], al[mi], bb[2], bb[3]);
                        }
                    }
                }
            }
        }
    }

    int g = lane >> 2, t4 = lane & 3;
    #pragma unroll
    for (int mi = 0; mi < 2; mi++) {
        int row0 = m0 + wm + mi * 16 + g;
        #pragma unroll
        for (int ni = 0; ni < 8; ni++) {
            int col = n0 + wn + ni * 8 + 2 * t4;
            float2 bi = *(const float2*)(bias + col);
            float2 o0, o1;
            o0.x = acc[mi][ni][0] + bi.x;
            o0.y = acc[mi][ni][1] + bi.y;
            o1.x = acc[mi][ni][2] + bi.x;
            o1.y = acc[mi][ni][3] + bi.y;
            if (GELU) {
                o0.x = gelu_tanh(o0.x); o0.y = gelu_tanh(o0.y);
                o1.x = gelu_tanh(o1.x); o1.y = gelu_tanh(o1.y);
            }
            size_t i0 = (size_t)row0 * N + col;
            size_t i1 = (size_t)(row0 + 8) * N + col;
            if (WF32) {
                *(float2*)(C + i0) = o0;
                *(float2*)(C + i1) = o1;
            }
            if (WSPL == 1) {
                uint32_t h0, l0, h1, l1;
                split2h(o0.x, o0.y, h0, l0);
                split2h(o1.x, o1.y, h1, l1);
                *(uint32_t*)(Chi + i0) = h0;
                *(uint32_t*)(Clo + i0) = l0;
                *(uint32_t*)(Chi + i1) = h1;
                *(uint32_t*)(Clo + i1) = l1;
            }
            if (WSPL == 2) {
                *(uint32_t*)(Chi + i0) = pack2h(o0.x, o0.y);
                *(uint32_t*)(Chi + i1) = pack2h(o1.x, o1.y);
            }
        }
    }
}

// ---------------- embedding + LN (x carried as hi+lo only) ----------------
__global__ void __launch_bounds__(256) embed_ln_kernel(
    const int* __restrict__ ids, const float* __restrict__ tok,
    const float* __restrict__ pos, const float* __restrict__ g,
    const float* __restrict__ b,
    __half* __restrict__ xh, __half* __restrict__ xl)
{
    int t = blockIdx.x, s = t & (SEQ - 1), id = ids[t];
    float val[3];
    #pragma unroll
    for (int j = 0; j < 3; j++) {
        int i = threadIdx.x + j * 256;
        val[j] = tok[(size_t)id * Dm + i] + pos[(size_t)s * Dm + i];
    }
    float mean = blk_sum256(val[0] + val[1] + val[2]) * (1.f / 768.f);
    float sq = 0.f;
    #pragma unroll
    for (int j = 0; j < 3; j++) { float d = val[j] - mean; sq += d * d; }
    float rstd = rsqrtf(blk_sum256(sq) * (1.f / 768.f) + 1e-12f);
    #pragma unroll
    for (int j = 0; j < 3; j++) {
        int i = threadIdx.x + j * 256;
        float o = (val[j] - mean) * rstd * g[i] + b[i];
        size_t idx = (size_t)t * Dm + i;
        __half h = __float2half_rn(o);
        xh[idx] = h;
        xl[idx] = __float2half_rn(o - __half2float(h));
    }
}

// ---------------- residual add + LN (x = hi+lo; branch fp16) ----------------
__global__ void __launch_bounds__(256) add_ln_kernel(
    __half* __restrict__ xh, __half* __restrict__ xl,
    const __half* __restrict__ y,
    const float* __restrict__ g, const float* __restrict__ b)
{
    size_t t = blockIdx.x;
    const __half* yp = y + t * Dm;
    float val[3];
    #pragma unroll
    for (int j = 0; j < 3; j++) {
        int i = threadIdx.x + j * 256;
        size_t idx = t * Dm + i;
        val[j] = __half2float(xh[idx]) + __half2float(xl[idx]) + __half2float(yp[i]);
    }
    float mean = blk_sum256(val[0] + val[1] + val[2]) * (1.f / 768.f);
    float sq = 0.f;
    #pragma unroll
    for (int j = 0; j < 3; j++) { float d = val[j] - mean; sq += d * d; }
    float rstd = rsqrtf(blk_sum256(sq) * (1.f / 768.f) + 1e-12f);
    #pragma unroll
    for (int j = 0; j < 3; j++) {
        int i = threadIdx.x + j * 256;
        float o = (val[j] - mean) * rstd * g[i] + b[i];
        size_t idx = t * Dm + i;
        __half h = __float2half_rn(o);
        xh[idx] = h;
        xl[idx] = __float2half_rn(o - __half2float(h));
    }
}

// ================= attention (all 1-term fp16) =================
#define ARS 144
#define A_QH 0
#define A_KH 9216
#define A_BLK 18432                   // KH + VH
#define A_SMEM (9216 + A_BLK)         // 27648
#define D_G0  9216
#define D_SMEM (9216 + 2*A_BLK)       // 46080
#define D_MRG 9216

struct AttnState {
    float m0, m1, l0, l1;
    float co[8][4];
};

__device__ __forceinline__ void stage_kv(
    const __half* __restrict__ qkvh,
    size_t kbase, uint32_t dk, uint32_t dv)
{
    size_t vbase = kbase + Dm;
    CPA16(dk,      qkvh + kbase);      CPA16(dk + 16, qkvh + kbase + 8);
    CPA16(dk + 32, qkvh + kbase + 16); CPA16(dk + 48, qkvh + kbase + 24);
    CPA16(dv,      qkvh + vbase);      CPA16(dv + 16, qkvh + vbase + 8);
    CPA16(dv + 32, qkvh + vbase + 16); CPA16(dv + 48, qkvh + vbase + 24);
    CP_COMMIT(); CP_WAIT(0);
}

__device__ __forceinline__ void attn_block(
    AttnState& st, const uint32_t qfh[4][4],
    uint32_t sbase, uint32_t offKH, int lane)
{
    const uint32_t dVH = 9216;
    uint32_t kb_h = sbase + offKH + (uint32_t)(lane & 7) * ARS + ((lane >> 3) & 1) * 16;
    float sc[8][4];
    #pragma unroll
    for (int ni = 0; ni < 8; ni++)
        #pragma unroll
        for (int t = 0; t < 4; t++) sc[ni][t] = 0.f;
    #pragma unroll
    for (int ni = 0; ni < 8; ni++) {
        uint32_t ba_h = kb_h + (uint32_t)(ni * 8) * ARS;
        #pragma unroll
        for (int ks = 0; ks < 4; ks++) {
            uint32_t bh0, bh1;
            LDSM2(bh0, bh1, ba_h + ks * 32);
            mma16816(sc[ni], qfh[ks], bh0, bh1);
        }
    }
    #pragma unroll
    for (int ni = 0; ni < 8; ni++) {
        sc[ni][0] *= 0.125f; sc[ni][1] *= 0.125f;
        sc[ni][2] *= 0.125f; sc[ni][3] *= 0.125f;
    }
    float bm0 = -1e30f, bm1 = -1e30f;
    #pragma unroll
    for (int ni = 0; ni < 8; ni++) {
        bm0 = fmaxf(bm0, fmaxf(sc[ni][0], sc[ni][1]));
        bm1 = fmaxf(bm1, fmaxf(sc[ni][2], sc[ni][3]));
    }
    bm0 = fmaxf(bm0, __shfl_xor_sync(0xffffffffu, bm0, 1));
    bm0 = fmaxf(bm0, __shfl_xor_sync(0xffffffffu, bm0, 2));
    bm1 = fmaxf(bm1, __shfl_xor_sync(0xffffffffu, bm1, 1));
    bm1 = fmaxf(bm1, __shfl_xor_sync(0xffffffffu, bm1, 2));
    float mn0 = fmaxf(st.m0, bm0), mn1 = fmaxf(st.m1, bm1);
    float corr0 = __expf(st.m0 - mn0), corr1 = __expf(st.m1 - mn1);
    st.m0 = mn0; st.m1 = mn1;
    #pragma unroll
    for (int nd = 0; nd < 8; nd++) {
        st.co[nd][0] *= corr0; st.co[nd][1] *= corr0;
        st.co[nd][2] *= corr1; st.co[nd][3] *= corr1;
    }
    float ls0 = 0.f, ls1 = 0.f;
    #pragma unroll
    for (int ni = 0; ni < 8; ni++) {
        sc[ni][0] = __expf(sc[ni][0] - mn0);
        sc[ni][1] = __expf(sc[ni][1] - mn0);
        sc[ni][2] = __expf(sc[ni][2] - mn1);
        sc[ni][3] = __expf(sc[ni][3] - mn1);
        ls0 += sc[ni][0] + sc[ni][1];
        ls1 += sc[ni][2] + sc[ni][3];
    }
    ls0 += __shfl_xor_sync(0xffffffffu, ls0, 1);
    ls0 += __shfl_xor_sync(0xffffffffu, ls0, 2);
    ls1 += __shfl_xor_sync(0xffffffffu, ls1, 1);
    ls1 += __shfl_xor_sync(0xffffffffu, ls1, 2);
    st.l0 = st.l0 * corr0 + ls0;
    st.l1 = st.l1 * corr1 + ls1;

    uint32_t pah[4][4];
    #pragma unroll
    for (int ksp = 0; ksp < 4; ksp++) {
        pah[ksp][0] = pack2h(sc[2*ksp][0],   sc[2*ksp][1]);
        pah[ksp][1] = pack2h(sc[2*ksp][2],   sc[2*ksp][3]);
        pah[ksp][2] = pack2h(sc[2*ksp+1][0], sc[2*ksp+1][1]);
        pah[ksp][3] = pack2h(sc[2*ksp+1][2], sc[2*ksp+1][3]);
    }
    #pragma unroll
    for (int nd = 0; nd < 8; nd++) {
        #pragma unroll
        for (int ksp = 0; ksp < 4; ksp++) {
            uint32_t va = sbase + offKH + dVH
                        + (uint32_t)(ksp * 16 + (lane & 15)) * ARS + nd * 16;
            uint32_t vh0, vh1;
            LDSM2T(vh0, vh1, va);
            mma16816(st.co[nd], pah[ksp], vh0, vh1);
        }
    }
}

__device__ __forceinline__ void load_q_frags(
    uint32_t sbase, int warp_q, int lane, uint32_t qfh[4][4])
{
    uint32_t qa_h = sbase + A_QH + (uint32_t)(warp_q * 16 + (lane & 15)) * ARS + (lane >> 4) * 16;
    #pragma unroll
    for (int ks = 0; ks < 4; ks++)
        LDSM4(qfh[ks], qa_h + ks * 32);
}

__device__ __forceinline__ void stage_q(
    const __half* __restrict__ qkvh,
    uint32_t sbase, int b, int qb, int h, int srow, int shalf)
{
    size_t off = ((size_t)(b * SEQ + qb * BLKS + srow)) * QKVD + h * DHd + shalf * 32;
    uint32_t dh = sbase + A_QH + (uint32_t)srow * ARS + shalf * 64;
    CPA16(dh,      qkvh + off);      CPA16(dh + 16, qkvh + off + 8);
    CPA16(dh + 32, qkvh + off + 16); CPA16(dh + 48, qkvh + off + 24);
    CP_COMMIT(); CP_WAIT(0);
}

// ---------------- sparse attention ----------------
__global__ void __launch_bounds__(128) attn_sparse_kernel(
    const __half* __restrict__ qkvh,
    const int* __restrict__ rb, __half* __restrict__ ch_g)
{
    extern __shared__ char sb[];
    uint32_t sbase = s2u(sb);
    int b = blockIdx.z, h = blockIdx.y, qb = blockIdx.x + 1;
    int tid = threadIdx.x, lane = tid & 31, w = tid >> 5;
    int srow = tid >> 1, shalf = tid & 1;

    stage_q(qkvh, sbase, b, qb, h, srow, shalf);
    __syncthreads();

    uint32_t qfh[4][4];
    load_q_frags(sbase, w, lane, qfh);

    AttnState st;
    st.m0 = st.m1 = -1e30f; st.l0 = st.l1 = 0.f;
    #pragma unroll
    for (int nd = 0; nd < 8; nd++)
        #pragma unroll
        for (int t = 0; t < 4; t++) st.co[nd][t] = 0.f;

    int blist[8];
    blist[0] = 0; blist[1] = qb - 1; blist[2] = qb; blist[3] = qb + 1;
    blist[4] = NB - 1;
    const int* rp = rb + (h * NB + qb) * RR;
    blist[5] = rp[0]; blist[6] = rp[1]; blist[7] = rp[2];

    uint32_t dk = sbase + A_KH + (uint32_t)srow * ARS + shalf * 64;
    uint32_t dv = dk + 9216;

    for (int jb = 0; jb < 8; jb++) {
        int kb = blist[jb];
        size_t kbase = ((size_t)(b * SEQ + kb * BLKS + srow)) * QKVD + Dm + h * DHd + shalf * 32;
        __syncthreads();
        stage_kv(qkvh, kbase, dk, dv);
        __syncthreads();
        attn_block(st, qfh, sbase, A_KH, lane);
    }

    float inv0 = 1.f / st.l0, inv1 = 1.f / st.l1;
    int g = lane >> 2, t4 = lane & 3;
    size_t rbase = ((size_t)(b * SEQ + qb * BLKS + w * 16 + g)) * Dm + h * DHd;
    #pragma unroll
    for (int nd = 0; nd < 8; nd++) {
        int col = nd * 8 + 2 * t4;
        *(uint32_t*)(ch_g + rbase + col) =
            pack2h(st.co[nd][0] * inv0, st.co[nd][1] * inv0);
        *(uint32_t*)(ch_g + rbase + 8 * Dm + col) =
            pack2h(st.co[nd][2] * inv1, st.co[nd][3] * inv1);
    }
}

// ---------------- dense attention (query blocks 0, NB-1) ----------------
__global__ void __launch_bounds__(256) attn_dense_kernel(
    const __half* __restrict__ qkvh, __half* __restrict__ ch_g)
{
    extern __shared__ char sb[];
    uint32_t sbase = s2u(sb);
    int b = blockIdx.z, h = blockIdx.y;
    int qb = (blockIdx.x == 0) ? 0 : NB - 1;
    int tid = threadIdx.x, lane = tid & 31;
    int grp = tid >> 7, ltid = tid & 127, w = ltid >> 5;
    int srow = ltid >> 1, shalf = ltid & 1;

    if (grp == 0) stage_q(qkvh, sbase, b, qb, h, srow, shalf);
    __syncthreads();

    uint32_t qfh[4][4];
    load_q_frags(sbase, w, lane, qfh);

    AttnState st;
    st.m0 = st.m1 = -1e30f; st.l0 = st.l1 = 0.f;
    #pragma unroll
    for (int nd = 0; nd < 8; nd++)
        #pragma unroll
        for (int t = 0; t < 4; t++) st.co[nd][t] = 0.f;

    uint32_t gbase = D_G0 + grp * A_BLK;
    uint32_t dk = sbase + gbase + (uint32_t)srow * ARS + shalf * 64;
    uint32_t dv = dk + 9216;

    for (int jb = 0; jb < 32; jb++) {
        int kb = grp * 32 + jb;
        size_t kbase = ((size_t)(b * SEQ + kb * BLKS + srow)) * QKVD + Dm + h * DHd + shalf * 32;
        __syncthreads();
        stage_kv(qkvh, kbase, dk, dv);
        __syncthreads();
        attn_block(st, qfh, sbase, gbase, lane);
    }

    __syncthreads();
    float* mg = (float*)(sb + D_MRG);
    int slot = (w * 32 + lane) * 36;
    if (grp == 1) {
        #pragma unroll
        for (int nd = 0; nd < 8; nd++)
            #pragma unroll
            for (int t = 0; t < 4; t++) mg[slot + nd * 4 + t] = st.co[nd][t];
        mg[slot + 32] = st.m0; mg[slot + 33] = st.m1;
        mg[slot + 34] = st.l0; mg[slot + 35] = st.l1;
    }
    __syncthreads();
    if (grp == 0) {
        float mB0 = mg[slot + 32], mB1 = mg[slot + 33];
        float lB0 = mg[slot + 34], lB1 = mg[slot + 35];
        float M0 = fmaxf(st.m0, mB0), M1 = fmaxf(st.m1, mB1);
        float cA0 = __expf(st.m0 - M0), cB0 = __expf(mB0 - M0);
        float cA1 = __expf(st.m1 - M1), cB1 = __expf(mB1 - M1);
        float L0 = st.l0 * cA0 + lB0 * cB0;
        float L1 = st.l1 * cA1 + lB1 * cB1;
        float inv0 = 1.f / L0, inv1 = 1.f / L1;
        int g = lane >> 2, t4 = lane & 3;
        size_t rbase = ((size_t)(b * SEQ + qb * BLKS + w * 16 + g)) * Dm + h * DHd;
        #pragma unroll
        for (int nd = 0; nd < 8; nd++) {
            float r0 = (st.co[nd][0] * cA0 + mg[slot + nd * 4 + 0] * cB0) * inv0;
            float r1 = (st.co[nd][1] * cA0 + mg[slot + nd * 4 + 1] * cB0) * inv0;
            float r2 = (st.co[nd][2] * cA1 + mg[slot + nd * 4 + 2] * cB1) * inv1;
            float r3 = (st.co[nd][3] * cA1 + mg[slot + nd * 4 + 3] * cB1) * inv1;
            int col = nd * 8 + 2 * t4;
            *(uint32_t*)(ch_g + rbase + col)          = pack2h(r0, r1);
            *(uint32_t*)(ch_g + rbase + 8 * Dm + col) = pack2h(r2, r3);
        }
    }
}

// ---------------- mean pool + linear head (x = hi+lo) ----------------
__global__ void __launch_bounds__(256) pool1_kernel(
    const __half* __restrict__ xh, const __half* __restrict__ xl,
    const float* __restrict__ w, float* __restrict__ part)
{
    int b = blockIdx.y, sl = blockIdx.x;
    size_t base = ((size_t)b * SEQ + sl * 128) * Dm;
    __shared__ float ws[Dm];
    for (int i = threadIdx.x; i < Dm; i += 256) ws[i] = w[i];
    __syncthreads();
    float acc = 0.f;
    for (int r = 0; r < 128; r++) {
        size_t rb2 = base + (size_t)r * Dm;
        for (int i = threadIdx.x; i < Dm; i += 256)
            acc += (__half2float(xh[rb2 + i]) + __half2float(xl[rb2 + i])) * ws[i];
    }
    float t = blk_sum256(acc);
    if (threadIdx.x == 0) part[b * 32 + sl] = t;
}
__global__ void pool2_kernel(const float* __restrict__ part,
                             const float* __restrict__ fb, float* __restrict__ out)
{
    int b = threadIdx.x;
    if (b < BB) {
        float s = 0.f;
        for (int i = 0; i < 32; i++) s += part[b * 32 + i];
        out[b] = s * (1.f / (float)SEQ) + fb[0];
    }
}

// ---------------- driver ----------------
extern "C" void kernel_launch(void* const* d_in, const int* in_sizes, int n_in,
                              void* d_out, int out_size)
{
    const int*   ids     = (const int*)  d_in[0];
    const int*   rb      = (const int*)  d_in[1];
    const float* emb_tok = (const float*)d_in[2];
    const float* emb_pos = (const float*)d_in[3];
    const float* lng     = (const float*)d_in[4];
    const float* lnb     = (const float*)d_in[5];
    const float* Wq = (const float*)d_in[6];  const float* bq = (const float*)d_in[7];
    const float* Wk = (const float*)d_in[8];  const float* bk = (const float*)d_in[9];
    const float* Wv = (const float*)d_in[10]; const float* bv = (const float*)d_in[11];
    const float* Wo = (const float*)d_in[12]; const float* bo = (const float*)d_in[13];
    const float* ln1g = (const float*)d_in[14]; const float* ln1b = (const float*)d_in[15];
    const float* W1 = (const float*)d_in[16]; const float* b1 = (const float*)d_in[17];
    const float* W2 = (const float*)d_in[18]; const float* b2 = (const float*)d_in[19];
    const float* ln2g = (const float*)d_in[20]; const float* ln2b = (const float*)d_in[21];
    const float* fcw = (const float*)d_in[22]; const float* fcb = (const float*)d_in[23];

    float *part, *bqkv;
    __half *tmph, *xh, *xl, *qkvh, *ch, *fh, *wh;
    cudaGetSymbolAddress((void**)&tmph, g_tmph);
    cudaGetSymbolAddress((void**)&xh,   g_xh);
    cudaGetSymbolAddress((void**)&xl,   g_xl);
    cudaGetSymbolAddress((void**)&qkvh, g_qkvh);
    cudaGetSymbolAddress((void**)&ch,   g_ch);
    cudaGetSymbolAddress((void**)&fh,   g_fh);
    cudaGetSymbolAddress((void**)&wh,   g_wh);
    cudaGetSymbolAddress((void**)&bqkv, g_bqkv);
    cudaGetSymbolAddress((void**)&part, g_part);

    const int SM_A1 = 2 * 2 * TL64;   // 73728 (all GEMMs are 1-term now)
    cudaFuncSetAttribute((const void*)gemm_mma<0,0,2,0,12>,
                         cudaFuncAttributeMaxDynamicSharedMemorySize, SM_A1);
    cudaFuncSetAttribute((const void*)gemm_mma<1,0,2,0,12>,
                         cudaFuncAttributeMaxDynamicSharedMemorySize, SM_A1);
    cudaFuncSetAttribute((const void*)gemm_mma<0,0,2,0,48>,
                         cudaFuncAttributeMaxDynamicSharedMemorySize, SM_A1);
    cudaFuncSetAttribute((const void*)attn_sparse_kernel,
                         cudaFuncAttributeMaxDynamicSharedMemorySize, A_SMEM);
    cudaFuncSetAttribute((const void*)attn_dense_kernel,
                         cudaFuncAttributeMaxDynamicSharedMemorySize, D_SMEM);

    dim3 gQKV(QKVD / 128, NTOK / 128);
    dim3 gO(Dm / 128, NTOK / 128);
    dim3 gF(FF / 128, NTOK / 128);
    dim3 gAttS(NB - 2, Hh, BB);
    dim3 gAttD(2, Hh, BB);
    dim3 gWS(Dm / 32, Dm / 32);

    wsplit3_kernel<<<dim3(Dm / 32, Dm / 32, 3), 256>>>(
        Wq, Wk, Wv, wh, bq, bk, bv, bqkv);
    wsplit_kernel<<<gWS, 256>>>(Wo, wh + 3 * (size_t)WSZ, Dm, Dm);
    wsplit_kernel<<<dim3(FF / 32, Dm / 32), 256>>>(W1, wh + 4 * (size_t)WSZ, Dm, FF);
    wsplit_kernel<<<dim3(Dm / 32, FF / 32), 256>>>(W2, wh + 4 * (size_t)WSZ + W1SZ, FF, Dm);
    embed_ln_kernel<<<NTOK, 256>>>(ids, emb_tok, emb_pos, lng, lnb, xh, xl);

    for (int l = 0; l < 2; l++) {
        size_t o = (size_t)l * OFFL;
        gemm_mma<0,0,2,0,12><<<gQKV, 256, SM_A1>>>(xh, nullptr, wh + o, bqkv + l * QKVD,
            nullptr, qkvh, nullptr, NTOK, QKVD);
        attn_sparse_kernel<<<gAttS, 128, A_SMEM>>>(qkvh, rb, ch);
        attn_dense_kernel<<<gAttD, 256, D_SMEM>>>(qkvh, ch);
        gemm_mma<0,0,2,0,12><<<gO, 256, SM_A1>>>(ch, nullptr, wh + o + 3 * WSZ,
            bo + l * Dm, nullptr, tmph, nullptr, NTOK, Dm);
        add_ln_kernel<<<NTOK, 256>>>(xh, xl, tmph, ln1g + l * Dm, ln1b + l * Dm);
        gemm_mma<1,0,2,0,12><<<gF, 256, SM_A1>>>(xh, nullptr, wh + o + 4 * WSZ,
            b1 + l * FF, nullptr, fh, nullptr, NTOK, FF);
        gemm_mma<0,0,2,0,48><<<gO, 256, SM_A1>>>(fh, nullptr, wh + o + 4 * WSZ + W1SZ,
            b2 + l * Dm, nullptr, tmph, nullptr, NTOK, Dm);
        add_ln_kernel<<<NTOK, 256>>>(xh, xl, tmph, ln2g + l * Dm, ln2b + l * Dm);

        if (l == 0) {
            size_t o1 = OFFL;
            wsplit3_kernel<<<dim3(Dm / 32, Dm / 32, 3), 256>>>(
                Wq + WSZ, Wk + WSZ, Wv + WSZ, wh + o1,
                bq + Dm, bk + Dm, bv + Dm, bqkv + QKVD);
            wsplit_kernel<<<gWS, 256>>>(Wo + WSZ, wh + o1 + 3 * (size_t)WSZ, Dm, Dm);
            wsplit_kernel<<<dim3(FF / 32, Dm / 32), 256>>>(W1 + W1SZ, wh + o1 + 4 * (size_t)WSZ, Dm, FF);
            wsplit_kernel<<<dim3(Dm / 32, FF / 32), 256>>>(W2 + W1SZ, wh + o1 + 4 * (size_t)WSZ + W1SZ, FF, Dm);
        }
    }

    pool1_kernel<<<dim3(32, BB), 256>>>(xh, xl, fcw, part);
    pool2_kernel<<<1, 32>>>(part, fcb, (float*)d_out);
}